// round 10
// baseline (speedup 1.0000x reference)
#include <cuda_runtime.h>
#include <math.h>
#include <float.h>
#include <stdint.h>

// ---------------- problem constants ----------------
#define CH   512
#define HW   4096
constexpr long long CHW = (long long)CH * HW;
constexpr long long CC  = (long long)CH * CH;
constexpr long long PQ  = (long long)HW * HW;

// ---------------- device scratch ----------------
__device__ float g_Fcent[4 * 2097152];
__device__ float g_means[4 * 512];
__device__ float g_Cov[4 * 262144];
__device__ float g_sigma[4];
__device__ float g_Ybuf[2 * 1048576];
__device__ float g_Zbuf[2 * 1048576];
__device__ float g_Tm[1048576];
__device__ float g_W[1048576];
__device__ float g_Cm[2 * 262144];
__device__ float g_NC[4 * 2097152];
__device__ float g_NSt[2 * 2097152];
__device__ float g_NCth[2 * 2097152];
__device__ float g_NCtl[2 * 2097152];
__device__ float g_NSth[2 * 2097152];
__device__ float g_NStl[2 * 2097152];
__device__ float g_snorm[2 * 4096];
__device__ float g_rk[2 * 4096];
__device__ float g_M0[33554432];
__device__ float g_Tb[33554432];
__device__ int   g_idx[2 * 4096];
__device__ float g_pbs[2 * 16 * 4096];
__device__ int   g_pbi[2 * 16 * 4096];
__device__ float g_reasT[2 * 2097152];

// ---------------- packed f32x2 helpers (SIMT GEMM stages) ----------------
typedef unsigned long long u64;
__device__ __forceinline__ u64 pack2(float x) {
    u64 r; asm("mov.b64 %0, {%1, %1};" : "=l"(r) : "f"(x)); return r;
}
__device__ __forceinline__ void ffma2(u64 &d, u64 a, u64 b) {
    asm("fma.rn.f32x2 %0, %1, %2, %3;" : "=l"(d) : "l"(a), "l"(b), "l"(d));
}
__device__ __forceinline__ float2 unpack2(u64 v) {
    float2 f; asm("mov.b64 {%0, %1}, %2;" : "=f"(f.x), "=f"(f.y) : "l"(v)); return f;
}

__device__ __forceinline__ float tf32_rna(float x) {
    uint32_t u; asm("cvt.rna.tf32.f32 %0, %1;" : "=r"(u) : "f"(x));
    return __uint_as_float(u);
}
__device__ __forceinline__ uint32_t smem_to_u32(const void* p) {
    uint32_t a;
    asm("{ .reg .u64 t; cvta.to.shared.u64 t, %1; cvt.u32.u64 %0, t; }" : "=r"(a) : "l"(p));
    return a;
}
__device__ __forceinline__ void cp_async16(uint32_t saddr, const void* g) {
    asm volatile("cp.async.cg.shared.global [%0], [%1], 16;" :: "r"(saddr), "l"(g));
}
#define CP_COMMIT() asm volatile("cp.async.commit_group;" ::: "memory")
#define CP_WAIT1()  asm volatile("cp.async.wait_group 1;" ::: "memory")
#define CP_WAIT0()  asm volatile("cp.async.wait_group 0;" ::: "memory")

// ---------------- warp-level tf32 MMA ----------------
__device__ __forceinline__ void mma_tf32(float* c, const uint32_t* a, const uint32_t* b) {
    asm volatile(
        "mma.sync.aligned.m16n8k8.row.col.f32.tf32.tf32.f32 "
        "{%0,%1,%2,%3}, {%4,%5,%6,%7}, {%8,%9}, {%0,%1,%2,%3};"
        : "+f"(c[0]), "+f"(c[1]), "+f"(c[2]), "+f"(c[3])
        : "r"(a[0]), "r"(a[1]), "r"(a[2]), "r"(a[3]), "r"(b[0]), "r"(b[1]));
}

// ---------------- M0 tensor-core kernel (3xTF32, cp.async double-buffered) ----------------
#define SKP 20
constexpr int M0_ARR  = 128 * SKP;
constexpr int M0_BUF  = 4 * M0_ARR;
constexpr int M0_SMEM = 2 * M0_BUF * 4;   // 81920 bytes

__global__ void __launch_bounds__(256, 2) m0_mma_kernel(
    const float* __restrict__ Ah, const float* __restrict__ Al,
    const float* __restrict__ Bh, const float* __restrict__ Bl,
    float* __restrict__ M0out)
{
    extern __shared__ float sm[];
    const uint32_t sbase = smem_to_u32(sm);
    const int tid  = threadIdx.x;
    const int wid  = tid >> 5, lane = tid & 31;
    const int g    = lane >> 2, t = lane & 3;
    const int wm   = wid & 3, wn = wid >> 2;
    const int m0   = blockIdx.y * 128, n0 = blockIdx.x * 128;
    const int b    = blockIdx.z;
    const float* arr0 = Ah + (long long)b * CHW;
    const float* arr1 = Al + (long long)b * CHW;
    const float* arr2 = Bh + (long long)b * CHW;
    const float* arr3 = Bl + (long long)b * CHW;

    auto stage = [&](int kt, int buf) {
#pragma unroll
        for (int tt = 0; tt < 8; tt++) {
            int idx = tid + tt * 256;
            int a   = idx >> 9;
            int r   = (idx & 511) >> 2;
            int c4  = (idx & 3) * 4;
            const float* src = (a == 0) ? arr0 : (a == 1) ? arr1 : (a == 2) ? arr2 : arr3;
            int rowbase = (a < 2) ? m0 : n0;
            const float* gp = src + (long long)(rowbase + r) * CH + kt * 16 + c4;
            uint32_t sa = sbase + (uint32_t)(buf * M0_BUF + a * M0_ARR + r * SKP + c4) * 4u;
            cp_async16(sa, gp);
        }
    };

    float acc[2][8][4];
#pragma unroll
    for (int i = 0; i < 2; i++)
#pragma unroll
        for (int j = 0; j < 8; j++)
#pragma unroll
            for (int k = 0; k < 4; k++) acc[i][j][k] = 0.f;

    stage(0, 0); CP_COMMIT();

    for (int kt = 0; kt < 32; kt++) {
        const int buf = kt & 1;
        if (kt + 1 < 32) { stage(kt + 1, buf ^ 1); CP_COMMIT(); CP_WAIT1(); }
        else             { CP_WAIT0(); }
        __syncthreads();

        const float* sAh = sm + buf * M0_BUF;
        const float* sAl = sAh + M0_ARR;
        const float* sBh = sAl + M0_ARR;
        const float* sBl = sBh + M0_ARR;
#pragma unroll
        for (int ks = 0; ks < 16; ks += 8) {
            uint32_t afh[2][4], afl[2][4];
#pragma unroll
            for (int mt = 0; mt < 2; mt++) {
                int r  = wm * 32 + mt * 16;
                int i0 = (r + g) * SKP + ks + t;
                int i8 = (r + g + 8) * SKP + ks + t;
                afh[mt][0] = __float_as_uint(sAh[i0]);
                afh[mt][1] = __float_as_uint(sAh[i8]);
                afh[mt][2] = __float_as_uint(sAh[i0 + 4]);
                afh[mt][3] = __float_as_uint(sAh[i8 + 4]);
                afl[mt][0] = __float_as_uint(sAl[i0]);
                afl[mt][1] = __float_as_uint(sAl[i8]);
                afl[mt][2] = __float_as_uint(sAl[i0 + 4]);
                afl[mt][3] = __float_as_uint(sAl[i8 + 4]);
            }
            // nt processed in pairs; (product, nt, mt) interleaved so that
            // instructions hitting the SAME accumulator are 4 mma apart
            // (kills the 3-deep RAW chain). Per-acc product order is
            // unchanged (hh, hl, lh) => bit-identical results.
#pragma unroll
            for (int ntp = 0; ntp < 4; ntp++) {
                const int nt0 = 2 * ntp, nt1 = nt0 + 1;
                int b0 = (wn * 64 + nt0 * 8 + g) * SKP + ks + t;
                int b1 = (wn * 64 + nt1 * 8 + g) * SKP + ks + t;
                uint32_t bfh0[2] = { __float_as_uint(sBh[b0]), __float_as_uint(sBh[b0 + 4]) };
                uint32_t bfl0[2] = { __float_as_uint(sBl[b0]), __float_as_uint(sBl[b0 + 4]) };
                uint32_t bfh1[2] = { __float_as_uint(sBh[b1]), __float_as_uint(sBh[b1 + 4]) };
                uint32_t bfl1[2] = { __float_as_uint(sBl[b1]), __float_as_uint(sBl[b1 + 4]) };
                mma_tf32(acc[0][nt0], afh[0], bfh0);
                mma_tf32(acc[1][nt0], afh[1], bfh0);
                mma_tf32(acc[0][nt1], afh[0], bfh1);
                mma_tf32(acc[1][nt1], afh[1], bfh1);
                mma_tf32(acc[0][nt0], afh[0], bfl0);
                mma_tf32(acc[1][nt0], afh[1], bfl0);
                mma_tf32(acc[0][nt1], afh[0], bfl1);
                mma_tf32(acc[1][nt1], afh[1], bfl1);
                mma_tf32(acc[0][nt0], afl[0], bfh0);
                mma_tf32(acc[1][nt0], afl[1], bfh0);
                mma_tf32(acc[0][nt1], afl[0], bfh1);
                mma_tf32(acc[1][nt1], afl[1], bfh1);
            }
        }
        __syncthreads();
    }

#pragma unroll
    for (int mt = 0; mt < 2; mt++) {
        int row = m0 + wm * 32 + mt * 16 + g;
        float* r0 = M0out + (long long)b * PQ + (long long)row * HW;
        float* r1 = r0 + 8ll * HW;
#pragma unroll
        for (int nt = 0; nt < 8; nt++) {
            int col = n0 + wn * 64 + nt * 8 + 2 * t;
            float2 v0; v0.x = acc[mt][nt][0]; v0.y = acc[mt][nt][1];
            float2 v1; v1.x = acc[mt][nt][2]; v1.y = acc[mt][nt][3];
            *(float2*)&r0[col] = v0;
            *(float2*)&r1[col] = v1;
        }
    }
}

// ---------------- double-buffered pipelined SGEMM (f32x2 inner loop) ----------------
template<int BM, int BN, int BK, int TM, int TN, bool TA, bool TB>
__device__ __forceinline__ void sgemm_tile(
    const float* __restrict__ Ab, const float* __restrict__ Bb, float* __restrict__ Cb,
    int M, int N, int K, float alpha, float diagAdd, const float* __restrict__ bias)
{
    constexpr int THREADS = (BM / TM) * (BN / TN);
    constexpr int LA4 = BM * BK / (4 * THREADS);
    constexpr int LB4 = BN * BK / (4 * THREADS);
    __shared__ float As[2][BK][BM + 4];
    __shared__ float Bs[2][BK][BN + 4];
    const int tid  = threadIdx.x;
    const int tcol = tid % (BN / TN);
    const int trow = tid / (BN / TN);
    const int m0 = blockIdx.y * BM;
    const int n0 = blockIdx.x * BN;

    float4 stA[LA4], stB[LB4];

    auto loadA = [&](int k0) {
#pragma unroll
        for (int l = 0; l < LA4; l++) {
            int i = tid + l * THREADS;
            if (TA) { int kk = i / (BM / 4); int m = (i % (BM / 4)) * 4;
                      stA[l] = *(const float4*)&Ab[(long long)(k0 + kk) * M + m0 + m]; }
            else    { int m = i / (BK / 4); int kk = (i % (BK / 4)) * 4;
                      stA[l] = *(const float4*)&Ab[(long long)(m0 + m) * K + k0 + kk]; }
        }
    };
    auto loadB = [&](int k0) {
#pragma unroll
        for (int l = 0; l < LB4; l++) {
            int i = tid + l * THREADS;
            if (TB) { int n = i / (BK / 4); int kk = (i % (BK / 4)) * 4;
                      stB[l] = *(const float4*)&Bb[(long long)(n0 + n) * K + k0 + kk]; }
            else    { int kk = i / (BN / 4); int n = (i % (BN / 4)) * 4;
                      stB[l] = *(const float4*)&Bb[(long long)(k0 + kk) * N + n0 + n]; }
        }
    };
    auto storeA = [&](int buf) {
#pragma unroll
        for (int l = 0; l < LA4; l++) {
            int i = tid + l * THREADS;
            if (TA) { int kk = i / (BM / 4); int m = (i % (BM / 4)) * 4;
                      *(float4*)&As[buf][kk][m] = stA[l]; }
            else    { int m = i / (BK / 4); int kk = (i % (BK / 4)) * 4;
                      As[buf][kk + 0][m] = stA[l].x; As[buf][kk + 1][m] = stA[l].y;
                      As[buf][kk + 2][m] = stA[l].z; As[buf][kk + 3][m] = stA[l].w; }
        }
    };
    auto storeB = [&](int buf) {
#pragma unroll
        for (int l = 0; l < LB4; l++) {
            int i = tid + l * THREADS;
            if (TB) { int n = i / (BK / 4); int kk = (i % (BK / 4)) * 4;
                      Bs[buf][kk + 0][n] = stB[l].x; Bs[buf][kk + 1][n] = stB[l].y;
                      Bs[buf][kk + 2][n] = stB[l].z; Bs[buf][kk + 3][n] = stB[l].w; }
            else    { int kk = i / (BN / 4); int n = (i % (BN / 4)) * 4;
                      *(float4*)&Bs[buf][kk][n] = stB[l]; }
        }
    };

    u64 acc[TM][TN / 2];
#pragma unroll
    for (int i = 0; i < TM; i++)
#pragma unroll
        for (int j = 0; j < TN / 2; j++) acc[i][j] = 0ull;

    loadA(0); loadB(0);
    storeA(0); storeB(0);
    __syncthreads();

    int buf = 0;
    for (int k0 = 0; k0 < K; k0 += BK) {
        const bool has_next = (k0 + BK < K);
        if (has_next) { loadA(k0 + BK); loadB(k0 + BK); }
#pragma unroll
        for (int kk = 0; kk < BK; kk++) {
            float ra[TM];
#pragma unroll
            for (int i4 = 0; i4 < TM / 4; i4++) {
                float4 a4 = *(const float4*)&As[buf][kk][trow * TM + i4 * 4];
                ra[i4 * 4 + 0] = a4.x; ra[i4 * 4 + 1] = a4.y;
                ra[i4 * 4 + 2] = a4.z; ra[i4 * 4 + 3] = a4.w;
            }
            u64 rb2[TN / 2];
#pragma unroll
            for (int j4 = 0; j4 < TN / 4; j4++) {
                ulonglong2 b2 = *(const ulonglong2*)&Bs[buf][kk][tcol * TN + j4 * 4];
                rb2[j4 * 2 + 0] = b2.x; rb2[j4 * 2 + 1] = b2.y;
            }
#pragma unroll
            for (int i = 0; i < TM; i++) {
                u64 a2 = pack2(ra[i]);
#pragma unroll
                for (int j = 0; j < TN / 2; j++) ffma2(acc[i][j], a2, rb2[j]);
            }
        }
        if (has_next) { storeA(buf ^ 1); storeB(buf ^ 1); }
        __syncthreads();
        buf ^= 1;
    }

#pragma unroll
    for (int i = 0; i < TM; i++) {
        int gm = m0 + trow * TM + i;
        float bv = bias ? bias[gm] : 0.f;
#pragma unroll
        for (int j = 0; j < TN / 2; j++) {
            float2 v = unpack2(acc[i][j]);
            int gn = n0 + tcol * TN + 2 * j;
            float x = alpha * v.x + bv; if (gm == gn)     x += diagAdd;
            float y = alpha * v.y + bv; if (gm == gn + 1) y += diagAdd;
            float2 o; o.x = x; o.y = y;
            *(float2*)&Cb[(long long)gm * N + gn] = o;
        }
    }
}

template<int BM, int BN, int BK, int TM, int TN, bool TA, bool TB>
__global__ void sgemm_kernel(const float* __restrict__ A, const float* __restrict__ B,
                             float* __restrict__ C,
                             int M, int N, int K,
                             long long sA, long long sB, long long sC,
                             float alpha, float diagAdd,
                             const float* __restrict__ bias, int biasStride)
{
    const float* Ab = A + (long long)blockIdx.z * sA;
    const float* Bb = B + (long long)blockIdx.z * sB;
    float* Cb = C + (long long)blockIdx.z * sC;
    const float* bb = bias ? bias + (long long)blockIdx.z * biasStride : nullptr;
    sgemm_tile<BM, BN, BK, TM, TN, TA, TB>(Ab, Bb, Cb, M, N, K, alpha, diagAdd, bb);
}

__global__ void ns_yz_kernel(const float* __restrict__ Y, const float* __restrict__ T,
                             const float* __restrict__ Z,
                             float* __restrict__ Yn, float* __restrict__ Zn)
{
    int z = blockIdx.z;
    const float *Ab, *Bb; float* Cb;
    if (z < 4) { Ab = Y + (long long)z * CC;       Bb = T + (long long)z * CC;       Cb = Yn + (long long)z * CC; }
    else       { Ab = T + (long long)(z - 4) * CC; Bb = Z + (long long)(z - 4) * CC; Cb = Zn + (long long)(z - 4) * CC; }
    sgemm_tile<64, 64, 16, 4, 4, false, false>(Ab, Bb, Cb, 512, 512, 512, 1.f, 0.f, nullptr);
}

// ---------------- per-channel mean + center ----------------
__global__ void center_kernel(const float* __restrict__ content, const float* __restrict__ style,
                              float* __restrict__ Fcent, float* __restrict__ means)
{
    int c = blockIdx.x, g = blockIdx.y;
    const float* src = (g < 2 ? content + (long long)g * CHW : style + (long long)(g - 2) * CHW)
                       + (long long)c * HW;
    __shared__ float red[256];
    float s = 0.f;
    for (int i = threadIdx.x; i < HW; i += 256) s += src[i];
    red[threadIdx.x] = s; __syncthreads();
    for (int st = 128; st > 0; st >>= 1) {
        if (threadIdx.x < st) red[threadIdx.x] += red[threadIdx.x + st];
        __syncthreads();
    }
    float mean = red[0] * (1.f / HW);
    if (threadIdx.x == 0) means[g * CH + c] = mean;
    float* dst = Fcent + (long long)g * CHW + (long long)c * HW;
    for (int i = threadIdx.x; i < HW; i += 256) dst[i] = src[i] - mean;
}

// ---------------- power iteration ----------------
__global__ void power_kernel(const float* __restrict__ Cov, float* __restrict__ sigma)
{
    int g = blockIdx.x;
    const float* A = Cov + (long long)g * CC;
    __shared__ float v[CH];
    __shared__ float red[CH];
    int t = threadIdx.x;
    v[t] = 1.f + 1e-4f * t;
    __syncthreads();
    float lam = 0.f;
    for (int it = 0; it < 40; it++) {
        float acc = 0.f;
        for (int k = 0; k < CH; k++) acc = fmaf(A[(long long)k * CH + t], v[k], acc);
        __syncthreads();
        red[t] = acc * acc; __syncthreads();
        for (int st = 256; st > 0; st >>= 1) {
            if (t < st) red[t] += red[t + st];
            __syncthreads();
        }
        float n2 = red[0];
        lam = sqrtf(n2);
        float inv = (n2 > 0.f) ? rsqrtf(n2) : 0.f;
        __syncthreads();
        v[t] = acc * inv;
        __syncthreads();
    }
    if (t == 0) sigma[g] = lam * 1.02f + 1e-20f;
}

// ---------------- Newton-Schulz init / rescale ----------------
__global__ void ns_init_kernel(const float* __restrict__ Cov, const float* __restrict__ sigma,
                               float* __restrict__ Y, float* __restrict__ Z)
{
    long long i = (long long)blockIdx.x * blockDim.x + threadIdx.x;
    if (i >= 4 * CC) return;
    int g = (int)(i / CC);
    long long r = i % CC;
    int row = (int)(r / CH), col = (int)(r % CH);
    Y[i] = Cov[i] / sigma[g];
    Z[i] = (row == col) ? 1.f : 0.f;
}

__global__ void scale_kernel(const float* __restrict__ Y, const float* __restrict__ Z,
                             const float* __restrict__ sigma,
                             float* __restrict__ W, float* __restrict__ Cm)
{
    long long i = (long long)blockIdx.x * blockDim.x + threadIdx.x;
    if (i >= 4 * CC) return;
    int g = (int)(i / CC);
    float sq = sqrtf(sigma[g]);
    W[i] = Z[i] / sq;
    if (g >= 2) Cm[i - 2 * CC] = Y[i] * sq;
}

// ---------------- transpose + tf32 hi/lo split ----------------
__global__ void transpose_split_kernel(const float* __restrict__ NC,
                                       float* __restrict__ NSt,
                                       float* __restrict__ NCth, float* __restrict__ NCtl,
                                       float* __restrict__ NSth, float* __restrict__ NStl)
{
    __shared__ float tile[32][33];
    int g = blockIdx.z;
    int p0 = blockIdx.x * 32, c0 = blockIdx.y * 32;
    const float* src = NC + (long long)g * CHW;
    tile[threadIdx.y][threadIdx.x] = src[(long long)(c0 + threadIdx.y) * HW + p0 + threadIdx.x];
    __syncthreads();
    float x = tile[threadIdx.x][threadIdx.y];
    long long o = (long long)(g & 1) * CHW + (long long)(p0 + threadIdx.y) * CH + c0 + threadIdx.x;
    float hi = tf32_rna(x);
    float lo = tf32_rna(x - hi);
    if (g < 2) { NCth[o] = hi; NCtl[o] = lo; }
    else       { NSt[o] = x; NSth[o] = hi; NStl[o] = lo; }
}

// ---------------- per-pixel squared norms ----------------
__global__ void snorm_kernel(const float* __restrict__ NSt, float* __restrict__ snorm)
{
    int gw = (blockIdx.x * blockDim.x + threadIdx.x) >> 5;
    int lane = threadIdx.x & 31;
    if (gw >= 2 * HW) return;
    int b = gw / HW, p = gw % HW;
    const float* row = NSt + (long long)b * CHW + (long long)p * CH;
    float s = 0.f;
    for (int c = lane; c < CH; c += 32) { float v = row[c]; s = fmaf(v, v, s); }
    for (int o = 16; o > 0; o >>= 1) s += __shfl_down_sync(0xffffffff, s, o);
    if (lane == 0) snorm[b * HW + p] = s;
}

__global__ void rknorm_kernel(const float* __restrict__ snorm, float* __restrict__ rk)
{
    int i = blockIdx.x * blockDim.x + threadIdx.x;
    if (i >= 2 * HW) return;
    int b = i / HW, p = i % HW;
    int py = p >> 6, px = p & 63;
    float sum = 0.f;
    for (int u = -1; u <= 1; u++)
        for (int v = -1; v <= 1; v++) {
            int yy = py + u, xx = px + v;
            if ((unsigned)yy < 64u && (unsigned)xx < 64u) sum += snorm[b * HW + yy * 64 + xx];
        }
    rk[i] = 1.f / (sqrtf(sum) + 1e-5f);
}

// ---------------- horizontal diagonal 3-box ----------------
__global__ void boxh_kernel(const float* __restrict__ M0, float* __restrict__ Tb)
{
    long long i = (long long)blockIdx.x * 256 + threadIdx.x;
    int b = blockIdx.y;
    const float* M = M0 + (long long)b * PQ;
    int p = (int)(i >> 12);
    int q = (int)(i & 4095);
    int px = p & 63, qx = q & 63;
    float s = 0.f;
#pragma unroll
    for (int v = -1; v <= 1; v++) {
        if ((unsigned)(px + v) < 64u && (unsigned)(qx + v) < 64u) s += M[i + (long long)v * 4097];
    }
    Tb[(long long)b * PQ + i] = s;
}

// ---------------- vertical diagonal 3-box + partial argmax ----------------
__global__ void argmax_part_kernel(const float* __restrict__ Tb, const float* __restrict__ rk,
                                   float* __restrict__ pbs, int* __restrict__ pbi)
{
    int b = blockIdx.z;
    int q = blockIdx.x * 256 + threadIdx.x;
    int pc = blockIdx.y;
    __shared__ float srk[256];
    srk[threadIdx.x] = rk[b * HW + pc * 256 + threadIdx.x];
    __syncthreads();
    const float* T = Tb + (long long)b * PQ;
    float best = -FLT_MAX; int bi = 0;
    for (int pp = 0; pp < 256; pp++) {
        int p = pc * 256 + pp;
        float s = 0.f;
#pragma unroll
        for (int u = -1; u <= 1; u++) {
            int row = p + 64 * u, col = q + 64 * u;
            if ((unsigned)row < (unsigned)HW && (unsigned)col < (unsigned)HW)
                s += T[(long long)row * HW + col];
        }
        float sc = s * srk[pp];
        if (sc > best) { best = sc; bi = p; }
    }
    pbs[(b * 16 + pc) * HW + q] = best;
    pbi[(b * 16 + pc) * HW + q] = bi;
}

__global__ void argmax_comb_kernel(const float* __restrict__ pbs, const int* __restrict__ pbi,
                                   int* __restrict__ idx)
{
    int i = blockIdx.x * 256 + threadIdx.x;
    if (i >= 2 * HW) return;
    int b = i / HW, q = i % HW;
    float best = -FLT_MAX; int bi = 0;
    for (int k = 0; k < 16; k++) {
        float s = pbs[(b * 16 + k) * HW + q];
        int p = pbi[(b * 16 + k) * HW + q];
        if (s > best || (s == best && p < bi)) { best = s; bi = p; }
    }
    idx[b * HW + q] = bi;
}

// ---------------- gather best patches + overlap-add ----------------
__global__ void gather_kernel(const float* __restrict__ NSt, const int* __restrict__ idx,
                              float* __restrict__ reasT)
{
    int b = blockIdx.y, pix = blockIdx.x;
    int Y = pix >> 6, X = pix & 63;
    __shared__ int sp[9];
    if (threadIdx.x < 9) {
        int dx = threadIdx.x / 3, dy = threadIdx.x % 3;
        int y = Y + 1 - dx, x = X + 1 - dy;
        int pos = -1;
        if ((unsigned)y < 64u && (unsigned)x < 64u) {
            int p = idx[b * HW + y * 64 + x];
            int sy = (p >> 6) + dx - 1, sx = (p & 63) + dy - 1;
            if ((unsigned)sy < 64u && (unsigned)sx < 64u) pos = sy * 64 + sx;
        }
        sp[threadIdx.x] = pos;
    }
    __syncthreads();
    int cy = (Y == 0 || Y == 63) ? 2 : 3;
    int cx = (X == 0 || X == 63) ? 2 : 3;
    float inv = 1.f / (float)(cy * cx);
    const float* base = NSt + (long long)b * CHW;
    float* out = reasT + (long long)b * CHW + (long long)pix * CH;
    for (int c = threadIdx.x; c < CH; c += 128) {
        float a = 0.f;
#pragma unroll
        for (int k = 0; k < 9; k++) {
            int pos = sp[k];
            if (pos >= 0) a += base[(long long)pos * CH + c];
        }
        out[c] = a * inv;
    }
}

// ---------------- host orchestration ----------------
extern "C" void kernel_launch(void* const* d_in, const int* in_sizes, int n_in,
                              void* d_out, int out_size)
{
    (void)in_sizes; (void)n_in; (void)out_size;
    const float* content = (const float*)d_in[0];
    const float* style   = (const float*)d_in[1];
    float* out = (float*)d_out;

    float *Fcent, *means, *Cov, *sigma, *Yb, *Zb, *Tm, *W, *Cm, *NC, *NSt, *snorm, *rk, *M0, *Tb, *pbs, *reasT;
    float *NCth, *NCtl, *NSth, *NStl;
    int *idx, *pbi;
    cudaGetSymbolAddress((void**)&Fcent, g_Fcent);
    cudaGetSymbolAddress((void**)&means, g_means);
    cudaGetSymbolAddress((void**)&Cov,   g_Cov);
    cudaGetSymbolAddress((void**)&sigma, g_sigma);
    cudaGetSymbolAddress((void**)&Yb,    g_Ybuf);
    cudaGetSymbolAddress((void**)&Zb,    g_Zbuf);
    cudaGetSymbolAddress((void**)&Tm,    g_Tm);
    cudaGetSymbolAddress((void**)&W,     g_W);
    cudaGetSymbolAddress((void**)&Cm,    g_Cm);
    cudaGetSymbolAddress((void**)&NC,    g_NC);
    cudaGetSymbolAddress((void**)&NSt,   g_NSt);
    cudaGetSymbolAddress((void**)&NCth,  g_NCth);
    cudaGetSymbolAddress((void**)&NCtl,  g_NCtl);
    cudaGetSymbolAddress((void**)&NSth,  g_NSth);
    cudaGetSymbolAddress((void**)&NStl,  g_NStl);
    cudaGetSymbolAddress((void**)&snorm, g_snorm);
    cudaGetSymbolAddress((void**)&rk,    g_rk);
    cudaGetSymbolAddress((void**)&M0,    g_M0);
    cudaGetSymbolAddress((void**)&Tb,    g_Tb);
    cudaGetSymbolAddress((void**)&idx,   g_idx);
    cudaGetSymbolAddress((void**)&pbs,   g_pbs);
    cudaGetSymbolAddress((void**)&pbi,   g_pbi);
    cudaGetSymbolAddress((void**)&reasT, g_reasT);

    cudaFuncSetAttribute(m0_mma_kernel, cudaFuncAttributeMaxDynamicSharedMemorySize, M0_SMEM);

    // 1) center
    center_kernel<<<dim3(CH, 4), 256>>>(content, style, Fcent, means);

    // 2) covariances
    sgemm_kernel<64, 64, 16, 4, 4, false, true><<<dim3(8, 8, 4), 256>>>(
        Fcent, Fcent, Cov, 512, 512, 4096, CHW, CHW, CC, 1.f / 4095.f, 0.f, nullptr, 0);

    // 3) lambda_max
    power_kernel<<<4, 512>>>(Cov, sigma);

    // 4) Newton-Schulz (5 iterations)
    ns_init_kernel<<<4096, 256>>>(Cov, sigma, Yb, Zb);
    float* Yc = Yb;            float* Yn = Yb + 4 * CC;
    float* Zc = Zb;            float* Zn = Zb + 4 * CC;
    for (int it = 0; it < 5; it++) {
        sgemm_kernel<64, 64, 16, 4, 4, false, false><<<dim3(8, 8, 4), 256>>>(
            Zc, Yc, Tm, 512, 512, 512, CC, CC, CC, -0.5f, 1.5f, nullptr, 0);
        ns_yz_kernel<<<dim3(8, 8, 8), 256>>>(Yc, Tm, Zc, Yn, Zn);
        float* t;
        t = Yc; Yc = Yn; Yn = t;
        t = Zc; Zc = Zn; Zn = t;
    }
    // 5) rescale
    scale_kernel<<<4096, 256>>>(Yc, Zc, sigma, W, Cm);

    // 6) whitening
    sgemm_kernel<128, 128, 16, 8, 8, false, false><<<dim3(32, 4, 4), 256>>>(
        W, Fcent, NC, 512, 4096, 512, CC, CHW, CHW, 1.f, 0.f, nullptr, 0);

    // 7) transpose + tf32 split + patch norms
    transpose_split_kernel<<<dim3(128, 16, 4), dim3(32, 32)>>>(NC, NSt, NCth, NCtl, NSth, NStl);
    snorm_kernel<<<1024, 256>>>(NSt, snorm);
    rknorm_kernel<<<32, 256>>>(snorm, rk);

    // 8) M0 via tf32 mma (3xTF32, RAW-chain-free ordering)
    m0_mma_kernel<<<dim3(32, 32, 2), 256, M0_SMEM>>>(NSth, NStl, NCth, NCtl, M0);

    // 9) box filter + argmax
    boxh_kernel<<<dim3(65536, 2), 256>>>(M0, Tb);
    argmax_part_kernel<<<dim3(16, 16, 2), 256>>>(Tb, rk, pbs, pbi);
    argmax_comb_kernel<<<32, 256>>>(pbs, pbi, idx);

    // 10) gather + overlap-add
    gather_kernel<<<dim3(4096, 2), 128>>>(NSt, idx, reasT);

    // 11) color
    sgemm_kernel<128, 128, 16, 8, 8, false, true><<<dim3(32, 4, 2), 256>>>(
        Cm, reasT, out, 512, 4096, 512, CC, CHW, CHW, 1.f, 0.f, means + 2 * CH, CH);
}

// round 11
// speedup vs baseline: 1.1637x; 1.1637x over previous
#include <cuda_runtime.h>
#include <cuda_fp16.h>
#include <math.h>
#include <float.h>
#include <stdint.h>

// ---------------- problem constants ----------------
#define CH   512
#define HW   4096
constexpr long long CHW = (long long)CH * HW;
constexpr long long CC  = (long long)CH * CH;
constexpr long long PQ  = (long long)HW * HW;

// ---------------- device scratch ----------------
__device__ float  g_Fcent[4 * 2097152];
__device__ float  g_means[4 * 512];
__device__ float  g_Cov[4 * 262144];
__device__ float  g_sigma[4];
__device__ float  g_Ybuf[2 * 1048576];
__device__ float  g_Zbuf[2 * 1048576];
__device__ float  g_Tm[1048576];
__device__ float  g_W[1048576];
__device__ float  g_Cm[2 * 262144];
__device__ float  g_NC[4 * 2097152];
__device__ float  g_NSt[2 * 2097152];
__device__ __half g_NCth[2 * 2097152];   // content^T hi (fp16)
__device__ __half g_NCtl[2 * 2097152];   // content^T lo
__device__ __half g_NSth[2 * 2097152];   // style^T hi
__device__ __half g_NStl[2 * 2097152];   // style^T lo
__device__ float  g_snorm[2 * 4096];
__device__ float  g_rk[2 * 4096];
__device__ float  g_M0[33554432];
__device__ float  g_Tb[33554432];
__device__ int    g_idx[2 * 4096];
__device__ float  g_pbs[2 * 16 * 4096];
__device__ int    g_pbi[2 * 16 * 4096];
__device__ float  g_reasT[2 * 2097152];

// ---------------- packed f32x2 helpers (SIMT GEMM stages) ----------------
typedef unsigned long long u64;
__device__ __forceinline__ u64 pack2(float x) {
    u64 r; asm("mov.b64 %0, {%1, %1};" : "=l"(r) : "f"(x)); return r;
}
__device__ __forceinline__ void ffma2(u64 &d, u64 a, u64 b) {
    asm("fma.rn.f32x2 %0, %1, %2, %3;" : "=l"(d) : "l"(a), "l"(b), "l"(d));
}
__device__ __forceinline__ float2 unpack2(u64 v) {
    float2 f; asm("mov.b64 {%0, %1}, %2;" : "=f"(f.x), "=f"(f.y) : "l"(v)); return f;
}

__device__ __forceinline__ uint32_t smem_to_u32(const void* p) {
    uint32_t a;
    asm("{ .reg .u64 t; cvta.to.shared.u64 t, %1; cvt.u32.u64 %0, t; }" : "=r"(a) : "l"(p));
    return a;
}
__device__ __forceinline__ void cp_async16(uint32_t saddr, const void* g) {
    asm volatile("cp.async.cg.shared.global [%0], [%1], 16;" :: "r"(saddr), "l"(g));
}
#define CP_COMMIT() asm volatile("cp.async.commit_group;" ::: "memory")
#define CP_WAIT1()  asm volatile("cp.async.wait_group 1;" ::: "memory")
#define CP_WAIT0()  asm volatile("cp.async.wait_group 0;" ::: "memory")

// ---------------- warp-level fp16 MMA (m16n8k16, f32 accum) ----------------
__device__ __forceinline__ void mma_f16(float* c, const uint32_t* a, const uint32_t* b) {
    asm volatile(
        "mma.sync.aligned.m16n8k16.row.col.f32.f16.f16.f32 "
        "{%0,%1,%2,%3}, {%4,%5,%6,%7}, {%8,%9}, {%0,%1,%2,%3};"
        : "+f"(c[0]), "+f"(c[1]), "+f"(c[2]), "+f"(c[3])
        : "r"(a[0]), "r"(a[1]), "r"(a[2]), "r"(a[3]), "r"(b[0]), "r"(b[1]));
}

// ---------------- M0 tensor-core kernel (3x fp16-split, cp.async double-buffered) ----------------
// D[128 x 128] per block = A[128 x 512] * B[128 x 512]^T, K staged in chunks of 32.
#define SKPH 40                              // smem row stride in halves (32 data + 8 pad)
constexpr int M0_ARRH = 128 * SKPH;          // halves per operand tile
constexpr int M0_BUFH = 4 * M0_ARRH;         // halves per pipeline buffer
constexpr int M0_SMEM = 2 * M0_BUFH * 2;     // bytes (81920)

__global__ void __launch_bounds__(256, 2) m0_mma_kernel(
    const __half* __restrict__ Ah, const __half* __restrict__ Al,
    const __half* __restrict__ Bh, const __half* __restrict__ Bl,
    float* __restrict__ M0out)
{
    extern __shared__ __half smh[];
    const uint32_t sbase = smem_to_u32(smh);
    const int tid  = threadIdx.x;
    const int wid  = tid >> 5, lane = tid & 31;
    const int g    = lane >> 2, t = lane & 3;
    const int wm   = wid & 3, wn = wid >> 2;
    const int m0   = blockIdx.y * 128, n0 = blockIdx.x * 128;
    const int b    = blockIdx.z;
    const __half* arr0 = Ah + (long long)b * CHW;
    const __half* arr1 = Al + (long long)b * CHW;
    const __half* arr2 = Bh + (long long)b * CHW;
    const __half* arr3 = Bl + (long long)b * CHW;

    // staging: 4 arrays x 128 rows x 32 halves = 2048 x 16B loads, 8 per thread
    auto stage = [&](int kt, int buf) {
#pragma unroll
        for (int tt = 0; tt < 8; tt++) {
            int idx = tid + tt * 256;
            int a   = idx >> 9;
            int rem = idx & 511;
            int r   = rem >> 2;
            int c8  = (rem & 3) * 8;
            const __half* src = (a == 0) ? arr0 : (a == 1) ? arr1 : (a == 2) ? arr2 : arr3;
            int rowbase = (a < 2) ? m0 : n0;
            const __half* gp = src + (long long)(rowbase + r) * CH + kt * 32 + c8;
            uint32_t sa = sbase + (uint32_t)(buf * M0_BUFH + a * M0_ARRH + r * SKPH + c8) * 2u;
            cp_async16(sa, gp);
        }
    };

    float acc[2][8][4];
#pragma unroll
    for (int i = 0; i < 2; i++)
#pragma unroll
        for (int j = 0; j < 8; j++)
#pragma unroll
            for (int k = 0; k < 4; k++) acc[i][j][k] = 0.f;

    stage(0, 0); CP_COMMIT();

    for (int kt = 0; kt < 16; kt++) {          // K = 512 in chunks of 32
        const int buf = kt & 1;
        if (kt + 1 < 16) { stage(kt + 1, buf ^ 1); CP_COMMIT(); CP_WAIT1(); }
        else             { CP_WAIT0(); }
        __syncthreads();

        const __half* sAh = smh + buf * M0_BUFH;
        const __half* sAl = sAh + M0_ARRH;
        const __half* sBh = sAl + M0_ARRH;
        const __half* sBl = sBh + M0_ARRH;
#pragma unroll
        for (int ks = 0; ks < 32; ks += 16) {
            uint32_t afh[2][4], afl[2][4];
#pragma unroll
            for (int mt = 0; mt < 2; mt++) {
                int r  = wm * 32 + mt * 16;
                int i0 = (r + g) * SKPH + ks + 2 * t;
                int i8 = (r + g + 8) * SKPH + ks + 2 * t;
                afh[mt][0] = *(const uint32_t*)&sAh[i0];
                afh[mt][1] = *(const uint32_t*)&sAh[i8];
                afh[mt][2] = *(const uint32_t*)&sAh[i0 + 8];
                afh[mt][3] = *(const uint32_t*)&sAh[i8 + 8];
                afl[mt][0] = *(const uint32_t*)&sAl[i0];
                afl[mt][1] = *(const uint32_t*)&sAl[i8];
                afl[mt][2] = *(const uint32_t*)&sAl[i0 + 8];
                afl[mt][3] = *(const uint32_t*)&sAl[i8 + 8];
            }
#pragma unroll
            for (int nt = 0; nt < 8; nt++) {
                int bb = (wn * 64 + nt * 8 + g) * SKPH + ks + 2 * t;
                uint32_t bfh[2] = { *(const uint32_t*)&sBh[bb], *(const uint32_t*)&sBh[bb + 8] };
                uint32_t bfl[2] = { *(const uint32_t*)&sBl[bb], *(const uint32_t*)&sBl[bb + 8] };
#pragma unroll
                for (int mt = 0; mt < 2; mt++) {
                    mma_f16(acc[mt][nt], afh[mt], bfh);
                    mma_f16(acc[mt][nt], afh[mt], bfl);
                    mma_f16(acc[mt][nt], afl[mt], bfh);
                }
            }
        }
        __syncthreads();
    }

#pragma unroll
    for (int mt = 0; mt < 2; mt++) {
        int row = m0 + wm * 32 + mt * 16 + g;
        float* r0 = M0out + (long long)b * PQ + (long long)row * HW;
        float* r1 = r0 + 8ll * HW;
#pragma unroll
        for (int nt = 0; nt < 8; nt++) {
            int col = n0 + wn * 64 + nt * 8 + 2 * t;
            float2 v0; v0.x = acc[mt][nt][0]; v0.y = acc[mt][nt][1];
            float2 v1; v1.x = acc[mt][nt][2]; v1.y = acc[mt][nt][3];
            *(float2*)&r0[col] = v0;
            *(float2*)&r1[col] = v1;
        }
    }
}

// ---------------- double-buffered pipelined SGEMM (f32x2 inner loop) ----------------
template<int BM, int BN, int BK, int TM, int TN, bool TA, bool TB>
__device__ __forceinline__ void sgemm_tile(
    const float* __restrict__ Ab, const float* __restrict__ Bb, float* __restrict__ Cb,
    int M, int N, int K, float alpha, float diagAdd, const float* __restrict__ bias)
{
    constexpr int THREADS = (BM / TM) * (BN / TN);
    constexpr int LA4 = BM * BK / (4 * THREADS);
    constexpr int LB4 = BN * BK / (4 * THREADS);
    __shared__ float As[2][BK][BM + 4];
    __shared__ float Bs[2][BK][BN + 4];
    const int tid  = threadIdx.x;
    const int tcol = tid % (BN / TN);
    const int trow = tid / (BN / TN);
    const int m0 = blockIdx.y * BM;
    const int n0 = blockIdx.x * BN;

    float4 stA[LA4], stB[LB4];

    auto loadA = [&](int k0) {
#pragma unroll
        for (int l = 0; l < LA4; l++) {
            int i = tid + l * THREADS;
            if (TA) { int kk = i / (BM / 4); int m = (i % (BM / 4)) * 4;
                      stA[l] = *(const float4*)&Ab[(long long)(k0 + kk) * M + m0 + m]; }
            else    { int m = i / (BK / 4); int kk = (i % (BK / 4)) * 4;
                      stA[l] = *(const float4*)&Ab[(long long)(m0 + m) * K + k0 + kk]; }
        }
    };
    auto loadB = [&](int k0) {
#pragma unroll
        for (int l = 0; l < LB4; l++) {
            int i = tid + l * THREADS;
            if (TB) { int n = i / (BK / 4); int kk = (i % (BK / 4)) * 4;
                      stB[l] = *(const float4*)&Bb[(long long)(n0 + n) * K + k0 + kk]; }
            else    { int kk = i / (BN / 4); int n = (i % (BN / 4)) * 4;
                      stB[l] = *(const float4*)&Bb[(long long)(k0 + kk) * N + n0 + n]; }
        }
    };
    auto storeA = [&](int buf) {
#pragma unroll
        for (int l = 0; l < LA4; l++) {
            int i = tid + l * THREADS;
            if (TA) { int kk = i / (BM / 4); int m = (i % (BM / 4)) * 4;
                      *(float4*)&As[buf][kk][m] = stA[l]; }
            else    { int m = i / (BK / 4); int kk = (i % (BK / 4)) * 4;
                      As[buf][kk + 0][m] = stA[l].x; As[buf][kk + 1][m] = stA[l].y;
                      As[buf][kk + 2][m] = stA[l].z; As[buf][kk + 3][m] = stA[l].w; }
        }
    };
    auto storeB = [&](int buf) {
#pragma unroll
        for (int l = 0; l < LB4; l++) {
            int i = tid + l * THREADS;
            if (TB) { int n = i / (BK / 4); int kk = (i % (BK / 4)) * 4;
                      Bs[buf][kk + 0][n] = stB[l].x; Bs[buf][kk + 1][n] = stB[l].y;
                      Bs[buf][kk + 2][n] = stB[l].z; Bs[buf][kk + 3][n] = stB[l].w; }
            else    { int kk = i / (BN / 4); int n = (i % (BN / 4)) * 4;
                      *(float4*)&Bs[buf][kk][n] = stB[l]; }
        }
    };

    u64 acc[TM][TN / 2];
#pragma unroll
    for (int i = 0; i < TM; i++)
#pragma unroll
        for (int j = 0; j < TN / 2; j++) acc[i][j] = 0ull;

    loadA(0); loadB(0);
    storeA(0); storeB(0);
    __syncthreads();

    int buf = 0;
    for (int k0 = 0; k0 < K; k0 += BK) {
        const bool has_next = (k0 + BK < K);
        if (has_next) { loadA(k0 + BK); loadB(k0 + BK); }
#pragma unroll
        for (int kk = 0; kk < BK; kk++) {
            float ra[TM];
#pragma unroll
            for (int i4 = 0; i4 < TM / 4; i4++) {
                float4 a4 = *(const float4*)&As[buf][kk][trow * TM + i4 * 4];
                ra[i4 * 4 + 0] = a4.x; ra[i4 * 4 + 1] = a4.y;
                ra[i4 * 4 + 2] = a4.z; ra[i4 * 4 + 3] = a4.w;
            }
            u64 rb2[TN / 2];
#pragma unroll
            for (int j4 = 0; j4 < TN / 4; j4++) {
                ulonglong2 b2 = *(const ulonglong2*)&Bs[buf][kk][tcol * TN + j4 * 4];
                rb2[j4 * 2 + 0] = b2.x; rb2[j4 * 2 + 1] = b2.y;
            }
#pragma unroll
            for (int i = 0; i < TM; i++) {
                u64 a2 = pack2(ra[i]);
#pragma unroll
                for (int j = 0; j < TN / 2; j++) ffma2(acc[i][j], a2, rb2[j]);
            }
        }
        if (has_next) { storeA(buf ^ 1); storeB(buf ^ 1); }
        __syncthreads();
        buf ^= 1;
    }

#pragma unroll
    for (int i = 0; i < TM; i++) {
        int gm = m0 + trow * TM + i;
        float bv = bias ? bias[gm] : 0.f;
#pragma unroll
        for (int j = 0; j < TN / 2; j++) {
            float2 v = unpack2(acc[i][j]);
            int gn = n0 + tcol * TN + 2 * j;
            float x = alpha * v.x + bv; if (gm == gn)     x += diagAdd;
            float y = alpha * v.y + bv; if (gm == gn + 1) y += diagAdd;
            float2 o; o.x = x; o.y = y;
            *(float2*)&Cb[(long long)gm * N + gn] = o;
        }
    }
}

template<int BM, int BN, int BK, int TM, int TN, bool TA, bool TB>
__global__ void sgemm_kernel(const float* __restrict__ A, const float* __restrict__ B,
                             float* __restrict__ C,
                             int M, int N, int K,
                             long long sA, long long sB, long long sC,
                             float alpha, float diagAdd,
                             const float* __restrict__ bias, int biasStride)
{
    const float* Ab = A + (long long)blockIdx.z * sA;
    const float* Bb = B + (long long)blockIdx.z * sB;
    float* Cb = C + (long long)blockIdx.z * sC;
    const float* bb = bias ? bias + (long long)blockIdx.z * biasStride : nullptr;
    sgemm_tile<BM, BN, BK, TM, TN, TA, TB>(Ab, Bb, Cb, M, N, K, alpha, diagAdd, bb);
}

__global__ void ns_yz_kernel(const float* __restrict__ Y, const float* __restrict__ T,
                             const float* __restrict__ Z,
                             float* __restrict__ Yn, float* __restrict__ Zn)
{
    int z = blockIdx.z;
    const float *Ab, *Bb; float* Cb;
    if (z < 4) { Ab = Y + (long long)z * CC;       Bb = T + (long long)z * CC;       Cb = Yn + (long long)z * CC; }
    else       { Ab = T + (long long)(z - 4) * CC; Bb = Z + (long long)(z - 4) * CC; Cb = Zn + (long long)(z - 4) * CC; }
    sgemm_tile<64, 64, 16, 4, 4, false, false>(Ab, Bb, Cb, 512, 512, 512, 1.f, 0.f, nullptr);
}

// ---------------- per-channel mean + center ----------------
__global__ void center_kernel(const float* __restrict__ content, const float* __restrict__ style,
                              float* __restrict__ Fcent, float* __restrict__ means)
{
    int c = blockIdx.x, g = blockIdx.y;
    const float* src = (g < 2 ? content + (long long)g * CHW : style + (long long)(g - 2) * CHW)
                       + (long long)c * HW;
    __shared__ float red[256];
    float s = 0.f;
    for (int i = threadIdx.x; i < HW; i += 256) s += src[i];
    red[threadIdx.x] = s; __syncthreads();
    for (int st = 128; st > 0; st >>= 1) {
        if (threadIdx.x < st) red[threadIdx.x] += red[threadIdx.x + st];
        __syncthreads();
    }
    float mean = red[0] * (1.f / HW);
    if (threadIdx.x == 0) means[g * CH + c] = mean;
    float* dst = Fcent + (long long)g * CHW + (long long)c * HW;
    for (int i = threadIdx.x; i < HW; i += 256) dst[i] = src[i] - mean;
}

// ---------------- power iteration ----------------
__global__ void power_kernel(const float* __restrict__ Cov, float* __restrict__ sigma)
{
    int g = blockIdx.x;
    const float* A = Cov + (long long)g * CC;
    __shared__ float v[CH];
    __shared__ float red[CH];
    int t = threadIdx.x;
    v[t] = 1.f + 1e-4f * t;
    __syncthreads();
    float lam = 0.f;
    for (int it = 0; it < 40; it++) {
        float acc = 0.f;
        for (int k = 0; k < CH; k++) acc = fmaf(A[(long long)k * CH + t], v[k], acc);
        __syncthreads();
        red[t] = acc * acc; __syncthreads();
        for (int st = 256; st > 0; st >>= 1) {
            if (t < st) red[t] += red[t + st];
            __syncthreads();
        }
        float n2 = red[0];
        lam = sqrtf(n2);
        float inv = (n2 > 0.f) ? rsqrtf(n2) : 0.f;
        __syncthreads();
        v[t] = acc * inv;
        __syncthreads();
    }
    if (t == 0) sigma[g] = lam * 1.02f + 1e-20f;
}

// ---------------- Newton-Schulz init / rescale ----------------
__global__ void ns_init_kernel(const float* __restrict__ Cov, const float* __restrict__ sigma,
                               float* __restrict__ Y, float* __restrict__ Z)
{
    long long i = (long long)blockIdx.x * blockDim.x + threadIdx.x;
    if (i >= 4 * CC) return;
    int g = (int)(i / CC);
    long long r = i % CC;
    int row = (int)(r / CH), col = (int)(r % CH);
    Y[i] = Cov[i] / sigma[g];
    Z[i] = (row == col) ? 1.f : 0.f;
}

__global__ void scale_kernel(const float* __restrict__ Y, const float* __restrict__ Z,
                             const float* __restrict__ sigma,
                             float* __restrict__ W, float* __restrict__ Cm)
{
    long long i = (long long)blockIdx.x * blockDim.x + threadIdx.x;
    if (i >= 4 * CC) return;
    int g = (int)(i / CC);
    float sq = sqrtf(sigma[g]);
    W[i] = Z[i] / sq;
    if (g >= 2) Cm[i - 2 * CC] = Y[i] * sq;
}

// ---------------- transpose + fp16 hi/lo split ----------------
__global__ void transpose_split_kernel(const float* __restrict__ NC,
                                       float* __restrict__ NSt,
                                       __half* __restrict__ NCth, __half* __restrict__ NCtl,
                                       __half* __restrict__ NSth, __half* __restrict__ NStl)
{
    __shared__ float tile[32][33];
    int g = blockIdx.z;
    int p0 = blockIdx.x * 32, c0 = blockIdx.y * 32;
    const float* src = NC + (long long)g * CHW;
    tile[threadIdx.y][threadIdx.x] = src[(long long)(c0 + threadIdx.y) * HW + p0 + threadIdx.x];
    __syncthreads();
    float x = tile[threadIdx.x][threadIdx.y];
    long long o = (long long)(g & 1) * CHW + (long long)(p0 + threadIdx.y) * CH + c0 + threadIdx.x;
    __half hi = __float2half_rn(x);
    __half lo = __float2half_rn(x - __half2float(hi));
    if (g < 2) { NCth[o] = hi; NCtl[o] = lo; }
    else       { NSt[o] = x; NSth[o] = hi; NStl[o] = lo; }
}

// ---------------- per-pixel squared norms ----------------
__global__ void snorm_kernel(const float* __restrict__ NSt, float* __restrict__ snorm)
{
    int gw = (blockIdx.x * blockDim.x + threadIdx.x) >> 5;
    int lane = threadIdx.x & 31;
    if (gw >= 2 * HW) return;
    int b = gw / HW, p = gw % HW;
    const float* row = NSt + (long long)b * CHW + (long long)p * CH;
    float s = 0.f;
    for (int c = lane; c < CH; c += 32) { float v = row[c]; s = fmaf(v, v, s); }
    for (int o = 16; o > 0; o >>= 1) s += __shfl_down_sync(0xffffffff, s, o);
    if (lane == 0) snorm[b * HW + p] = s;
}

__global__ void rknorm_kernel(const float* __restrict__ snorm, float* __restrict__ rk)
{
    int i = blockIdx.x * blockDim.x + threadIdx.x;
    if (i >= 2 * HW) return;
    int b = i / HW, p = i % HW;
    int py = p >> 6, px = p & 63;
    float sum = 0.f;
    for (int u = -1; u <= 1; u++)
        for (int v = -1; v <= 1; v++) {
            int yy = py + u, xx = px + v;
            if ((unsigned)yy < 64u && (unsigned)xx < 64u) sum += snorm[b * HW + yy * 64 + xx];
        }
    rk[i] = 1.f / (sqrtf(sum) + 1e-5f);
}

// ---------------- horizontal diagonal 3-box ----------------
__global__ void boxh_kernel(const float* __restrict__ M0, float* __restrict__ Tb)
{
    long long i = (long long)blockIdx.x * 256 + threadIdx.x;
    int b = blockIdx.y;
    const float* M = M0 + (long long)b * PQ;
    int p = (int)(i >> 12);
    int q = (int)(i & 4095);
    int px = p & 63, qx = q & 63;
    float s = 0.f;
#pragma unroll
    for (int v = -1; v <= 1; v++) {
        if ((unsigned)(px + v) < 64u && (unsigned)(qx + v) < 64u) s += M[i + (long long)v * 4097];
    }
    Tb[(long long)b * PQ + i] = s;
}

// ---------------- vertical diagonal 3-box + partial argmax ----------------
__global__ void argmax_part_kernel(const float* __restrict__ Tb, const float* __restrict__ rk,
                                   float* __restrict__ pbs, int* __restrict__ pbi)
{
    int b = blockIdx.z;
    int q = blockIdx.x * 256 + threadIdx.x;
    int pc = blockIdx.y;
    __shared__ float srk[256];
    srk[threadIdx.x] = rk[b * HW + pc * 256 + threadIdx.x];
    __syncthreads();
    const float* T = Tb + (long long)b * PQ;
    float best = -FLT_MAX; int bi = 0;
    for (int pp = 0; pp < 256; pp++) {
        int p = pc * 256 + pp;
        float s = 0.f;
#pragma unroll
        for (int u = -1; u <= 1; u++) {
            int row = p + 64 * u, col = q + 64 * u;
            if ((unsigned)row < (unsigned)HW && (unsigned)col < (unsigned)HW)
                s += T[(long long)row * HW + col];
        }
        float sc = s * srk[pp];
        if (sc > best) { best = sc; bi = p; }
    }
    pbs[(b * 16 + pc) * HW + q] = best;
    pbi[(b * 16 + pc) * HW + q] = bi;
}

__global__ void argmax_comb_kernel(const float* __restrict__ pbs, const int* __restrict__ pbi,
                                   int* __restrict__ idx)
{
    int i = blockIdx.x * 256 + threadIdx.x;
    if (i >= 2 * HW) return;
    int b = i / HW, q = i % HW;
    float best = -FLT_MAX; int bi = 0;
    for (int k = 0; k < 16; k++) {
        float s = pbs[(b * 16 + k) * HW + q];
        int p = pbi[(b * 16 + k) * HW + q];
        if (s > best || (s == best && p < bi)) { best = s; bi = p; }
    }
    idx[b * HW + q] = bi;
}

// ---------------- gather best patches + overlap-add ----------------
__global__ void gather_kernel(const float* __restrict__ NSt, const int* __restrict__ idx,
                              float* __restrict__ reasT)
{
    int b = blockIdx.y, pix = blockIdx.x;
    int Y = pix >> 6, X = pix & 63;
    __shared__ int sp[9];
    if (threadIdx.x < 9) {
        int dx = threadIdx.x / 3, dy = threadIdx.x % 3;
        int y = Y + 1 - dx, x = X + 1 - dy;
        int pos = -1;
        if ((unsigned)y < 64u && (unsigned)x < 64u) {
            int p = idx[b * HW + y * 64 + x];
            int sy = (p >> 6) + dx - 1, sx = (p & 63) + dy - 1;
            if ((unsigned)sy < 64u && (unsigned)sx < 64u) pos = sy * 64 + sx;
        }
        sp[threadIdx.x] = pos;
    }
    __syncthreads();
    int cy = (Y == 0 || Y == 63) ? 2 : 3;
    int cx = (X == 0 || X == 63) ? 2 : 3;
    float inv = 1.f / (float)(cy * cx);
    const float* base = NSt + (long long)b * CHW;
    float* out = reasT + (long long)b * CHW + (long long)pix * CH;
    for (int c = threadIdx.x; c < CH; c += 128) {
        float a = 0.f;
#pragma unroll
        for (int k = 0; k < 9; k++) {
            int pos = sp[k];
            if (pos >= 0) a += base[(long long)pos * CH + c];
        }
        out[c] = a * inv;
    }
}

// ---------------- host orchestration ----------------
extern "C" void kernel_launch(void* const* d_in, const int* in_sizes, int n_in,
                              void* d_out, int out_size)
{
    (void)in_sizes; (void)n_in; (void)out_size;
    const float* content = (const float*)d_in[0];
    const float* style   = (const float*)d_in[1];
    float* out = (float*)d_out;

    float *Fcent, *means, *Cov, *sigma, *Yb, *Zb, *Tm, *W, *Cm, *NC, *NSt, *snorm, *rk, *M0, *Tb, *pbs, *reasT;
    __half *NCth, *NCtl, *NSth, *NStl;
    int *idx, *pbi;
    cudaGetSymbolAddress((void**)&Fcent, g_Fcent);
    cudaGetSymbolAddress((void**)&means, g_means);
    cudaGetSymbolAddress((void**)&Cov,   g_Cov);
    cudaGetSymbolAddress((void**)&sigma, g_sigma);
    cudaGetSymbolAddress((void**)&Yb,    g_Ybuf);
    cudaGetSymbolAddress((void**)&Zb,    g_Zbuf);
    cudaGetSymbolAddress((void**)&Tm,    g_Tm);
    cudaGetSymbolAddress((void**)&W,     g_W);
    cudaGetSymbolAddress((void**)&Cm,    g_Cm);
    cudaGetSymbolAddress((void**)&NC,    g_NC);
    cudaGetSymbolAddress((void**)&NSt,   g_NSt);
    cudaGetSymbolAddress((void**)&NCth,  g_NCth);
    cudaGetSymbolAddress((void**)&NCtl,  g_NCtl);
    cudaGetSymbolAddress((void**)&NSth,  g_NSth);
    cudaGetSymbolAddress((void**)&NStl,  g_NStl);
    cudaGetSymbolAddress((void**)&snorm, g_snorm);
    cudaGetSymbolAddress((void**)&rk,    g_rk);
    cudaGetSymbolAddress((void**)&M0,    g_M0);
    cudaGetSymbolAddress((void**)&Tb,    g_Tb);
    cudaGetSymbolAddress((void**)&idx,   g_idx);
    cudaGetSymbolAddress((void**)&pbs,   g_pbs);
    cudaGetSymbolAddress((void**)&pbi,   g_pbi);
    cudaGetSymbolAddress((void**)&reasT, g_reasT);

    cudaFuncSetAttribute(m0_mma_kernel, cudaFuncAttributeMaxDynamicSharedMemorySize, M0_SMEM);

    // 1) center
    center_kernel<<<dim3(CH, 4), 256>>>(content, style, Fcent, means);

    // 2) covariances
    sgemm_kernel<64, 64, 16, 4, 4, false, true><<<dim3(8, 8, 4), 256>>>(
        Fcent, Fcent, Cov, 512, 512, 4096, CHW, CHW, CC, 1.f / 4095.f, 0.f, nullptr, 0);

    // 3) lambda_max
    power_kernel<<<4, 512>>>(Cov, sigma);

    // 4) Newton-Schulz (5 iterations)
    ns_init_kernel<<<4096, 256>>>(Cov, sigma, Yb, Zb);
    float* Yc = Yb;            float* Yn = Yb + 4 * CC;
    float* Zc = Zb;            float* Zn = Zb + 4 * CC;
    for (int it = 0; it < 5; it++) {
        sgemm_kernel<64, 64, 16, 4, 4, false, false><<<dim3(8, 8, 4), 256>>>(
            Zc, Yc, Tm, 512, 512, 512, CC, CC, CC, -0.5f, 1.5f, nullptr, 0);
        ns_yz_kernel<<<dim3(8, 8, 8), 256>>>(Yc, Tm, Zc, Yn, Zn);
        float* t;
        t = Yc; Yc = Yn; Yn = t;
        t = Zc; Zc = Zn; Zn = t;
    }
    // 5) rescale
    scale_kernel<<<4096, 256>>>(Yc, Zc, sigma, W, Cm);

    // 6) whitening
    sgemm_kernel<128, 128, 16, 8, 8, false, false><<<dim3(32, 4, 4), 256>>>(
        W, Fcent, NC, 512, 4096, 512, CC, CHW, CHW, 1.f, 0.f, nullptr, 0);

    // 7) transpose + fp16 split + patch norms
    transpose_split_kernel<<<dim3(128, 16, 4), dim3(32, 32)>>>(NC, NSt, NCth, NCtl, NSth, NStl);
    snorm_kernel<<<1024, 256>>>(NSt, snorm);
    rknorm_kernel<<<32, 256>>>(snorm, rk);

    // 8) M0 via fp16 m16n8k16 mma (3-product split, cp.async pipelined)
    m0_mma_kernel<<<dim3(32, 32, 2), 256, M0_SMEM>>>(NSth, NStl, NCth, NCtl, M0);

    // 9) box filter + argmax
    boxh_kernel<<<dim3(65536, 2), 256>>>(M0, Tb);
    argmax_part_kernel<<<dim3(16, 16, 2), 256>>>(Tb, rk, pbs, pbi);
    argmax_comb_kernel<<<32, 256>>>(pbs, pbi, idx);

    // 10) gather + overlap-add
    gather_kernel<<<dim3(4096, 2), 128>>>(NSt, idx, reasT);

    // 11) color
    sgemm_kernel<128, 128, 16, 8, 8, false, true><<<dim3(32, 4, 2), 256>>>(
        Cm, reasT, out, 512, 4096, 512, CC, CHW, CHW, 1.f, 0.f, means + 2 * CH, CH);
}

// round 12
// speedup vs baseline: 1.2130x; 1.0424x over previous
#include <cuda_runtime.h>
#include <cuda_fp16.h>
#include <math.h>
#include <float.h>
#include <stdint.h>

// ---------------- problem constants ----------------
#define CH   512
#define HW   4096
constexpr long long CHW = (long long)CH * HW;     // 2,097,152
constexpr long long CC  = (long long)CH * CH;     // 262,144
constexpr long long PQ  = (long long)HW * HW;

// ---------------- device scratch ----------------
__device__ float  g_Fcent[4 * 2097152];
__device__ __half g_Fch[4 * 2097152];
__device__ __half g_Fcl[4 * 2097152];
__device__ __half g_FcTh[4 * 2097152];
__device__ __half g_FcTl[4 * 2097152];
__device__ float  g_means[4 * 512];
__device__ float  g_Cov[4 * 262144];
__device__ float  g_sigma[4];
__device__ float  g_Yf[2 * 4 * 262144];
__device__ float  g_Zf[2 * 4 * 262144];
__device__ __half g_Yh[2 * 4 * 262144];
__device__ __half g_Yl[2 * 4 * 262144];
__device__ __half g_Zh[2 * 4 * 262144];
__device__ __half g_Zl[2 * 4 * 262144];
__device__ __half g_Th[4 * 262144];
__device__ __half g_Tl[4 * 262144];
__device__ __half g_Wh[4 * 262144];
__device__ __half g_Wl[4 * 262144];
__device__ __half g_Cmh[2 * 262144];
__device__ __half g_Cml[2 * 262144];
__device__ float  g_NSt[2 * 2097152];
__device__ __half g_NCth[2 * 2097152];
__device__ __half g_NCtl[2 * 2097152];
__device__ __half g_NSth[2 * 2097152];
__device__ __half g_NStl[2 * 2097152];
__device__ float  g_snorm[2 * 4096];
__device__ float  g_rk[2 * 4096];
__device__ float  g_M0[33554432];
__device__ float  g_Tb[33554432];
__device__ int    g_idx[2 * 4096];
__device__ float  g_pbs[2 * 16 * 4096];
__device__ int    g_pbi[2 * 16 * 4096];
__device__ __half g_rTh[2 * 2097152];
__device__ __half g_rTl[2 * 2097152];

// ---------------- helpers ----------------
__device__ __forceinline__ uint32_t smem_to_u32(const void* p) {
    uint32_t a;
    asm("{ .reg .u64 t; cvta.to.shared.u64 t, %1; cvt.u32.u64 %0, t; }" : "=r"(a) : "l"(p));
    return a;
}
__device__ __forceinline__ void cp_async16(uint32_t saddr, const void* g) {
    asm volatile("cp.async.cg.shared.global [%0], [%1], 16;" :: "r"(saddr), "l"(g));
}
#define CP_COMMIT() asm volatile("cp.async.commit_group;" ::: "memory")
#define CP_WAIT1()  asm volatile("cp.async.wait_group 1;" ::: "memory")
#define CP_WAIT0()  asm volatile("cp.async.wait_group 0;" ::: "memory")

__device__ __forceinline__ void mma_f16(float* c, const uint32_t* a, const uint32_t* b) {
    asm volatile(
        "mma.sync.aligned.m16n8k16.row.col.f32.f16.f16.f32 "
        "{%0,%1,%2,%3}, {%4,%5,%6,%7}, {%8,%9}, {%0,%1,%2,%3};"
        : "+f"(c[0]), "+f"(c[1]), "+f"(c[2]), "+f"(c[3])
        : "r"(a[0]), "r"(a[1]), "r"(a[2]), "r"(a[3]), "r"(b[0]), "r"(b[1]));
}

__device__ __forceinline__ void split_store(__half* Ch, __half* Cl, long long off,
                                            float x, float y) {
    __half hx = __float2half_rn(x), hy = __float2half_rn(y);
    __half lx = __float2half_rn(x - __half2float(hx));
    __half ly = __float2half_rn(y - __half2float(hy));
    *(__half2*)&Ch[off] = __halves2half2(hx, hy);
    *(__half2*)&Cl[off] = __halves2half2(lx, ly);
}

// ---------------- generic fp16-split 3-product MMA GEMM tile ----------------
// C[128x128 tile] = alpha * A @ B^T (+diagAdd on diag) (+bias[row])
// A: [*, K] hi/lo row-major; B: [*, K] hi/lo row-major; both row stride K.
// Outputs (any may be null): Cf (fp32), Ch/Cl (fp16 split), all row stride ldC.
#define SKPH 40
constexpr int HG_ARRH = 128 * SKPH;
constexpr int HG_BUFH = 4 * HG_ARRH;
constexpr int HG_SMEM = 2 * HG_BUFH * 2;     // 81920 bytes

__device__ __forceinline__ void hgemm_tile(
    const __half* __restrict__ Ah, const __half* __restrict__ Al,
    const __half* __restrict__ Bh, const __half* __restrict__ Bl,
    float* __restrict__ Cf, __half* __restrict__ Ch, __half* __restrict__ Cl,
    int ldC, int K, float alpha, float diagAdd, const float* __restrict__ bias,
    __half* smh)
{
    const uint32_t sbase = smem_to_u32(smh);
    const int tid  = threadIdx.x;
    const int wid  = tid >> 5, lane = tid & 31;
    const int g    = lane >> 2, t = lane & 3;
    const int wm   = wid & 3, wn = wid >> 2;
    const int m0   = blockIdx.y * 128, n0 = blockIdx.x * 128;

    auto stage = [&](int kt, int buf) {
#pragma unroll
        for (int tt = 0; tt < 8; tt++) {
            int idx = tid + tt * 256;
            int a   = idx >> 9;
            int rem = idx & 511;
            int r   = rem >> 2;
            int c8  = (rem & 3) * 8;
            const __half* src = (a == 0) ? Ah : (a == 1) ? Al : (a == 2) ? Bh : Bl;
            int rowbase = (a < 2) ? m0 : n0;
            const __half* gp = src + (long long)(rowbase + r) * K + kt * 32 + c8;
            uint32_t sa = sbase + (uint32_t)(buf * HG_BUFH + a * HG_ARRH + r * SKPH + c8) * 2u;
            cp_async16(sa, gp);
        }
    };

    float acc[2][8][4];
#pragma unroll
    for (int i = 0; i < 2; i++)
#pragma unroll
        for (int j = 0; j < 8; j++)
#pragma unroll
            for (int k = 0; k < 4; k++) acc[i][j][k] = 0.f;

    const int nk = K >> 5;
    stage(0, 0); CP_COMMIT();

    for (int kt = 0; kt < nk; kt++) {
        const int buf = kt & 1;
        if (kt + 1 < nk) { stage(kt + 1, buf ^ 1); CP_COMMIT(); CP_WAIT1(); }
        else             { CP_WAIT0(); }
        __syncthreads();

        const __half* sAh = smh + buf * HG_BUFH;
        const __half* sAl = sAh + HG_ARRH;
        const __half* sBh = sAl + HG_ARRH;
        const __half* sBl = sBh + HG_ARRH;
#pragma unroll
        for (int ks = 0; ks < 32; ks += 16) {
            uint32_t afh[2][4], afl[2][4];
#pragma unroll
            for (int mt = 0; mt < 2; mt++) {
                int r  = wm * 32 + mt * 16;
                int i0 = (r + g) * SKPH + ks + 2 * t;
                int i8 = (r + g + 8) * SKPH + ks + 2 * t;
                afh[mt][0] = *(const uint32_t*)&sAh[i0];
                afh[mt][1] = *(const uint32_t*)&sAh[i8];
                afh[mt][2] = *(const uint32_t*)&sAh[i0 + 8];
                afh[mt][3] = *(const uint32_t*)&sAh[i8 + 8];
                afl[mt][0] = *(const uint32_t*)&sAl[i0];
                afl[mt][1] = *(const uint32_t*)&sAl[i8];
                afl[mt][2] = *(const uint32_t*)&sAl[i0 + 8];
                afl[mt][3] = *(const uint32_t*)&sAl[i8 + 8];
            }
#pragma unroll
            for (int nt = 0; nt < 8; nt++) {
                int bb = (wn * 64 + nt * 8 + g) * SKPH + ks + 2 * t;
                uint32_t bfh[2] = { *(const uint32_t*)&sBh[bb], *(const uint32_t*)&sBh[bb + 8] };
                uint32_t bfl[2] = { *(const uint32_t*)&sBl[bb], *(const uint32_t*)&sBl[bb + 8] };
#pragma unroll
                for (int mt = 0; mt < 2; mt++) {
                    mma_f16(acc[mt][nt], afh[mt], bfh);
                    mma_f16(acc[mt][nt], afh[mt], bfl);
                    mma_f16(acc[mt][nt], afl[mt], bfh);
                }
            }
        }
        __syncthreads();
    }

#pragma unroll
    for (int mt = 0; mt < 2; mt++) {
        int row0 = m0 + wm * 32 + mt * 16 + g;
        int row1 = row0 + 8;
        float bv0 = bias ? bias[row0] : 0.f;
        float bv1 = bias ? bias[row1] : 0.f;
#pragma unroll
        for (int nt = 0; nt < 8; nt++) {
            int col = n0 + wn * 64 + nt * 8 + 2 * t;
            float x0 = alpha * acc[mt][nt][0] + bv0; if (row0 == col)     x0 += diagAdd;
            float y0 = alpha * acc[mt][nt][1] + bv0; if (row0 == col + 1) y0 += diagAdd;
            float x1 = alpha * acc[mt][nt][2] + bv1; if (row1 == col)     x1 += diagAdd;
            float y1 = alpha * acc[mt][nt][3] + bv1; if (row1 == col + 1) y1 += diagAdd;
            long long o0 = (long long)row0 * ldC + col;
            long long o1 = (long long)row1 * ldC + col;
            if (Cf) {
                float2 v0; v0.x = x0; v0.y = y0; *(float2*)&Cf[o0] = v0;
                float2 v1; v1.x = x1; v1.y = y1; *(float2*)&Cf[o1] = v1;
            }
            if (Ch) {
                split_store(Ch, Cl, o0, x0, y0);
                split_store(Ch, Cl, o1, x1, y1);
            }
        }
    }
}

// ---------------- hgemm wrapper kernels ----------------
__global__ void __launch_bounds__(256, 2) cov16_kernel(
    const __half* __restrict__ Fh, const __half* __restrict__ Fl, float* __restrict__ Cov)
{
    extern __shared__ __half smh[];
    long long o = (long long)blockIdx.z * CHW;
    hgemm_tile(Fh + o, Fl + o, Fh + o, Fl + o,
               Cov + (long long)blockIdx.z * CC, nullptr, nullptr,
               512, 4096, 1.f / 4095.f, 0.f, nullptr, smh);
}

__global__ void __launch_bounds__(256, 2) nsT16_kernel(
    const __half* __restrict__ Zh, const __half* __restrict__ Zl,
    const __half* __restrict__ Yh, const __half* __restrict__ Yl,
    __half* __restrict__ Th, __half* __restrict__ Tl)
{
    extern __shared__ __half smh[];
    long long o = (long long)blockIdx.z * CC;
    hgemm_tile(Zh + o, Zl + o, Yh + o, Yl + o,
               nullptr, Th + o, Tl + o, 512, 512, -0.5f, 1.5f, nullptr, smh);
}

__global__ void __launch_bounds__(256, 2) nsYZ16_kernel(
    const __half* __restrict__ Yh, const __half* __restrict__ Yl,
    const __half* __restrict__ Zh, const __half* __restrict__ Zl,
    const __half* __restrict__ Th, const __half* __restrict__ Tl,
    float* __restrict__ Ynf, __half* __restrict__ Ynh, __half* __restrict__ Ynl,
    float* __restrict__ Znf, __half* __restrict__ Znh, __half* __restrict__ Znl)
{
    extern __shared__ __half smh[];
    int z = blockIdx.z;
    if (z < 4) {
        long long o = (long long)z * CC;
        hgemm_tile(Yh + o, Yl + o, Th + o, Tl + o,
                   Ynf + o, Ynh + o, Ynl + o, 512, 512, 1.f, 0.f, nullptr, smh);
    } else {
        long long o = (long long)(z - 4) * CC;
        hgemm_tile(Th + o, Tl + o, Zh + o, Zl + o,
                   Znf + o, Znh + o, Znl + o, 512, 512, 1.f, 0.f, nullptr, smh);
    }
}

__global__ void __launch_bounds__(256, 2) whiten16_kernel(
    const __half* __restrict__ FcTh, const __half* __restrict__ FcTl,
    const __half* __restrict__ Wh, const __half* __restrict__ Wl,
    float* __restrict__ NSt,
    __half* __restrict__ NCth, __half* __restrict__ NCtl,
    __half* __restrict__ NSth, __half* __restrict__ NStl)
{
    extern __shared__ __half smh[];
    int z = blockIdx.z;
    long long oa = (long long)z * CHW;
    long long ow = (long long)z * CC;
    float* cf; __half *ch, *cl;
    if (z < 2) { cf = nullptr; ch = NCth + oa; cl = NCtl + oa; }
    else       { long long os = (long long)(z - 2) * CHW;
                 cf = NSt + os; ch = NSth + os; cl = NStl + os; }
    hgemm_tile(FcTh + oa, FcTl + oa, Wh + ow, Wl + ow,
               cf, ch, cl, 512, 512, 1.f, 0.f, nullptr, smh);
}

__global__ void __launch_bounds__(256, 2) m016_kernel(
    const __half* __restrict__ Ah, const __half* __restrict__ Al,
    const __half* __restrict__ Bh, const __half* __restrict__ Bl,
    float* __restrict__ M0out)
{
    extern __shared__ __half smh[];
    long long o = (long long)blockIdx.z * CHW;
    hgemm_tile(Ah + o, Al + o, Bh + o, Bl + o,
               M0out + (long long)blockIdx.z * PQ, nullptr, nullptr,
               4096, 512, 1.f, 0.f, nullptr, smh);
}

__global__ void __launch_bounds__(256, 2) color16_kernel(
    const __half* __restrict__ Cmh, const __half* __restrict__ Cml,
    const __half* __restrict__ rTh, const __half* __restrict__ rTl,
    float* __restrict__ out, const float* __restrict__ means)
{
    extern __shared__ __half smh[];
    int b = blockIdx.z;
    hgemm_tile(Cmh + (long long)b * CC, Cml + (long long)b * CC,
               rTh + (long long)b * CHW, rTl + (long long)b * CHW,
               out + (long long)b * CHW, nullptr, nullptr,
               4096, 512, 1.f, 0.f, means + (long long)(2 + b) * CH, smh);
}

// ---------------- per-channel mean + center (+ fp16 split, channel-major) ----------------
__global__ void center_kernel(const float* __restrict__ content, const float* __restrict__ style,
                              float* __restrict__ Fcent, __half* __restrict__ Fch,
                              __half* __restrict__ Fcl, float* __restrict__ means)
{
    int c = blockIdx.x, g = blockIdx.y;
    const float* src = (g < 2 ? content + (long long)g * CHW : style + (long long)(g - 2) * CHW)
                       + (long long)c * HW;
    __shared__ float red[256];
    float s = 0.f;
    for (int i = threadIdx.x; i < HW; i += 256) s += src[i];
    red[threadIdx.x] = s; __syncthreads();
    for (int st = 128; st > 0; st >>= 1) {
        if (threadIdx.x < st) red[threadIdx.x] += red[threadIdx.x + st];
        __syncthreads();
    }
    float mean = red[0] * (1.f / HW);
    if (threadIdx.x == 0) means[g * CH + c] = mean;
    long long base = (long long)g * CHW + (long long)c * HW;
    for (int i = threadIdx.x; i < HW; i += 256) {
        float v = src[i] - mean;
        Fcent[base + i] = v;
        __half h = __float2half_rn(v);
        Fch[base + i] = h;
        Fcl[base + i] = __float2half_rn(v - __half2float(h));
    }
}

// ---------------- transpose + fp16 split of Fcent (pixel-major) ----------------
__global__ void transposeFcT_kernel(const float* __restrict__ Fcent,
                                    __half* __restrict__ FcTh, __half* __restrict__ FcTl)
{
    __shared__ float tile[32][33];
    int g = blockIdx.z;
    int p0 = blockIdx.x * 32, c0 = blockIdx.y * 32;
    tile[threadIdx.y][threadIdx.x] =
        Fcent[(long long)g * CHW + (long long)(c0 + threadIdx.y) * HW + p0 + threadIdx.x];
    __syncthreads();
    float x = tile[threadIdx.x][threadIdx.y];
    long long o = (long long)g * CHW + (long long)(p0 + threadIdx.y) * CH + c0 + threadIdx.x;
    __half h = __float2half_rn(x);
    FcTh[o] = h;
    FcTl[o] = __float2half_rn(x - __half2float(h));
}

// ---------------- power iteration ----------------
__global__ void power_kernel(const float* __restrict__ Cov, float* __restrict__ sigma)
{
    int g = blockIdx.x;
    const float* A = Cov + (long long)g * CC;
    __shared__ float v[CH];
    __shared__ float red[CH];
    int t = threadIdx.x;
    v[t] = 1.f + 1e-4f * t;
    __syncthreads();
    float lam = 0.f;
    for (int it = 0; it < 40; it++) {
        float acc = 0.f;
        for (int k = 0; k < CH; k++) acc = fmaf(A[(long long)k * CH + t], v[k], acc);
        __syncthreads();
        red[t] = acc * acc; __syncthreads();
        for (int st = 256; st > 0; st >>= 1) {
            if (t < st) red[t] += red[t + st];
            __syncthreads();
        }
        float n2 = red[0];
        lam = sqrtf(n2);
        float inv = (n2 > 0.f) ? rsqrtf(n2) : 0.f;
        __syncthreads();
        v[t] = acc * inv;
        __syncthreads();
    }
    if (t == 0) sigma[g] = lam * 1.02f + 1e-20f;
}

// ---------------- Newton-Schulz init (fp16 split) ----------------
__global__ void ns_init_kernel(const float* __restrict__ Cov, const float* __restrict__ sigma,
                               __half* __restrict__ Yh, __half* __restrict__ Yl,
                               __half* __restrict__ Zh, __half* __restrict__ Zl)
{
    long long i = (long long)blockIdx.x * blockDim.x + threadIdx.x;
    if (i >= 4 * CC) return;
    int g = (int)(i / CC);
    long long r = i % CC;
    int row = (int)(r / CH), col = (int)(r % CH);
    float y = Cov[i] / sigma[g];
    __half h = __float2half_rn(y);
    Yh[i] = h;
    Yl[i] = __float2half_rn(y - __half2float(h));
    Zh[i] = __float2half_rn((row == col) ? 1.f : 0.f);
    Zl[i] = __float2half_rn(0.f);
}

// ---------------- rescale -> W, Cm fp16 splits ----------------
__global__ void scale16_kernel(const float* __restrict__ Yf, const float* __restrict__ Zf,
                               const float* __restrict__ sigma,
                               __half* __restrict__ Wh, __half* __restrict__ Wl,
                               __half* __restrict__ Cmh, __half* __restrict__ Cml)
{
    long long i = (long long)blockIdx.x * blockDim.x + threadIdx.x;
    if (i >= 4 * CC) return;
    int g = (int)(i / CC);
    float sq = sqrtf(sigma[g]);
    float w = Zf[i] / sq;
    __half h = __float2half_rn(w);
    Wh[i] = h;
    Wl[i] = __float2half_rn(w - __half2float(h));
    if (g >= 2) {
        float cm = Yf[i] * sq;
        __half hc = __float2half_rn(cm);
        Cmh[i - 2 * CC] = hc;
        Cml[i - 2 * CC] = __float2half_rn(cm - __half2float(hc));
    }
}

// ---------------- per-pixel squared norms ----------------
__global__ void snorm_kernel(const float* __restrict__ NSt, float* __restrict__ snorm)
{
    int gw = (blockIdx.x * blockDim.x + threadIdx.x) >> 5;
    int lane = threadIdx.x & 31;
    if (gw >= 2 * HW) return;
    int b = gw / HW, p = gw % HW;
    const float* row = NSt + (long long)b * CHW + (long long)p * CH;
    float s = 0.f;
    for (int c = lane; c < CH; c += 32) { float v = row[c]; s = fmaf(v, v, s); }
    for (int o = 16; o > 0; o >>= 1) s += __shfl_down_sync(0xffffffff, s, o);
    if (lane == 0) snorm[b * HW + p] = s;
}

__global__ void rknorm_kernel(const float* __restrict__ snorm, float* __restrict__ rk)
{
    int i = blockIdx.x * blockDim.x + threadIdx.x;
    if (i >= 2 * HW) return;
    int b = i / HW, p = i % HW;
    int py = p >> 6, px = p & 63;
    float sum = 0.f;
    for (int u = -1; u <= 1; u++)
        for (int v = -1; v <= 1; v++) {
            int yy = py + u, xx = px + v;
            if ((unsigned)yy < 64u && (unsigned)xx < 64u) sum += snorm[b * HW + yy * 64 + xx];
        }
    rk[i] = 1.f / (sqrtf(sum) + 1e-5f);
}

// ---------------- horizontal diagonal 3-box ----------------
__global__ void boxh_kernel(const float* __restrict__ M0, float* __restrict__ Tb)
{
    long long i = (long long)blockIdx.x * 256 + threadIdx.x;
    int b = blockIdx.y;
    const float* M = M0 + (long long)b * PQ;
    int p = (int)(i >> 12);
    int q = (int)(i & 4095);
    int px = p & 63, qx = q & 63;
    float s = 0.f;
#pragma unroll
    for (int v = -1; v <= 1; v++) {
        if ((unsigned)(px + v) < 64u && (unsigned)(qx + v) < 64u) s += M[i + (long long)v * 4097];
    }
    Tb[(long long)b * PQ + i] = s;
}

// ---------------- vertical diagonal 3-box + partial argmax ----------------
__global__ void argmax_part_kernel(const float* __restrict__ Tb, const float* __restrict__ rk,
                                   float* __restrict__ pbs, int* __restrict__ pbi)
{
    int b = blockIdx.z;
    int q = blockIdx.x * 256 + threadIdx.x;
    int pc = blockIdx.y;
    __shared__ float srk[256];
    srk[threadIdx.x] = rk[b * HW + pc * 256 + threadIdx.x];
    __syncthreads();
    const float* T = Tb + (long long)b * PQ;
    float best = -FLT_MAX; int bi = 0;
    for (int pp = 0; pp < 256; pp++) {
        int p = pc * 256 + pp;
        float s = 0.f;
#pragma unroll
        for (int u = -1; u <= 1; u++) {
            int row = p + 64 * u, col = q + 64 * u;
            if ((unsigned)row < (unsigned)HW && (unsigned)col < (unsigned)HW)
                s += T[(long long)row * HW + col];
        }
        float sc = s * srk[pp];
        if (sc > best) { best = sc; bi = p; }
    }
    pbs[(b * 16 + pc) * HW + q] = best;
    pbi[(b * 16 + pc) * HW + q] = bi;
}

__global__ void argmax_comb_kernel(const float* __restrict__ pbs, const int* __restrict__ pbi,
                                   int* __restrict__ idx)
{
    int i = blockIdx.x * 256 + threadIdx.x;
    if (i >= 2 * HW) return;
    int b = i / HW, q = i % HW;
    float best = -FLT_MAX; int bi = 0;
    for (int k = 0; k < 16; k++) {
        float s = pbs[(b * 16 + k) * HW + q];
        int p = pbi[(b * 16 + k) * HW + q];
        if (s > best || (s == best && p < bi)) { best = s; bi = p; }
    }
    idx[b * HW + q] = bi;
}

// ---------------- gather + overlap-add (emit fp16 split) ----------------
__global__ void gather_kernel(const float* __restrict__ NSt, const int* __restrict__ idx,
                              __half* __restrict__ rTh, __half* __restrict__ rTl)
{
    int b = blockIdx.y, pix = blockIdx.x;
    int Y = pix >> 6, X = pix & 63;
    __shared__ int sp[9];
    if (threadIdx.x < 9) {
        int dx = threadIdx.x / 3, dy = threadIdx.x % 3;
        int y = Y + 1 - dx, x = X + 1 - dy;
        int pos = -1;
        if ((unsigned)y < 64u && (unsigned)x < 64u) {
            int p = idx[b * HW + y * 64 + x];
            int sy = (p >> 6) + dx - 1, sx = (p & 63) + dy - 1;
            if ((unsigned)sy < 64u && (unsigned)sx < 64u) pos = sy * 64 + sx;
        }
        sp[threadIdx.x] = pos;
    }
    __syncthreads();
    int cy = (Y == 0 || Y == 63) ? 2 : 3;
    int cx = (X == 0 || X == 63) ? 2 : 3;
    float inv = 1.f / (float)(cy * cx);
    const float* base = NSt + (long long)b * CHW;
    long long obase = (long long)b * CHW + (long long)pix * CH;
    for (int c = threadIdx.x; c < CH; c += 128) {
        float a = 0.f;
#pragma unroll
        for (int k = 0; k < 9; k++) {
            int pos = sp[k];
            if (pos >= 0) a += base[(long long)pos * CH + c];
        }
        float v = a * inv;
        __half h = __float2half_rn(v);
        rTh[obase + c] = h;
        rTl[obase + c] = __float2half_rn(v - __half2float(h));
    }
}

// ---------------- host orchestration ----------------
extern "C" void kernel_launch(void* const* d_in, const int* in_sizes, int n_in,
                              void* d_out, int out_size)
{
    (void)in_sizes; (void)n_in; (void)out_size;
    const float* content = (const float*)d_in[0];
    const float* style   = (const float*)d_in[1];
    float* out = (float*)d_out;

    float *Fcent, *means, *Cov, *sigma, *Yf, *Zf, *NSt, *snorm, *rk, *M0, *Tb, *pbs;
    __half *Fch, *Fcl, *FcTh, *FcTl, *Yh, *Yl, *Zh, *Zl, *Th, *Tl, *Wh, *Wl, *Cmh, *Cml;
    __half *NCth, *NCtl, *NSth, *NStl, *rTh, *rTl;
    int *idx, *pbi;
    cudaGetSymbolAddress((void**)&Fcent, g_Fcent);
    cudaGetSymbolAddress((void**)&Fch,   g_Fch);
    cudaGetSymbolAddress((void**)&Fcl,   g_Fcl);
    cudaGetSymbolAddress((void**)&FcTh,  g_FcTh);
    cudaGetSymbolAddress((void**)&FcTl,  g_FcTl);
    cudaGetSymbolAddress((void**)&means, g_means);
    cudaGetSymbolAddress((void**)&Cov,   g_Cov);
    cudaGetSymbolAddress((void**)&sigma, g_sigma);
    cudaGetSymbolAddress((void**)&Yf,    g_Yf);
    cudaGetSymbolAddress((void**)&Zf,    g_Zf);
    cudaGetSymbolAddress((void**)&Yh,    g_Yh);
    cudaGetSymbolAddress((void**)&Yl,    g_Yl);
    cudaGetSymbolAddress((void**)&Zh,    g_Zh);
    cudaGetSymbolAddress((void**)&Zl,    g_Zl);
    cudaGetSymbolAddress((void**)&Th,    g_Th);
    cudaGetSymbolAddress((void**)&Tl,    g_Tl);
    cudaGetSymbolAddress((void**)&Wh,    g_Wh);
    cudaGetSymbolAddress((void**)&Wl,    g_Wl);
    cudaGetSymbolAddress((void**)&Cmh,   g_Cmh);
    cudaGetSymbolAddress((void**)&Cml,   g_Cml);
    cudaGetSymbolAddress((void**)&NSt,   g_NSt);
    cudaGetSymbolAddress((void**)&NCth,  g_NCth);
    cudaGetSymbolAddress((void**)&NCtl,  g_NCtl);
    cudaGetSymbolAddress((void**)&NSth,  g_NSth);
    cudaGetSymbolAddress((void**)&NStl,  g_NStl);
    cudaGetSymbolAddress((void**)&snorm, g_snorm);
    cudaGetSymbolAddress((void**)&rk,    g_rk);
    cudaGetSymbolAddress((void**)&M0,    g_M0);
    cudaGetSymbolAddress((void**)&Tb,    g_Tb);
    cudaGetSymbolAddress((void**)&idx,   g_idx);
    cudaGetSymbolAddress((void**)&pbs,   g_pbs);
    cudaGetSymbolAddress((void**)&pbi,   g_pbi);
    cudaGetSymbolAddress((void**)&rTh,   g_rTh);
    cudaGetSymbolAddress((void**)&rTl,   g_rTl);

    cudaFuncSetAttribute(cov16_kernel,    cudaFuncAttributeMaxDynamicSharedMemorySize, HG_SMEM);
    cudaFuncSetAttribute(nsT16_kernel,    cudaFuncAttributeMaxDynamicSharedMemorySize, HG_SMEM);
    cudaFuncSetAttribute(nsYZ16_kernel,   cudaFuncAttributeMaxDynamicSharedMemorySize, HG_SMEM);
    cudaFuncSetAttribute(whiten16_kernel, cudaFuncAttributeMaxDynamicSharedMemorySize, HG_SMEM);
    cudaFuncSetAttribute(m016_kernel,     cudaFuncAttributeMaxDynamicSharedMemorySize, HG_SMEM);
    cudaFuncSetAttribute(color16_kernel,  cudaFuncAttributeMaxDynamicSharedMemorySize, HG_SMEM);

    // 1) center (+ channel-major fp16 split)
    center_kernel<<<dim3(CH, 4), 256>>>(content, style, Fcent, Fch, Fcl, means);

    // 2) pixel-major transposed fp16 split (for whitening A operand)
    transposeFcT_kernel<<<dim3(128, 16, 4), dim3(32, 32)>>>(Fcent, FcTh, FcTl);

    // 3) covariances on tensor cores
    cov16_kernel<<<dim3(4, 4, 4), 256, HG_SMEM>>>(Fch, Fcl, Cov);

    // 4) lambda_max
    power_kernel<<<4, 512>>>(Cov, sigma);

    // 5) Newton-Schulz (5 iterations, fp16-split mma; all iterates symmetric)
    ns_init_kernel<<<4096, 256>>>(Cov, sigma, Yh, Yl, Zh, Zl);
    int cur = 0;
    for (int it = 0; it < 5; it++) {
        int nxt = cur ^ 1;
        long long hc = (long long)cur * 4 * CC, hn = (long long)nxt * 4 * CC;
        nsT16_kernel<<<dim3(4, 4, 4), 256, HG_SMEM>>>(
            Zh + hc, Zl + hc, Yh + hc, Yl + hc, Th, Tl);
        nsYZ16_kernel<<<dim3(4, 4, 8), 256, HG_SMEM>>>(
            Yh + hc, Yl + hc, Zh + hc, Zl + hc, Th, Tl,
            Yf + hn, Yh + hn, Yl + hn, Zf + hn, Zh + hn, Zl + hn);
        cur = nxt;
    }
    long long hf = (long long)cur * 4 * CC;

    // 6) rescale -> W, Cm splits
    scale16_kernel<<<4096, 256>>>(Yf + hf, Zf + hf, sigma, Wh, Wl, Cmh, Cml);

    // 7) whitening on tensor cores: NCt[p][c] = sum_k FcT[p,k] W[c,k]
    whiten16_kernel<<<dim3(4, 32, 4), 256, HG_SMEM>>>(
        FcTh, FcTl, Wh, Wl, NSt, NCth, NCtl, NSth, NStl);

    // 8) patch norms
    snorm_kernel<<<1024, 256>>>(NSt, snorm);
    rknorm_kernel<<<32, 256>>>(snorm, rk);

    // 9) M0 = ns^T @ nc on tensor cores
    m016_kernel<<<dim3(32, 32, 2), 256, HG_SMEM>>>(NSth, NStl, NCth, NCtl, M0);

    // 10) box filter + argmax
    boxh_kernel<<<dim3(65536, 2), 256>>>(M0, Tb);
    argmax_part_kernel<<<dim3(16, 16, 2), 256>>>(Tb, rk, pbs, pbi);
    argmax_comb_kernel<<<32, 256>>>(pbs, pbi, idx);

    // 11) gather + overlap-add (fp16 split out)
    gather_kernel<<<dim3(4096, 2), 128>>>(NSt, idx, rTh, rTl);

    // 12) color on tensor cores: out[c][p] = sum_k Cm[c,k] reasT[p,k] + mean[c]
    color16_kernel<<<dim3(32, 4, 2), 256, HG_SMEM>>>(Cmh, Cml, rTh, rTl, out, means);
}

// round 13
// speedup vs baseline: 1.9448x; 1.6033x over previous
#include <cuda_runtime.h>
#include <cuda_fp16.h>
#include <math.h>
#include <float.h>
#include <stdint.h>

// ---------------- problem constants ----------------
#define CH   512
#define HW   4096
constexpr long long CHW = (long long)CH * HW;
constexpr long long CC  = (long long)CH * CH;
constexpr long long PQ  = (long long)HW * HW;

// ---------------- device scratch ----------------
__device__ float  g_Fcent[4 * 2097152];
__device__ __half g_Fch[4 * 2097152];
__device__ __half g_Fcl[4 * 2097152];
__device__ __half g_FcTh[4 * 2097152];
__device__ __half g_FcTl[4 * 2097152];
__device__ float  g_means[4 * 512];
__device__ float  g_Cov[4 * 262144];
__device__ float  g_sigma[4];
__device__ float  g_Yf[2 * 4 * 262144];
__device__ float  g_Zf[2 * 4 * 262144];
__device__ __half g_Yh[2 * 4 * 262144];
__device__ __half g_Yl[2 * 4 * 262144];
__device__ __half g_Zh[2 * 4 * 262144];
__device__ __half g_Zl[2 * 4 * 262144];
__device__ __half g_Th[4 * 262144];
__device__ __half g_Tl[4 * 262144];
__device__ __half g_Wh[4 * 262144];
__device__ __half g_Wl[4 * 262144];
__device__ __half g_Cmh[2 * 262144];
__device__ __half g_Cml[2 * 262144];
__device__ float  g_NSt[2 * 2097152];
__device__ __half g_NCth[2 * 2097152];
__device__ __half g_NCtl[2 * 2097152];
__device__ __half g_NSth[2 * 2097152];
__device__ __half g_NStl[2 * 2097152];
__device__ float  g_snorm[2 * 4096];
__device__ float  g_rk[2 * 4096];
__device__ float  g_M0[33554432];
__device__ float  g_Tb[33554432];
__device__ int    g_idx[2 * 4096];
__device__ float  g_pbs[2 * 16 * 4096];
__device__ int    g_pbi[2 * 16 * 4096];
__device__ __half g_rTh[2 * 2097152];
__device__ __half g_rTl[2 * 2097152];

// ---------------- helpers ----------------
__device__ __forceinline__ uint32_t smem_to_u32(const void* p) {
    uint32_t a;
    asm("{ .reg .u64 t; cvta.to.shared.u64 t, %1; cvt.u32.u64 %0, t; }" : "=r"(a) : "l"(p));
    return a;
}
__device__ __forceinline__ void cp_async16(uint32_t saddr, const void* g) {
    asm volatile("cp.async.cg.shared.global [%0], [%1], 16;" :: "r"(saddr), "l"(g));
}
#define CP_COMMIT() asm volatile("cp.async.commit_group;" ::: "memory")
#define CP_WAIT1()  asm volatile("cp.async.wait_group 1;" ::: "memory")
#define CP_WAIT0()  asm volatile("cp.async.wait_group 0;" ::: "memory")

__device__ __forceinline__ void mma_f16(float* c, const uint32_t* a, const uint32_t* b) {
    asm volatile(
        "mma.sync.aligned.m16n8k16.row.col.f32.f16.f16.f32 "
        "{%0,%1,%2,%3}, {%4,%5,%6,%7}, {%8,%9}, {%0,%1,%2,%3};"
        : "+f"(c[0]), "+f"(c[1]), "+f"(c[2]), "+f"(c[3])
        : "r"(a[0]), "r"(a[1]), "r"(a[2]), "r"(a[3]), "r"(b[0]), "r"(b[1]));
}

__device__ __forceinline__ void split_store(__half* Ch, __half* Cl, long long off,
                                            float x, float y) {
    __half hx = __float2half_rn(x), hy = __float2half_rn(y);
    __half lx = __float2half_rn(x - __half2float(hx));
    __half ly = __float2half_rn(y - __half2float(hy));
    *(__half2*)&Ch[off] = __halves2half2(hx, hy);
    *(__half2*)&Cl[off] = __halves2half2(lx, ly);
}

// ---------------- generic fp16-split 3-product MMA GEMM tile ----------------
#define SKPH 40
constexpr int HG_ARRH = 128 * SKPH;
constexpr int HG_BUFH = 4 * HG_ARRH;
constexpr int HG_SMEM = 2 * HG_BUFH * 2;     // 81920 bytes

__device__ __forceinline__ void hgemm_tile(
    const __half* __restrict__ Ah, const __half* __restrict__ Al,
    const __half* __restrict__ Bh, const __half* __restrict__ Bl,
    float* __restrict__ Cf, __half* __restrict__ Ch, __half* __restrict__ Cl,
    int ldC, int K, float alpha, float diagAdd, const float* __restrict__ bias,
    __half* smh)
{
    const uint32_t sbase = smem_to_u32(smh);
    const int tid  = threadIdx.x;
    const int wid  = tid >> 5, lane = tid & 31;
    const int g    = lane >> 2, t = lane & 3;
    const int wm   = wid & 3, wn = wid >> 2;
    const int m0   = blockIdx.y * 128, n0 = blockIdx.x * 128;

    auto stage = [&](int kt, int buf) {
#pragma unroll
        for (int tt = 0; tt < 8; tt++) {
            int idx = tid + tt * 256;
            int a   = idx >> 9;
            int rem = idx & 511;
            int r   = rem >> 2;
            int c8  = (rem & 3) * 8;
            const __half* src = (a == 0) ? Ah : (a == 1) ? Al : (a == 2) ? Bh : Bl;
            int rowbase = (a < 2) ? m0 : n0;
            const __half* gp = src + (long long)(rowbase + r) * K + kt * 32 + c8;
            uint32_t sa = sbase + (uint32_t)(buf * HG_BUFH + a * HG_ARRH + r * SKPH + c8) * 2u;
            cp_async16(sa, gp);
        }
    };

    float acc[2][8][4];
#pragma unroll
    for (int i = 0; i < 2; i++)
#pragma unroll
        for (int j = 0; j < 8; j++)
#pragma unroll
            for (int k = 0; k < 4; k++) acc[i][j][k] = 0.f;

    const int nk = K >> 5;
    stage(0, 0); CP_COMMIT();

    for (int kt = 0; kt < nk; kt++) {
        const int buf = kt & 1;
        if (kt + 1 < nk) { stage(kt + 1, buf ^ 1); CP_COMMIT(); CP_WAIT1(); }
        else             { CP_WAIT0(); }
        __syncthreads();

        const __half* sAh = smh + buf * HG_BUFH;
        const __half* sAl = sAh + HG_ARRH;
        const __half* sBh = sAl + HG_ARRH;
        const __half* sBl = sBh + HG_ARRH;
#pragma unroll
        for (int ks = 0; ks < 32; ks += 16) {
            uint32_t afh[2][4], afl[2][4];
#pragma unroll
            for (int mt = 0; mt < 2; mt++) {
                int r  = wm * 32 + mt * 16;
                int i0 = (r + g) * SKPH + ks + 2 * t;
                int i8 = (r + g + 8) * SKPH + ks + 2 * t;
                afh[mt][0] = *(const uint32_t*)&sAh[i0];
                afh[mt][1] = *(const uint32_t*)&sAh[i8];
                afh[mt][2] = *(const uint32_t*)&sAh[i0 + 8];
                afh[mt][3] = *(const uint32_t*)&sAh[i8 + 8];
                afl[mt][0] = *(const uint32_t*)&sAl[i0];
                afl[mt][1] = *(const uint32_t*)&sAl[i8];
                afl[mt][2] = *(const uint32_t*)&sAl[i0 + 8];
                afl[mt][3] = *(const uint32_t*)&sAl[i8 + 8];
            }
#pragma unroll
            for (int nt = 0; nt < 8; nt++) {
                int bb = (wn * 64 + nt * 8 + g) * SKPH + ks + 2 * t;
                uint32_t bfh[2] = { *(const uint32_t*)&sBh[bb], *(const uint32_t*)&sBh[bb + 8] };
                uint32_t bfl[2] = { *(const uint32_t*)&sBl[bb], *(const uint32_t*)&sBl[bb + 8] };
#pragma unroll
                for (int mt = 0; mt < 2; mt++) {
                    mma_f16(acc[mt][nt], afh[mt], bfh);
                    mma_f16(acc[mt][nt], afh[mt], bfl);
                    mma_f16(acc[mt][nt], afl[mt], bfh);
                }
            }
        }
        __syncthreads();
    }

#pragma unroll
    for (int mt = 0; mt < 2; mt++) {
        int row0 = m0 + wm * 32 + mt * 16 + g;
        int row1 = row0 + 8;
        float bv0 = bias ? bias[row0] : 0.f;
        float bv1 = bias ? bias[row1] : 0.f;
#pragma unroll
        for (int nt = 0; nt < 8; nt++) {
            int col = n0 + wn * 64 + nt * 8 + 2 * t;
            float x0 = alpha * acc[mt][nt][0] + bv0; if (row0 == col)     x0 += diagAdd;
            float y0 = alpha * acc[mt][nt][1] + bv0; if (row0 == col + 1) y0 += diagAdd;
            float x1 = alpha * acc[mt][nt][2] + bv1; if (row1 == col)     x1 += diagAdd;
            float y1 = alpha * acc[mt][nt][3] + bv1; if (row1 == col + 1) y1 += diagAdd;
            long long o0 = (long long)row0 * ldC + col;
            long long o1 = (long long)row1 * ldC + col;
            if (Cf) {
                float2 v0; v0.x = x0; v0.y = y0; *(float2*)&Cf[o0] = v0;
                float2 v1; v1.x = x1; v1.y = y1; *(float2*)&Cf[o1] = v1;
            }
            if (Ch) {
                split_store(Ch, Cl, o0, x0, y0);
                split_store(Ch, Cl, o1, x1, y1);
            }
        }
    }
}

// ---------------- hgemm wrapper kernels ----------------
__global__ void __launch_bounds__(256, 2) cov16_kernel(
    const __half* __restrict__ Fh, const __half* __restrict__ Fl, float* __restrict__ Cov)
{
    extern __shared__ __half smh[];
    long long o = (long long)blockIdx.z * CHW;
    hgemm_tile(Fh + o, Fl + o, Fh + o, Fl + o,
               Cov + (long long)blockIdx.z * CC, nullptr, nullptr,
               512, 4096, 1.f / 4095.f, 0.f, nullptr, smh);
}

__global__ void __launch_bounds__(256, 2) nsT16_kernel(
    const __half* __restrict__ Zh, const __half* __restrict__ Zl,
    const __half* __restrict__ Yh, const __half* __restrict__ Yl,
    __half* __restrict__ Th, __half* __restrict__ Tl)
{
    extern __shared__ __half smh[];
    long long o = (long long)blockIdx.z * CC;
    hgemm_tile(Zh + o, Zl + o, Yh + o, Yl + o,
               nullptr, Th + o, Tl + o, 512, 512, -0.5f, 1.5f, nullptr, smh);
}

__global__ void __launch_bounds__(256, 2) nsYZ16_kernel(
    const __half* __restrict__ Yh, const __half* __restrict__ Yl,
    const __half* __restrict__ Zh, const __half* __restrict__ Zl,
    const __half* __restrict__ Th, const __half* __restrict__ Tl,
    float* __restrict__ Ynf, __half* __restrict__ Ynh, __half* __restrict__ Ynl,
    float* __restrict__ Znf, __half* __restrict__ Znh, __half* __restrict__ Znl)
{
    extern __shared__ __half smh[];
    int z = blockIdx.z;
    if (z < 4) {
        long long o = (long long)z * CC;
        hgemm_tile(Yh + o, Yl + o, Th + o, Tl + o,
                   Ynf + o, Ynh + o, Ynl + o, 512, 512, 1.f, 0.f, nullptr, smh);
    } else {
        long long o = (long long)(z - 4) * CC;
        hgemm_tile(Th + o, Tl + o, Zh + o, Zl + o,
                   Znf + o, Znh + o, Znl + o, 512, 512, 1.f, 0.f, nullptr, smh);
    }
}

__global__ void __launch_bounds__(256, 2) whiten16_kernel(
    const __half* __restrict__ FcTh, const __half* __restrict__ FcTl,
    const __half* __restrict__ Wh, const __half* __restrict__ Wl,
    float* __restrict__ NSt,
    __half* __restrict__ NCth, __half* __restrict__ NCtl,
    __half* __restrict__ NSth, __half* __restrict__ NStl)
{
    extern __shared__ __half smh[];
    int z = blockIdx.z;
    long long oa = (long long)z * CHW;
    long long ow = (long long)z * CC;
    float* cf; __half *ch, *cl;
    if (z < 2) { cf = nullptr; ch = NCth + oa; cl = NCtl + oa; }
    else       { long long os = (long long)(z - 2) * CHW;
                 cf = NSt + os; ch = NSth + os; cl = NStl + os; }
    hgemm_tile(FcTh + oa, FcTl + oa, Wh + ow, Wl + ow,
               cf, ch, cl, 512, 512, 1.f, 0.f, nullptr, smh);
}

__global__ void __launch_bounds__(256, 2) m016_kernel(
    const __half* __restrict__ Ah, const __half* __restrict__ Al,
    const __half* __restrict__ Bh, const __half* __restrict__ Bl,
    float* __restrict__ M0out)
{
    extern __shared__ __half smh[];
    long long o = (long long)blockIdx.z * CHW;
    hgemm_tile(Ah + o, Al + o, Bh + o, Bl + o,
               M0out + (long long)blockIdx.z * PQ, nullptr, nullptr,
               4096, 512, 1.f, 0.f, nullptr, smh);
}

__global__ void __launch_bounds__(256, 2) color16_kernel(
    const __half* __restrict__ Cmh, const __half* __restrict__ Cml,
    const __half* __restrict__ rTh, const __half* __restrict__ rTl,
    float* __restrict__ out, const float* __restrict__ means)
{
    extern __shared__ __half smh[];
    int b = blockIdx.z;
    hgemm_tile(Cmh + (long long)b * CC, Cml + (long long)b * CC,
               rTh + (long long)b * CHW, rTl + (long long)b * CHW,
               out + (long long)b * CHW, nullptr, nullptr,
               4096, 512, 1.f, 0.f, means + (long long)(2 + b) * CH, smh);
}

// ---------------- per-channel mean + center (+ fp16 split, channel-major) ----------------
__global__ void center_kernel(const float* __restrict__ content, const float* __restrict__ style,
                              float* __restrict__ Fcent, __half* __restrict__ Fch,
                              __half* __restrict__ Fcl, float* __restrict__ means)
{
    int c = blockIdx.x, g = blockIdx.y;
    const float* src = (g < 2 ? content + (long long)g * CHW : style + (long long)(g - 2) * CHW)
                       + (long long)c * HW;
    __shared__ float red[256];
    float s = 0.f;
    for (int i = threadIdx.x; i < HW; i += 256) s += src[i];
    red[threadIdx.x] = s; __syncthreads();
    for (int st = 128; st > 0; st >>= 1) {
        if (threadIdx.x < st) red[threadIdx.x] += red[threadIdx.x + st];
        __syncthreads();
    }
    float mean = red[0] * (1.f / HW);
    if (threadIdx.x == 0) means[g * CH + c] = mean;
    long long base = (long long)g * CHW + (long long)c * HW;
    for (int i = threadIdx.x; i < HW; i += 256) {
        float v = src[i] - mean;
        Fcent[base + i] = v;
        __half h = __float2half_rn(v);
        Fch[base + i] = h;
        Fcl[base + i] = __float2half_rn(v - __half2float(h));
    }
}

// ---------------- transpose + fp16 split of Fcent (pixel-major) ----------------
__global__ void transposeFcT_kernel(const float* __restrict__ Fcent,
                                    __half* __restrict__ FcTh, __half* __restrict__ FcTl)
{
    __shared__ float tile[32][33];
    int g = blockIdx.z;
    int p0 = blockIdx.x * 32, c0 = blockIdx.y * 32;
    tile[threadIdx.y][threadIdx.x] =
        Fcent[(long long)g * CHW + (long long)(c0 + threadIdx.y) * HW + p0 + threadIdx.x];
    __syncthreads();
    float x = tile[threadIdx.x][threadIdx.y];
    long long o = (long long)g * CHW + (long long)(p0 + threadIdx.y) * CH + c0 + threadIdx.x;
    __half h = __float2half_rn(x);
    FcTh[o] = h;
    FcTl[o] = __float2half_rn(x - __half2float(h));
}

// ---------------- power iteration (6 iters; NS tolerates sigma in [lam/3, lam]) ----------------
__global__ void power_kernel(const float* __restrict__ Cov, float* __restrict__ sigma)
{
    int g = blockIdx.x;
    const float* A = Cov + (long long)g * CC;
    __shared__ float v[CH];
    __shared__ float red[CH];
    int t = threadIdx.x;
    v[t] = 1.f + 1e-4f * t;
    __syncthreads();
    float lam = 0.f;
    for (int it = 0; it < 6; it++) {
        float a0 = 0.f, a1 = 0.f, a2 = 0.f, a3 = 0.f;
#pragma unroll 4
        for (int k = 0; k < CH; k += 4) {
            a0 = fmaf(A[(long long)(k + 0) * CH + t], v[k + 0], a0);
            a1 = fmaf(A[(long long)(k + 1) * CH + t], v[k + 1], a1);
            a2 = fmaf(A[(long long)(k + 2) * CH + t], v[k + 2], a2);
            a3 = fmaf(A[(long long)(k + 3) * CH + t], v[k + 3], a3);
        }
        float acc = (a0 + a1) + (a2 + a3);
        __syncthreads();
        red[t] = acc * acc; __syncthreads();
        for (int st = 256; st > 0; st >>= 1) {
            if (t < st) red[t] += red[t + st];
            __syncthreads();
        }
        float n2 = red[0];
        lam = sqrtf(n2);
        float inv = (n2 > 0.f) ? rsqrtf(n2) : 0.f;
        __syncthreads();
        v[t] = acc * inv;
        __syncthreads();
    }
    if (t == 0) sigma[g] = lam * 1.02f + 1e-20f;
}

// ---------------- Newton-Schulz init (fp16 split) ----------------
__global__ void ns_init_kernel(const float* __restrict__ Cov, const float* __restrict__ sigma,
                               __half* __restrict__ Yh, __half* __restrict__ Yl,
                               __half* __restrict__ Zh, __half* __restrict__ Zl)
{
    long long i = (long long)blockIdx.x * blockDim.x + threadIdx.x;
    if (i >= 4 * CC) return;
    int g = (int)(i / CC);
    long long r = i % CC;
    int row = (int)(r / CH), col = (int)(r % CH);
    float y = Cov[i] / sigma[g];
    __half h = __float2half_rn(y);
    Yh[i] = h;
    Yl[i] = __float2half_rn(y - __half2float(h));
    Zh[i] = __float2half_rn((row == col) ? 1.f : 0.f);
    Zl[i] = __float2half_rn(0.f);
}

// ---------------- rescale -> W, Cm fp16 splits ----------------
__global__ void scale16_kernel(const float* __restrict__ Yf, const float* __restrict__ Zf,
                               const float* __restrict__ sigma,
                               __half* __restrict__ Wh, __half* __restrict__ Wl,
                               __half* __restrict__ Cmh, __half* __restrict__ Cml)
{
    long long i = (long long)blockIdx.x * blockDim.x + threadIdx.x;
    if (i >= 4 * CC) return;
    int g = (int)(i / CC);
    float sq = sqrtf(sigma[g]);
    float w = Zf[i] / sq;
    __half h = __float2half_rn(w);
    Wh[i] = h;
    Wl[i] = __float2half_rn(w - __half2float(h));
    if (g >= 2) {
        float cm = Yf[i] * sq;
        __half hc = __float2half_rn(cm);
        Cmh[i - 2 * CC] = hc;
        Cml[i - 2 * CC] = __float2half_rn(cm - __half2float(hc));
    }
}

// ---------------- per-pixel squared norms ----------------
__global__ void snorm_kernel(const float* __restrict__ NSt, float* __restrict__ snorm)
{
    int gw = (blockIdx.x * blockDim.x + threadIdx.x) >> 5;
    int lane = threadIdx.x & 31;
    if (gw >= 2 * HW) return;
    int b = gw / HW, p = gw % HW;
    const float* row = NSt + (long long)b * CHW + (long long)p * CH;
    float s = 0.f;
    for (int c = lane; c < CH; c += 32) { float v = row[c]; s = fmaf(v, v, s); }
    for (int o = 16; o > 0; o >>= 1) s += __shfl_down_sync(0xffffffff, s, o);
    if (lane == 0) snorm[b * HW + p] = s;
}

__global__ void rknorm_kernel(const float* __restrict__ snorm, float* __restrict__ rk)
{
    int i = blockIdx.x * blockDim.x + threadIdx.x;
    if (i >= 2 * HW) return;
    int b = i / HW, p = i % HW;
    int py = p >> 6, px = p & 63;
    float sum = 0.f;
    for (int u = -1; u <= 1; u++)
        for (int v = -1; v <= 1; v++) {
            int yy = py + u, xx = px + v;
            if ((unsigned)yy < 64u && (unsigned)xx < 64u) sum += snorm[b * HW + yy * 64 + xx];
        }
    rk[i] = 1.f / (sqrtf(sum) + 1e-5f);
}

// ---------------- horizontal diagonal 3-box ----------------
__global__ void boxh_kernel(const float* __restrict__ M0, float* __restrict__ Tb)
{
    long long i = (long long)blockIdx.x * 256 + threadIdx.x;
    int b = blockIdx.y;
    const float* M = M0 + (long long)b * PQ;
    int p = (int)(i >> 12);
    int q = (int)(i & 4095);
    int px = p & 63, qx = q & 63;
    float s = 0.f;
#pragma unroll
    for (int v = -1; v <= 1; v++) {
        if ((unsigned)(px + v) < 64u && (unsigned)(qx + v) < 64u) s += M[i + (long long)v * 4097];
    }
    Tb[(long long)b * PQ + i] = s;
}

// ---------------- vertical diagonal 3-box + partial argmax ----------------
__global__ void argmax_part_kernel(const float* __restrict__ Tb, const float* __restrict__ rk,
                                   float* __restrict__ pbs, int* __restrict__ pbi)
{
    int b = blockIdx.z;
    int q = blockIdx.x * 256 + threadIdx.x;
    int pc = blockIdx.y;
    __shared__ float srk[256];
    srk[threadIdx.x] = rk[b * HW + pc * 256 + threadIdx.x];
    __syncthreads();
    const float* T = Tb + (long long)b * PQ;
    float best = -FLT_MAX; int bi = 0;
    for (int pp = 0; pp < 256; pp++) {
        int p = pc * 256 + pp;
        float s = 0.f;
#pragma unroll
        for (int u = -1; u <= 1; u++) {
            int row = p + 64 * u, col = q + 64 * u;
            if ((unsigned)row < (unsigned)HW && (unsigned)col < (unsigned)HW)
                s += T[(long long)row * HW + col];
        }
        float sc = s * srk[pp];
        if (sc > best) { best = sc; bi = p; }
    }
    pbs[(b * 16 + pc) * HW + q] = best;
    pbi[(b * 16 + pc) * HW + q] = bi;
}

__global__ void argmax_comb_kernel(const float* __restrict__ pbs, const int* __restrict__ pbi,
                                   int* __restrict__ idx)
{
    int i = blockIdx.x * 256 + threadIdx.x;
    if (i >= 2 * HW) return;
    int b = i / HW, q = i % HW;
    float best = -FLT_MAX; int bi = 0;
    for (int k = 0; k < 16; k++) {
        float s = pbs[(b * 16 + k) * HW + q];
        int p = pbi[(b * 16 + k) * HW + q];
        if (s > best || (s == best && p < bi)) { best = s; bi = p; }
    }
    idx[b * HW + q] = bi;
}

// ---------------- gather + overlap-add (emit fp16 split) ----------------
__global__ void gather_kernel(const float* __restrict__ NSt, const int* __restrict__ idx,
                              __half* __restrict__ rTh, __half* __restrict__ rTl)
{
    int b = blockIdx.y, pix = blockIdx.x;
    int Y = pix >> 6, X = pix & 63;
    __shared__ int sp[9];
    if (threadIdx.x < 9) {
        int dx = threadIdx.x / 3, dy = threadIdx.x % 3;
        int y = Y + 1 - dx, x = X + 1 - dy;
        int pos = -1;
        if ((unsigned)y < 64u && (unsigned)x < 64u) {
            int p = idx[b * HW + y * 64 + x];
            int sy = (p >> 6) + dx - 1, sx = (p & 63) + dy - 1;
            if ((unsigned)sy < 64u && (unsigned)sx < 64u) pos = sy * 64 + sx;
        }
        sp[threadIdx.x] = pos;
    }
    __syncthreads();
    int cy = (Y == 0 || Y == 63) ? 2 : 3;
    int cx = (X == 0 || X == 63) ? 2 : 3;
    float inv = 1.f / (float)(cy * cx);
    const float* base = NSt + (long long)b * CHW;
    long long obase = (long long)b * CHW + (long long)pix * CH;
    for (int c = threadIdx.x; c < CH; c += 128) {
        float a = 0.f;
#pragma unroll
        for (int k = 0; k < 9; k++) {
            int pos = sp[k];
            if (pos >= 0) a += base[(long long)pos * CH + c];
        }
        float v = a * inv;
        __half h = __float2half_rn(v);
        rTh[obase + c] = h;
        rTl[obase + c] = __float2half_rn(v - __half2float(h));
    }
}

// ---------------- host orchestration ----------------
extern "C" void kernel_launch(void* const* d_in, const int* in_sizes, int n_in,
                              void* d_out, int out_size)
{
    (void)in_sizes; (void)n_in; (void)out_size;
    const float* content = (const float*)d_in[0];
    const float* style   = (const float*)d_in[1];
    float* out = (float*)d_out;

    float *Fcent, *means, *Cov, *sigma, *Yf, *Zf, *NSt, *snorm, *rk, *M0, *Tb, *pbs;
    __half *Fch, *Fcl, *FcTh, *FcTl, *Yh, *Yl, *Zh, *Zl, *Th, *Tl, *Wh, *Wl, *Cmh, *Cml;
    __half *NCth, *NCtl, *NSth, *NStl, *rTh, *rTl;
    int *idx, *pbi;
    cudaGetSymbolAddress((void**)&Fcent, g_Fcent);
    cudaGetSymbolAddress((void**)&Fch,   g_Fch);
    cudaGetSymbolAddress((void**)&Fcl,   g_Fcl);
    cudaGetSymbolAddress((void**)&FcTh,  g_FcTh);
    cudaGetSymbolAddress((void**)&FcTl,  g_FcTl);
    cudaGetSymbolAddress((void**)&means, g_means);
    cudaGetSymbolAddress((void**)&Cov,   g_Cov);
    cudaGetSymbolAddress((void**)&sigma, g_sigma);
    cudaGetSymbolAddress((void**)&Yf,    g_Yf);
    cudaGetSymbolAddress((void**)&Zf,    g_Zf);
    cudaGetSymbolAddress((void**)&Yh,    g_Yh);
    cudaGetSymbolAddress((void**)&Yl,    g_Yl);
    cudaGetSymbolAddress((void**)&Zh,    g_Zh);
    cudaGetSymbolAddress((void**)&Zl,    g_Zl);
    cudaGetSymbolAddress((void**)&Th,    g_Th);
    cudaGetSymbolAddress((void**)&Tl,    g_Tl);
    cudaGetSymbolAddress((void**)&Wh,    g_Wh);
    cudaGetSymbolAddress((void**)&Wl,    g_Wl);
    cudaGetSymbolAddress((void**)&Cmh,   g_Cmh);
    cudaGetSymbolAddress((void**)&Cml,   g_Cml);
    cudaGetSymbolAddress((void**)&NSt,   g_NSt);
    cudaGetSymbolAddress((void**)&NCth,  g_NCth);
    cudaGetSymbolAddress((void**)&NCtl,  g_NCtl);
    cudaGetSymbolAddress((void**)&NSth,  g_NSth);
    cudaGetSymbolAddress((void**)&NStl,  g_NStl);
    cudaGetSymbolAddress((void**)&snorm, g_snorm);
    cudaGetSymbolAddress((void**)&rk,    g_rk);
    cudaGetSymbolAddress((void**)&M0,    g_M0);
    cudaGetSymbolAddress((void**)&Tb,    g_Tb);
    cudaGetSymbolAddress((void**)&idx,   g_idx);
    cudaGetSymbolAddress((void**)&pbs,   g_pbs);
    cudaGetSymbolAddress((void**)&pbi,   g_pbi);
    cudaGetSymbolAddress((void**)&rTh,   g_rTh);
    cudaGetSymbolAddress((void**)&rTl,   g_rTl);

    cudaFuncSetAttribute(cov16_kernel,    cudaFuncAttributeMaxDynamicSharedMemorySize, HG_SMEM);
    cudaFuncSetAttribute(nsT16_kernel,    cudaFuncAttributeMaxDynamicSharedMemorySize, HG_SMEM);
    cudaFuncSetAttribute(nsYZ16_kernel,   cudaFuncAttributeMaxDynamicSharedMemorySize, HG_SMEM);
    cudaFuncSetAttribute(whiten16_kernel, cudaFuncAttributeMaxDynamicSharedMemorySize, HG_SMEM);
    cudaFuncSetAttribute(m016_kernel,     cudaFuncAttributeMaxDynamicSharedMemorySize, HG_SMEM);
    cudaFuncSetAttribute(color16_kernel,  cudaFuncAttributeMaxDynamicSharedMemorySize, HG_SMEM);

    // 1) center (+ channel-major fp16 split)
    center_kernel<<<dim3(CH, 4), 256>>>(content, style, Fcent, Fch, Fcl, means);

    // 2) pixel-major transposed fp16 split
    transposeFcT_kernel<<<dim3(128, 16, 4), dim3(32, 32)>>>(Fcent, FcTh, FcTl);

    // 3) covariances on tensor cores
    cov16_kernel<<<dim3(4, 4, 4), 256, HG_SMEM>>>(Fch, Fcl, Cov);

    // 4) lambda_max (6 iterations; Rayleigh lower bound is fine for NS)
    power_kernel<<<4, 512>>>(Cov, sigma);

    // 5) Newton-Schulz (5 iterations)
    ns_init_kernel<<<4096, 256>>>(Cov, sigma, Yh, Yl, Zh, Zl);
    int cur = 0;
    for (int it = 0; it < 5; it++) {
        int nxt = cur ^ 1;
        long long hc = (long long)cur * 4 * CC, hn = (long long)nxt * 4 * CC;
        nsT16_kernel<<<dim3(4, 4, 4), 256, HG_SMEM>>>(
            Zh + hc, Zl + hc, Yh + hc, Yl + hc, Th, Tl);
        nsYZ16_kernel<<<dim3(4, 4, 8), 256, HG_SMEM>>>(
            Yh + hc, Yl + hc, Zh + hc, Zl + hc, Th, Tl,
            Yf + hn, Yh + hn, Yl + hn, Zf + hn, Zh + hn, Zl + hn);
        cur = nxt;
    }
    long long hf = (long long)cur * 4 * CC;

    // 6) rescale -> W, Cm splits
    scale16_kernel<<<4096, 256>>>(Yf + hf, Zf + hf, sigma, Wh, Wl, Cmh, Cml);

    // 7) whitening on tensor cores
    whiten16_kernel<<<dim3(4, 32, 4), 256, HG_SMEM>>>(
        FcTh, FcTl, Wh, Wl, NSt, NCth, NCtl, NSth, NStl);

    // 8) patch norms
    snorm_kernel<<<1024, 256>>>(NSt, snorm);
    rknorm_kernel<<<32, 256>>>(snorm, rk);

    // 9) M0 on tensor cores
    m016_kernel<<<dim3(32, 32, 2), 256, HG_SMEM>>>(NSth, NStl, NCth, NCtl, M0);

    // 10) box filter + argmax
    boxh_kernel<<<dim3(65536, 2), 256>>>(M0, Tb);
    argmax_part_kernel<<<dim3(16, 16, 2), 256>>>(Tb, rk, pbs, pbi);
    argmax_comb_kernel<<<32, 256>>>(pbs, pbi, idx);

    // 11) gather + overlap-add
    gather_kernel<<<dim3(4096, 2), 128>>>(NSt, idx, rTh, rTl);

    // 12) color on tensor cores
    color16_kernel<<<dim3(32, 4, 2), 256, HG_SMEM>>>(Cmh, Cml, rTh, rTl, out, means);
}

// round 15
// speedup vs baseline: 2.0408x; 1.0494x over previous
#include <cuda_runtime.h>
#include <cuda_fp16.h>
#include <math.h>
#include <float.h>
#include <stdint.h>

// ---------------- problem constants ----------------
#define CH   512
#define HW   4096
constexpr long long CHW = (long long)CH * HW;
constexpr long long CC  = (long long)CH * CH;
constexpr long long PQ  = (long long)HW * HW;

// ---------------- device scratch ----------------
__device__ float  g_Fcent[4 * 2097152];
__device__ __half g_Fch[4 * 2097152];
__device__ __half g_Fcl[4 * 2097152];
__device__ __half g_FcTh[4 * 2097152];
__device__ __half g_FcTl[4 * 2097152];
__device__ float  g_means[4 * 512];
__device__ float  g_Cov[4 * 262144];
__device__ float  g_sigma[4];
__device__ float  g_pv[2 * 4 * 512];
__device__ float  g_Yf[2 * 4 * 262144];
__device__ float  g_Zf[2 * 4 * 262144];
__device__ __half g_Yh[2 * 4 * 262144];
__device__ __half g_Yl[2 * 4 * 262144];
__device__ __half g_Zh[2 * 4 * 262144];
__device__ __half g_Zl[2 * 4 * 262144];
__device__ __half g_Th[4 * 262144];
__device__ __half g_Tl[4 * 262144];
__device__ __half g_Wh[4 * 262144];
__device__ __half g_Wl[4 * 262144];
__device__ __half g_Cmh[2 * 262144];
__device__ __half g_Cml[2 * 262144];
__device__ float  g_NSt[2 * 2097152];
__device__ __half g_NCth[2 * 2097152];
__device__ __half g_NCtl[2 * 2097152];
__device__ __half g_NSth[2 * 2097152];
__device__ __half g_NStl[2 * 2097152];
__device__ float  g_snorm[2 * 4096];
__device__ float  g_rk[2 * 4096];
__device__ float  g_M0[33554432];
__device__ float  g_Tb[33554432];
__device__ int    g_idx[2 * 4096];
__device__ float  g_pbs[2 * 16 * 4096];
__device__ int    g_pbi[2 * 16 * 4096];
__device__ __half g_rTh[2 * 2097152];
__device__ __half g_rTl[2 * 2097152];

// ---------------- helpers ----------------
__device__ __forceinline__ uint32_t smem_to_u32(const void* p) {
    uint32_t a;
    asm("{ .reg .u64 t; cvta.to.shared.u64 t, %1; cvt.u32.u64 %0, t; }" : "=r"(a) : "l"(p));
    return a;
}
__device__ __forceinline__ void cp_async16(uint32_t saddr, const void* g) {
    asm volatile("cp.async.cg.shared.global [%0], [%1], 16;" :: "r"(saddr), "l"(g));
}
#define CP_COMMIT() asm volatile("cp.async.commit_group;" ::: "memory")
#define CP_WAIT1()  asm volatile("cp.async.wait_group 1;" ::: "memory")
#define CP_WAIT0()  asm volatile("cp.async.wait_group 0;" ::: "memory")

__device__ __forceinline__ void mma_f16(float* c, const uint32_t* a, const uint32_t* b) {
    asm volatile(
        "mma.sync.aligned.m16n8k16.row.col.f32.f16.f16.f32 "
        "{%0,%1,%2,%3}, {%4,%5,%6,%7}, {%8,%9}, {%0,%1,%2,%3};"
        : "+f"(c[0]), "+f"(c[1]), "+f"(c[2]), "+f"(c[3])
        : "r"(a[0]), "r"(a[1]), "r"(a[2]), "r"(a[3]), "r"(b[0]), "r"(b[1]));
}

__device__ __forceinline__ void split_store(__half* Ch, __half* Cl, long long off,
                                            float x, float y) {
    __half hx = __float2half_rn(x), hy = __float2half_rn(y);
    __half lx = __float2half_rn(x - __half2float(hx));
    __half ly = __float2half_rn(y - __half2float(hy));
    *(__half2*)&Ch[off] = __halves2half2(hx, hy);
    *(__half2*)&Cl[off] = __halves2half2(lx, ly);
}

// ---------------- generic fp16-split 3-product MMA GEMM tile ----------------
#define SKPH 40
constexpr int HG_ARRH = 128 * SKPH;
constexpr int HG_BUFH = 4 * HG_ARRH;
constexpr int HG_SMEM = 2 * HG_BUFH * 2;     // 81920 bytes

__device__ __forceinline__ void hgemm_tile(
    const __half* __restrict__ Ah, const __half* __restrict__ Al,
    const __half* __restrict__ Bh, const __half* __restrict__ Bl,
    float* __restrict__ Cf, __half* __restrict__ Ch, __half* __restrict__ Cl,
    int ldC, int K, float alpha, float diagAdd, const float* __restrict__ bias,
    __half* smh)
{
    const uint32_t sbase = smem_to_u32(smh);
    const int tid  = threadIdx.x;
    const int wid  = tid >> 5, lane = tid & 31;
    const int g    = lane >> 2, t = lane & 3;
    const int wm   = wid & 3, wn = wid >> 2;
    const int m0   = blockIdx.y * 128, n0 = blockIdx.x * 128;

    auto stage = [&](int kt, int buf) {
#pragma unroll
        for (int tt = 0; tt < 8; tt++) {
            int idx = tid + tt * 256;
            int a   = idx >> 9;
            int rem = idx & 511;
            int r   = rem >> 2;
            int c8  = (rem & 3) * 8;
            const __half* src = (a == 0) ? Ah : (a == 1) ? Al : (a == 2) ? Bh : Bl;
            int rowbase = (a < 2) ? m0 : n0;
            const __half* gp = src + (long long)(rowbase + r) * K + kt * 32 + c8;
            uint32_t sa = sbase + (uint32_t)(buf * HG_BUFH + a * HG_ARRH + r * SKPH + c8) * 2u;
            cp_async16(sa, gp);
        }
    };

    float acc[2][8][4];
#pragma unroll
    for (int i = 0; i < 2; i++)
#pragma unroll
        for (int j = 0; j < 8; j++)
#pragma unroll
            for (int k = 0; k < 4; k++) acc[i][j][k] = 0.f;

    const int nk = K >> 5;
    stage(0, 0); CP_COMMIT();

    for (int kt = 0; kt < nk; kt++) {
        const int buf = kt & 1;
        if (kt + 1 < nk) { stage(kt + 1, buf ^ 1); CP_COMMIT(); CP_WAIT1(); }
        else             { CP_WAIT0(); }
        __syncthreads();

        const __half* sAh = smh + buf * HG_BUFH;
        const __half* sAl = sAh + HG_ARRH;
        const __half* sBh = sAl + HG_ARRH;
        const __half* sBl = sBh + HG_ARRH;
#pragma unroll
        for (int ks = 0; ks < 32; ks += 16) {
            uint32_t afh[2][4], afl[2][4];
#pragma unroll
            for (int mt = 0; mt < 2; mt++) {
                int r  = wm * 32 + mt * 16;
                int i0 = (r + g) * SKPH + ks + 2 * t;
                int i8 = (r + g + 8) * SKPH + ks + 2 * t;
                afh[mt][0] = *(const uint32_t*)&sAh[i0];
                afh[mt][1] = *(const uint32_t*)&sAh[i8];
                afh[mt][2] = *(const uint32_t*)&sAh[i0 + 8];
                afh[mt][3] = *(const uint32_t*)&sAh[i8 + 8];
                afl[mt][0] = *(const uint32_t*)&sAl[i0];
                afl[mt][1] = *(const uint32_t*)&sAl[i8];
                afl[mt][2] = *(const uint32_t*)&sAl[i0 + 8];
                afl[mt][3] = *(const uint32_t*)&sAl[i8 + 8];
            }
#pragma unroll
            for (int nt = 0; nt < 8; nt++) {
                int bb = (wn * 64 + nt * 8 + g) * SKPH + ks + 2 * t;
                uint32_t bfh[2] = { *(const uint32_t*)&sBh[bb], *(const uint32_t*)&sBh[bb + 8] };
                uint32_t bfl[2] = { *(const uint32_t*)&sBl[bb], *(const uint32_t*)&sBl[bb + 8] };
#pragma unroll
                for (int mt = 0; mt < 2; mt++) {
                    mma_f16(acc[mt][nt], afh[mt], bfh);
                    mma_f16(acc[mt][nt], afh[mt], bfl);
                    mma_f16(acc[mt][nt], afl[mt], bfh);
                }
            }
        }
        __syncthreads();
    }

#pragma unroll
    for (int mt = 0; mt < 2; mt++) {
        int row0 = m0 + wm * 32 + mt * 16 + g;
        int row1 = row0 + 8;
        float bv0 = bias ? bias[row0] : 0.f;
        float bv1 = bias ? bias[row1] : 0.f;
#pragma unroll
        for (int nt = 0; nt < 8; nt++) {
            int col = n0 + wn * 64 + nt * 8 + 2 * t;
            float x0 = alpha * acc[mt][nt][0] + bv0; if (row0 == col)     x0 += diagAdd;
            float y0 = alpha * acc[mt][nt][1] + bv0; if (row0 == col + 1) y0 += diagAdd;
            float x1 = alpha * acc[mt][nt][2] + bv1; if (row1 == col)     x1 += diagAdd;
            float y1 = alpha * acc[mt][nt][3] + bv1; if (row1 == col + 1) y1 += diagAdd;
            long long o0 = (long long)row0 * ldC + col;
            long long o1 = (long long)row1 * ldC + col;
            if (Cf) {
                float2 v0; v0.x = x0; v0.y = y0; *(float2*)&Cf[o0] = v0;
                float2 v1; v1.x = x1; v1.y = y1; *(float2*)&Cf[o1] = v1;
            }
            if (Ch) {
                split_store(Ch, Cl, o0, x0, y0);
                split_store(Ch, Cl, o1, x1, y1);
            }
        }
    }
}

// ---------------- hgemm wrapper kernels ----------------
__global__ void __launch_bounds__(256, 2) cov16_kernel(
    const __half* __restrict__ Fh, const __half* __restrict__ Fl, float* __restrict__ Cov)
{
    extern __shared__ __half smh[];
    long long o = (long long)blockIdx.z * CHW;
    hgemm_tile(Fh + o, Fl + o, Fh + o, Fl + o,
               Cov + (long long)blockIdx.z * CC, nullptr, nullptr,
               512, 4096, 1.f / 4095.f, 0.f, nullptr, smh);
}

__global__ void __launch_bounds__(256, 2) nsT16_kernel(
    const __half* __restrict__ Zh, const __half* __restrict__ Zl,
    const __half* __restrict__ Yh, const __half* __restrict__ Yl,
    __half* __restrict__ Th, __half* __restrict__ Tl)
{
    extern __shared__ __half smh[];
    long long o = (long long)blockIdx.z * CC;
    hgemm_tile(Zh + o, Zl + o, Yh + o, Yl + o,
               nullptr, Th + o, Tl + o, 512, 512, -0.5f, 1.5f, nullptr, smh);
}

__global__ void __launch_bounds__(256, 2) nsYZ16_kernel(
    const __half* __restrict__ Yh, const __half* __restrict__ Yl,
    const __half* __restrict__ Zh, const __half* __restrict__ Zl,
    const __half* __restrict__ Th, const __half* __restrict__ Tl,
    float* __restrict__ Ynf, __half* __restrict__ Ynh, __half* __restrict__ Ynl,
    float* __restrict__ Znf, __half* __restrict__ Znh, __half* __restrict__ Znl)
{
    extern __shared__ __half smh[];
    int z = blockIdx.z;
    if (z < 4) {
        long long o = (long long)z * CC;
        hgemm_tile(Yh + o, Yl + o, Th + o, Tl + o,
                   Ynf + o, Ynh + o, Ynl + o, 512, 512, 1.f, 0.f, nullptr, smh);
    } else {
        long long o = (long long)(z - 4) * CC;
        hgemm_tile(Th + o, Tl + o, Zh + o, Zl + o,
                   Znf + o, Znh + o, Znl + o, 512, 512, 1.f, 0.f, nullptr, smh);
    }
}

__global__ void __launch_bounds__(256, 2) whiten16_kernel(
    const __half* __restrict__ FcTh, const __half* __restrict__ FcTl,
    const __half* __restrict__ Wh, const __half* __restrict__ Wl,
    float* __restrict__ NSt,
    __half* __restrict__ NCth, __half* __restrict__ NCtl,
    __half* __restrict__ NSth, __half* __restrict__ NStl)
{
    extern __shared__ __half smh[];
    int z = blockIdx.z;
    long long oa = (long long)z * CHW;
    long long ow = (long long)z * CC;
    float* cf; __half *ch, *cl;
    if (z < 2) { cf = nullptr; ch = NCth + oa; cl = NCtl + oa; }
    else       { long long os = (long long)(z - 2) * CHW;
                 cf = NSt + os; ch = NSth + os; cl = NStl + os; }
    hgemm_tile(FcTh + oa, FcTl + oa, Wh + ow, Wl + ow,
               cf, ch, cl, 512, 512, 1.f, 0.f, nullptr, smh);
}

__global__ void __launch_bounds__(256, 2) m016_kernel(
    const __half* __restrict__ Ah, const __half* __restrict__ Al,
    const __half* __restrict__ Bh, const __half* __restrict__ Bl,
    float* __restrict__ M0out)
{
    extern __shared__ __half smh[];
    long long o = (long long)blockIdx.z * CHW;
    hgemm_tile(Ah + o, Al + o, Bh + o, Bl + o,
               M0out + (long long)blockIdx.z * PQ, nullptr, nullptr,
               4096, 512, 1.f, 0.f, nullptr, smh);
}

__global__ void __launch_bounds__(256, 2) color16_kernel(
    const __half* __restrict__ Cmh, const __half* __restrict__ Cml,
    const __half* __restrict__ rTh, const __half* __restrict__ rTl,
    float* __restrict__ out, const float* __restrict__ means)
{
    extern __shared__ __half smh[];
    int b = blockIdx.z;
    hgemm_tile(Cmh + (long long)b * CC, Cml + (long long)b * CC,
               rTh + (long long)b * CHW, rTl + (long long)b * CHW,
               out + (long long)b * CHW, nullptr, nullptr,
               4096, 512, 1.f, 0.f, means + (long long)(2 + b) * CH, smh);
}

// ---------------- per-channel mean + center (+ fp16 split, channel-major) ----------------
__global__ void center_kernel(const float* __restrict__ content, const float* __restrict__ style,
                              float* __restrict__ Fcent, __half* __restrict__ Fch,
                              __half* __restrict__ Fcl, float* __restrict__ means)
{
    int c = blockIdx.x, g = blockIdx.y;
    const float* src = (g < 2 ? content + (long long)g * CHW : style + (long long)(g - 2) * CHW)
                       + (long long)c * HW;
    __shared__ float red[256];
    float s = 0.f;
    for (int i = threadIdx.x; i < HW; i += 256) s += src[i];
    red[threadIdx.x] = s; __syncthreads();
    for (int st = 128; st > 0; st >>= 1) {
        if (threadIdx.x < st) red[threadIdx.x] += red[threadIdx.x + st];
        __syncthreads();
    }
    float mean = red[0] * (1.f / HW);
    if (threadIdx.x == 0) means[g * CH + c] = mean;
    long long base = (long long)g * CHW + (long long)c * HW;
    for (int i = threadIdx.x; i < HW; i += 256) {
        float v = src[i] - mean;
        Fcent[base + i] = v;
        __half h = __float2half_rn(v);
        Fch[base + i] = h;
        Fcl[base + i] = __float2half_rn(v - __half2float(h));
    }
}

// ---------------- transpose + fp16 split of Fcent (pixel-major) ----------------
__global__ void transposeFcT_kernel(const float* __restrict__ Fcent,
                                    __half* __restrict__ FcTh, __half* __restrict__ FcTl)
{
    __shared__ float tile[32][33];
    int g = blockIdx.z;
    int p0 = blockIdx.x * 32, c0 = blockIdx.y * 32;
    tile[threadIdx.y][threadIdx.x] =
        Fcent[(long long)g * CHW + (long long)(c0 + threadIdx.y) * HW + p0 + threadIdx.x];
    __syncthreads();
    float x = tile[threadIdx.x][threadIdx.y];
    long long o = (long long)g * CHW + (long long)(p0 + threadIdx.y) * CH + c0 + threadIdx.x;
    __half h = __float2half_rn(x);
    FcTh[o] = h;
    FcTl[o] = __float2half_rn(x - __half2float(h));
}

// ---------------- power iteration as unnormalized matvec chain ----------------
__global__ void pinit_kernel(float* __restrict__ v)
{
    int i = blockIdx.x * 256 + threadIdx.x;
    if (i < 4 * CH) v[i] = 1.f + 1e-4f * (i & (CH - 1));
}

__global__ void matvec_kernel(const float* __restrict__ Cov,
                              const float* __restrict__ vin, float* __restrict__ vout)
{
    int gmat = blockIdx.y;
    const float* A = Cov + (long long)gmat * CC;
    const float* v = vin + gmat * CH;
    int col = blockIdx.x * 64 + (threadIdx.x & 63);
    int kc  = threadIdx.x >> 6;
    __shared__ float part[4][64];
    float a0 = 0.f, a1 = 0.f, a2 = 0.f, a3 = 0.f;
    int k0 = kc * 128;
#pragma unroll 8
    for (int k = 0; k < 128; k += 4) {
        a0 = fmaf(A[(long long)(k0 + k + 0) * CH + col], v[k0 + k + 0], a0);
        a1 = fmaf(A[(long long)(k0 + k + 1) * CH + col], v[k0 + k + 1], a1);
        a2 = fmaf(A[(long long)(k0 + k + 2) * CH + col], v[k0 + k + 2], a2);
        a3 = fmaf(A[(long long)(k0 + k + 3) * CH + col], v[k0 + k + 3], a3);
    }
    part[kc][threadIdx.x & 63] = (a0 + a1) + (a2 + a3);
    __syncthreads();
    if (kc == 0) {
        int c = threadIdx.x & 63;
        vout[gmat * CH + col] = part[0][c] + part[1][c] + part[2][c] + part[3][c];
    }
}

__global__ void lam_kernel(const float* __restrict__ vprev, const float* __restrict__ vlast,
                           float* __restrict__ sigma)
{
    int g = blockIdx.x;
    int t = threadIdx.x;
    __shared__ float rp[512], rl[512];
    float vp = vprev[g * CH + t], vl = vlast[g * CH + t];
    rp[t] = vp * vp; rl[t] = vl * vl;
    __syncthreads();
    for (int st = 256; st > 0; st >>= 1) {
        if (t < st) { rp[t] += rp[t + st]; rl[t] += rl[t + st]; }
        __syncthreads();
    }
    if (t == 0) sigma[g] = 1.02f * sqrtf(rl[0] / fmaxf(rp[0], 1e-30f)) + 1e-20f;
}

// ---------------- Newton-Schulz init (fp16 split) ----------------
__global__ void ns_init_kernel(const float* __restrict__ Cov, const float* __restrict__ sigma,
                               __half* __restrict__ Yh, __half* __restrict__ Yl,
                               __half* __restrict__ Zh, __half* __restrict__ Zl)
{
    long long i = (long long)blockIdx.x * blockDim.x + threadIdx.x;
    if (i >= 4 * CC) return;
    int g = (int)(i / CC);
    long long r = i % CC;
    int row = (int)(r / CH), col = (int)(r % CH);
    float y = Cov[i] / sigma[g];
    __half h = __float2half_rn(y);
    Yh[i] = h;
    Yl[i] = __float2half_rn(y - __half2float(h));
    Zh[i] = __float2half_rn((row == col) ? 1.f : 0.f);
    Zl[i] = __float2half_rn(0.f);
}

// ---------------- rescale -> W, Cm fp16 splits ----------------
__global__ void scale16_kernel(const float* __restrict__ Yf, const float* __restrict__ Zf,
                               const float* __restrict__ sigma,
                               __half* __restrict__ Wh, __half* __restrict__ Wl,
                               __half* __restrict__ Cmh, __half* __restrict__ Cml)
{
    long long i = (long long)blockIdx.x * blockDim.x + threadIdx.x;
    if (i >= 4 * CC) return;
    int g = (int)(i / CC);
    float sq = sqrtf(sigma[g]);
    float w = Zf[i] / sq;
    __half h = __float2half_rn(w);
    Wh[i] = h;
    Wl[i] = __float2half_rn(w - __half2float(h));
    if (g >= 2) {
        float cm = Yf[i] * sq;
        __half hc = __float2half_rn(cm);
        Cmh[i - 2 * CC] = hc;
        Cml[i - 2 * CC] = __float2half_rn(cm - __half2float(hc));
    }
}

// ---------------- per-pixel squared norms ----------------
__global__ void snorm_kernel(const float* __restrict__ NSt, float* __restrict__ snorm)
{
    int gw = (blockIdx.x * blockDim.x + threadIdx.x) >> 5;
    int lane = threadIdx.x & 31;
    if (gw >= 2 * HW) return;
    int b = gw / HW, p = gw % HW;
    const float* row = NSt + (long long)b * CHW + (long long)p * CH;
    float s = 0.f;
    for (int c = lane; c < CH; c += 32) { float v = row[c]; s = fmaf(v, v, s); }
    for (int o = 16; o > 0; o >>= 1) s += __shfl_down_sync(0xffffffff, s, o);
    if (lane == 0) snorm[b * HW + p] = s;
}

__global__ void rknorm_kernel(const float* __restrict__ snorm, float* __restrict__ rk)
{
    int i = blockIdx.x * blockDim.x + threadIdx.x;
    if (i >= 2 * HW) return;
    int b = i / HW, p = i % HW;
    int py = p >> 6, px = p & 63;
    float sum = 0.f;
    for (int u = -1; u <= 1; u++)
        for (int v = -1; v <= 1; v++) {
            int yy = py + u, xx = px + v;
            if ((unsigned)yy < 64u && (unsigned)xx < 64u) sum += snorm[b * HW + yy * 64 + xx];
        }
    rk[i] = 1.f / (sqrtf(sum) + 1e-5f);
}

// ---------------- horizontal diagonal 3-box ----------------
__global__ void boxh_kernel(const float* __restrict__ M0, float* __restrict__ Tb)
{
    long long i = (long long)blockIdx.x * 256 + threadIdx.x;
    int b = blockIdx.y;
    const float* M = M0 + (long long)b * PQ;
    int p = (int)(i >> 12);
    int q = (int)(i & 4095);
    int px = p & 63, qx = q & 63;
    float s = 0.f;
#pragma unroll
    for (int v = -1; v <= 1; v++) {
        if ((unsigned)(px + v) < 64u && (unsigned)(qx + v) < 64u) s += M[i + (long long)v * 4097];
    }
    Tb[(long long)b * PQ + i] = s;
}

// ---------------- vertical diagonal 3-box + partial argmax ----------------
__global__ void argmax_part_kernel(const float* __restrict__ Tb, const float* __restrict__ rk,
                                   float* __restrict__ pbs, int* __restrict__ pbi)
{
    int b = blockIdx.z;
    int q = blockIdx.x * 256 + threadIdx.x;
    int pc = blockIdx.y;
    __shared__ float srk[256];
    srk[threadIdx.x] = rk[b * HW + pc * 256 + threadIdx.x];
    __syncthreads();
    const float* T = Tb + (long long)b * PQ;
    float best = -FLT_MAX; int bi = 0;
    for (int pp = 0; pp < 256; pp++) {
        int p = pc * 256 + pp;
        float s = 0.f;
#pragma unroll
        for (int u = -1; u <= 1; u++) {
            int row = p + 64 * u, col = q + 64 * u;
            if ((unsigned)row < (unsigned)HW && (unsigned)col < (unsigned)HW)
                s += T[(long long)row * HW + col];
        }
        float sc = s * srk[pp];
        if (sc > best) { best = sc; bi = p; }
    }
    pbs[(b * 16 + pc) * HW + q] = best;
    pbi[(b * 16 + pc) * HW + q] = bi;
}

__global__ void argmax_comb_kernel(const float* __restrict__ pbs, const int* __restrict__ pbi,
                                   int* __restrict__ idx)
{
    int i = blockIdx.x * 256 + threadIdx.x;
    if (i >= 2 * HW) return;
    int b = i / HW, q = i % HW;
    float best = -FLT_MAX; int bi = 0;
    for (int k = 0; k < 16; k++) {
        float s = pbs[(b * 16 + k) * HW + q];
        int p = pbi[(b * 16 + k) * HW + q];
        if (s > best || (s == best && p < bi)) { best = s; bi = p; }
    }
    idx[b * HW + q] = bi;
}

// ---------------- gather + overlap-add (emit fp16 split) ----------------
__global__ void gather_kernel(const float* __restrict__ NSt, const int* __restrict__ idx,
                              __half* __restrict__ rTh, __half* __restrict__ rTl)
{
    int b = blockIdx.y, pix = blockIdx.x;
    int Y = pix >> 6, X = pix & 63;
    __shared__ int sp[9];
    if (threadIdx.x < 9) {
        int dx = threadIdx.x / 3, dy = threadIdx.x % 3;
        int y = Y + 1 - dx, x = X + 1 - dy;
        int pos = -1;
        if ((unsigned)y < 64u && (unsigned)x < 64u) {
            int p = idx[b * HW + y * 64 + x];
            int sy = (p >> 6) + dx - 1, sx = (p & 63) + dy - 1;
            if ((unsigned)sy < 64u && (unsigned)sx < 64u) pos = sy * 64 + sx;
        }
        sp[threadIdx.x] = pos;
    }
    __syncthreads();
    int cy = (Y == 0 || Y == 63) ? 2 : 3;
    int cx = (X == 0 || X == 63) ? 2 : 3;
    float inv = 1.f / (float)(cy * cx);
    const float* base = NSt + (long long)b * CHW;
    long long obase = (long long)b * CHW + (long long)pix * CH;
    for (int c = threadIdx.x; c < CH; c += 128) {
        float a = 0.f;
#pragma unroll
        for (int k = 0; k < 9; k++) {
            int pos = sp[k];
            if (pos >= 0) a += base[(long long)pos * CH + c];
        }
        float v = a * inv;
        __half h = __float2half_rn(v);
        rTh[obase + c] = h;
        rTl[obase + c] = __float2half_rn(v - __half2float(h));
    }
}

// ---------------- host orchestration ----------------
extern "C" void kernel_launch(void* const* d_in, const int* in_sizes, int n_in,
                              void* d_out, int out_size)
{
    (void)in_sizes; (void)n_in; (void)out_size;
    const float* content = (const float*)d_in[0];
    const float* style   = (const float*)d_in[1];
    float* out = (float*)d_out;

    float *Fcent, *means, *Cov, *sigma, *pv, *Yf, *Zf, *NSt, *snorm, *rk, *M0, *Tb, *pbs;
    __half *Fch, *Fcl, *FcTh, *FcTl, *Yh, *Yl, *Zh, *Zl, *Th, *Tl, *Wh, *Wl, *Cmh, *Cml;
    __half *NCth, *NCtl, *NSth, *NStl, *rTh, *rTl;
    int *idx, *pbi;
    cudaGetSymbolAddress((void**)&Fcent, g_Fcent);
    cudaGetSymbolAddress((void**)&Fch,   g_Fch);
    cudaGetSymbolAddress((void**)&Fcl,   g_Fcl);
    cudaGetSymbolAddress((void**)&FcTh,  g_FcTh);
    cudaGetSymbolAddress((void**)&FcTl,  g_FcTl);
    cudaGetSymbolAddress((void**)&means, g_means);
    cudaGetSymbolAddress((void**)&Cov,   g_Cov);
    cudaGetSymbolAddress((void**)&sigma, g_sigma);
    cudaGetSymbolAddress((void**)&pv,    g_pv);
    cudaGetSymbolAddress((void**)&Yf,    g_Yf);
    cudaGetSymbolAddress((void**)&Zf,    g_Zf);
    cudaGetSymbolAddress((void**)&Yh,    g_Yh);
    cudaGetSymbolAddress((void**)&Yl,    g_Yl);
    cudaGetSymbolAddress((void**)&Zh,    g_Zh);
    cudaGetSymbolAddress((void**)&Zl,    g_Zl);
    cudaGetSymbolAddress((void**)&Th,    g_Th);
    cudaGetSymbolAddress((void**)&Tl,    g_Tl);
    cudaGetSymbolAddress((void**)&Wh,    g_Wh);
    cudaGetSymbolAddress((void**)&Wl,    g_Wl);
    cudaGetSymbolAddress((void**)&Cmh,   g_Cmh);
    cudaGetSymbolAddress((void**)&Cml,   g_Cml);
    cudaGetSymbolAddress((void**)&NSt,   g_NSt);
    cudaGetSymbolAddress((void**)&NCth,  g_NCth);
    cudaGetSymbolAddress((void**)&NCtl,  g_NCtl);
    cudaGetSymbolAddress((void**)&NSth,  g_NSth);
    cudaGetSymbolAddress((void**)&NStl,  g_NStl);
    cudaGetSymbolAddress((void**)&snorm, g_snorm);
    cudaGetSymbolAddress((void**)&rk,    g_rk);
    cudaGetSymbolAddress((void**)&M0,    g_M0);
    cudaGetSymbolAddress((void**)&Tb,    g_Tb);
    cudaGetSymbolAddress((void**)&idx,   g_idx);
    cudaGetSymbolAddress((void**)&pbs,   g_pbs);
    cudaGetSymbolAddress((void**)&pbi,   g_pbi);
    cudaGetSymbolAddress((void**)&rTh,   g_rTh);
    cudaGetSymbolAddress((void**)&rTl,   g_rTl);

    cudaFuncSetAttribute(cov16_kernel,    cudaFuncAttributeMaxDynamicSharedMemorySize, HG_SMEM);
    cudaFuncSetAttribute(nsT16_kernel,    cudaFuncAttributeMaxDynamicSharedMemorySize, HG_SMEM);
    cudaFuncSetAttribute(nsYZ16_kernel,   cudaFuncAttributeMaxDynamicSharedMemorySize, HG_SMEM);
    cudaFuncSetAttribute(whiten16_kernel, cudaFuncAttributeMaxDynamicSharedMemorySize, HG_SMEM);
    cudaFuncSetAttribute(m016_kernel,     cudaFuncAttributeMaxDynamicSharedMemorySize, HG_SMEM);
    cudaFuncSetAttribute(color16_kernel,  cudaFuncAttributeMaxDynamicSharedMemorySize, HG_SMEM);

    // 1) center (+ channel-major fp16 split)
    center_kernel<<<dim3(CH, 4), 256>>>(content, style, Fcent, Fch, Fcl, means);

    // 2) pixel-major transposed fp16 split
    transposeFcT_kernel<<<dim3(128, 16, 4), dim3(32, 32)>>>(Fcent, FcTh, FcTl);

    // 3) covariances on tensor cores
    cov16_kernel<<<dim3(4, 4, 4), 256, HG_SMEM>>>(Fch, Fcl, Cov);

    // 4) lambda_max: 6 unnormalized matvecs + norm ratio
    pinit_kernel<<<8, 256>>>(pv);
    float* vc = pv;
    float* vn = pv + 4 * CH;
    for (int it = 0; it < 6; it++) {
        matvec_kernel<<<dim3(8, 4), 256>>>(Cov, vc, vn);
        float* t = vc; vc = vn; vn = t;
    }
    lam_kernel<<<4, 512>>>(vn, vc, sigma);

    // 5) Newton-Schulz (5 iterations — 4 was shown insufficient in R14)
    ns_init_kernel<<<4096, 256>>>(Cov, sigma, Yh, Yl, Zh, Zl);
    int cur = 0;
    for (int it = 0; it < 5; it++) {
        int nxt = cur ^ 1;
        long long hc = (long long)cur * 4 * CC, hn = (long long)nxt * 4 * CC;
        nsT16_kernel<<<dim3(4, 4, 4), 256, HG_SMEM>>>(
            Zh + hc, Zl + hc, Yh + hc, Yl + hc, Th, Tl);
        nsYZ16_kernel<<<dim3(4, 4, 8), 256, HG_SMEM>>>(
            Yh + hc, Yl + hc, Zh + hc, Zl + hc, Th, Tl,
            Yf + hn, Yh + hn, Yl + hn, Zf + hn, Zh + hn, Zl + hn);
        cur = nxt;
    }
    long long hf = (long long)cur * 4 * CC;

    // 6) rescale -> W, Cm splits
    scale16_kernel<<<4096, 256>>>(Yf + hf, Zf + hf, sigma, Wh, Wl, Cmh, Cml);

    // 7) whitening on tensor cores
    whiten16_kernel<<<dim3(4, 32, 4), 256, HG_SMEM>>>(
        FcTh, FcTl, Wh, Wl, NSt, NCth, NCtl, NSth, NStl);

    // 8) patch norms
    snorm_kernel<<<1024, 256>>>(NSt, snorm);
    rknorm_kernel<<<32, 256>>>(snorm, rk);

    // 9) M0 on tensor cores
    m016_kernel<<<dim3(32, 32, 2), 256, HG_SMEM>>>(NSth, NStl, NCth, NCtl, M0);

    // 10) box filter + argmax
    boxh_kernel<<<dim3(65536, 2), 256>>>(M0, Tb);
    argmax_part_kernel<<<dim3(16, 16, 2), 256>>>(Tb, rk, pbs, pbi);
    argmax_comb_kernel<<<32, 256>>>(pbs, pbi, idx);

    // 11) gather + overlap-add
    gather_kernel<<<dim3(4096, 2), 128>>>(NSt, idx, rTh, rTl);

    // 12) color on tensor cores
    color16_kernel<<<dim3(32, 4, 2), 256, HG_SMEM>>>(Cmh, Cml, rTh, rTl, out, means);
}

// round 16
// speedup vs baseline: 2.2123x; 1.0840x over previous
#include <cuda_runtime.h>
#include <cuda_fp16.h>
#include <math.h>
#include <float.h>
#include <stdint.h>

// ---------------- problem constants ----------------
#define CH   512
#define HW   4096
constexpr long long CHW = (long long)CH * HW;
constexpr long long CC  = (long long)CH * CH;
constexpr long long PQ  = (long long)HW * HW;

// ---------------- device scratch ----------------
__device__ float  g_Fcent[4 * 2097152];
__device__ __half g_Fch[4 * 2097152];
__device__ __half g_Fcl[4 * 2097152];
__device__ __half g_FcTh[4 * 2097152];
__device__ __half g_FcTl[4 * 2097152];
__device__ float  g_means[4 * 512];
__device__ float  g_Cov[4 * 262144];
__device__ float  g_Covp[32 * 262144];   // 8 K-chunks x 4 matrices
__device__ float  g_sigma[4];
__device__ float  g_pv[2 * 4 * 512];
__device__ float  g_Yf[2 * 4 * 262144];
__device__ float  g_Zf[2 * 4 * 262144];
__device__ __half g_Yh[2 * 4 * 262144];
__device__ __half g_Yl[2 * 4 * 262144];
__device__ __half g_Zh[2 * 4 * 262144];
__device__ __half g_Zl[2 * 4 * 262144];
__device__ __half g_Th[4 * 262144];
__device__ __half g_Tl[4 * 262144];
__device__ __half g_Wh[4 * 262144];
__device__ __half g_Wl[4 * 262144];
__device__ __half g_Cmh[2 * 262144];
__device__ __half g_Cml[2 * 262144];
__device__ float  g_NSt[2 * 2097152];
__device__ __half g_NCth[2 * 2097152];
__device__ __half g_NCtl[2 * 2097152];
__device__ __half g_NSth[2 * 2097152];
__device__ __half g_NStl[2 * 2097152];
__device__ float  g_snorm[2 * 4096];
__device__ float  g_rk[2 * 4096];
__device__ float  g_M0[33554432];
__device__ float  g_Tb[33554432];
__device__ int    g_idx[2 * 4096];
__device__ float  g_pbs[2 * 16 * 4096];
__device__ int    g_pbi[2 * 16 * 4096];
__device__ __half g_rTh[2 * 2097152];
__device__ __half g_rTl[2 * 2097152];

// ---------------- helpers ----------------
__device__ __forceinline__ uint32_t smem_to_u32(const void* p) {
    uint32_t a;
    asm("{ .reg .u64 t; cvta.to.shared.u64 t, %1; cvt.u32.u64 %0, t; }" : "=r"(a) : "l"(p));
    return a;
}
__device__ __forceinline__ void cp_async16(uint32_t saddr, const void* g) {
    asm volatile("cp.async.cg.shared.global [%0], [%1], 16;" :: "r"(saddr), "l"(g));
}
#define CP_COMMIT() asm volatile("cp.async.commit_group;" ::: "memory")
#define CP_WAIT1()  asm volatile("cp.async.wait_group 1;" ::: "memory")
#define CP_WAIT0()  asm volatile("cp.async.wait_group 0;" ::: "memory")

__device__ __forceinline__ void mma_f16(float* c, const uint32_t* a, const uint32_t* b) {
    asm volatile(
        "mma.sync.aligned.m16n8k16.row.col.f32.f16.f16.f32 "
        "{%0,%1,%2,%3}, {%4,%5,%6,%7}, {%8,%9}, {%0,%1,%2,%3};"
        : "+f"(c[0]), "+f"(c[1]), "+f"(c[2]), "+f"(c[3])
        : "r"(a[0]), "r"(a[1]), "r"(a[2]), "r"(a[3]), "r"(b[0]), "r"(b[1]));
}

__device__ __forceinline__ void split_store(__half* Ch, __half* Cl, long long off,
                                            float x, float y) {
    __half hx = __float2half_rn(x), hy = __float2half_rn(y);
    __half lx = __float2half_rn(x - __half2float(hx));
    __half ly = __float2half_rn(y - __half2float(hy));
    *(__half2*)&Ch[off] = __halves2half2(hx, hy);
    *(__half2*)&Cl[off] = __halves2half2(lx, ly);
}

// ---------------- generic fp16-split 3-product MMA GEMM tile ----------------
// A rows at stride lda, B rows at stride lda, K columns consumed.
#define SKPH 40
constexpr int HG_ARRH = 128 * SKPH;
constexpr int HG_BUFH = 4 * HG_ARRH;
constexpr int HG_SMEM = 2 * HG_BUFH * 2;     // 81920 bytes

__device__ __forceinline__ void hgemm_tile(
    const __half* __restrict__ Ah, const __half* __restrict__ Al,
    const __half* __restrict__ Bh, const __half* __restrict__ Bl,
    float* __restrict__ Cf, __half* __restrict__ Ch, __half* __restrict__ Cl,
    int ldC, int K, int lda, float alpha, float diagAdd, const float* __restrict__ bias,
    __half* smh)
{
    const uint32_t sbase = smem_to_u32(smh);
    const int tid  = threadIdx.x;
    const int wid  = tid >> 5, lane = tid & 31;
    const int g    = lane >> 2, t = lane & 3;
    const int wm   = wid & 3, wn = wid >> 2;
    const int m0   = blockIdx.y * 128, n0 = blockIdx.x * 128;

    auto stage = [&](int kt, int buf) {
#pragma unroll
        for (int tt = 0; tt < 8; tt++) {
            int idx = tid + tt * 256;
            int a   = idx >> 9;
            int rem = idx & 511;
            int r   = rem >> 2;
            int c8  = (rem & 3) * 8;
            const __half* src = (a == 0) ? Ah : (a == 1) ? Al : (a == 2) ? Bh : Bl;
            int rowbase = (a < 2) ? m0 : n0;
            const __half* gp = src + (long long)(rowbase + r) * lda + kt * 32 + c8;
            uint32_t sa = sbase + (uint32_t)(buf * HG_BUFH + a * HG_ARRH + r * SKPH + c8) * 2u;
            cp_async16(sa, gp);
        }
    };

    float acc[2][8][4];
#pragma unroll
    for (int i = 0; i < 2; i++)
#pragma unroll
        for (int j = 0; j < 8; j++)
#pragma unroll
            for (int k = 0; k < 4; k++) acc[i][j][k] = 0.f;

    const int nk = K >> 5;
    stage(0, 0); CP_COMMIT();

    for (int kt = 0; kt < nk; kt++) {
        const int buf = kt & 1;
        if (kt + 1 < nk) { stage(kt + 1, buf ^ 1); CP_COMMIT(); CP_WAIT1(); }
        else             { CP_WAIT0(); }
        __syncthreads();

        const __half* sAh = smh + buf * HG_BUFH;
        const __half* sAl = sAh + HG_ARRH;
        const __half* sBh = sAl + HG_ARRH;
        const __half* sBl = sBh + HG_ARRH;
#pragma unroll
        for (int ks = 0; ks < 32; ks += 16) {
            uint32_t afh[2][4], afl[2][4];
#pragma unroll
            for (int mt = 0; mt < 2; mt++) {
                int r  = wm * 32 + mt * 16;
                int i0 = (r + g) * SKPH + ks + 2 * t;
                int i8 = (r + g + 8) * SKPH + ks + 2 * t;
                afh[mt][0] = *(const uint32_t*)&sAh[i0];
                afh[mt][1] = *(const uint32_t*)&sAh[i8];
                afh[mt][2] = *(const uint32_t*)&sAh[i0 + 8];
                afh[mt][3] = *(const uint32_t*)&sAh[i8 + 8];
                afl[mt][0] = *(const uint32_t*)&sAl[i0];
                afl[mt][1] = *(const uint32_t*)&sAl[i8];
                afl[mt][2] = *(const uint32_t*)&sAl[i0 + 8];
                afl[mt][3] = *(const uint32_t*)&sAl[i8 + 8];
            }
#pragma unroll
            for (int nt = 0; nt < 8; nt++) {
                int bb = (wn * 64 + nt * 8 + g) * SKPH + ks + 2 * t;
                uint32_t bfh[2] = { *(const uint32_t*)&sBh[bb], *(const uint32_t*)&sBh[bb + 8] };
                uint32_t bfl[2] = { *(const uint32_t*)&sBl[bb], *(const uint32_t*)&sBl[bb + 8] };
#pragma unroll
                for (int mt = 0; mt < 2; mt++) {
                    mma_f16(acc[mt][nt], afh[mt], bfh);
                    mma_f16(acc[mt][nt], afh[mt], bfl);
                    mma_f16(acc[mt][nt], afl[mt], bfh);
                }
            }
        }
        __syncthreads();
    }

#pragma unroll
    for (int mt = 0; mt < 2; mt++) {
        int row0 = m0 + wm * 32 + mt * 16 + g;
        int row1 = row0 + 8;
        float bv0 = bias ? bias[row0] : 0.f;
        float bv1 = bias ? bias[row1] : 0.f;
#pragma unroll
        for (int nt = 0; nt < 8; nt++) {
            int col = n0 + wn * 64 + nt * 8 + 2 * t;
            float x0 = alpha * acc[mt][nt][0] + bv0; if (row0 == col)     x0 += diagAdd;
            float y0 = alpha * acc[mt][nt][1] + bv0; if (row0 == col + 1) y0 += diagAdd;
            float x1 = alpha * acc[mt][nt][2] + bv1; if (row1 == col)     x1 += diagAdd;
            float y1 = alpha * acc[mt][nt][3] + bv1; if (row1 == col + 1) y1 += diagAdd;
            long long o0 = (long long)row0 * ldC + col;
            long long o1 = (long long)row1 * ldC + col;
            if (Cf) {
                float2 v0; v0.x = x0; v0.y = y0; *(float2*)&Cf[o0] = v0;
                float2 v1; v1.x = x1; v1.y = y1; *(float2*)&Cf[o1] = v1;
            }
            if (Ch) {
                split_store(Ch, Cl, o0, x0, y0);
                split_store(Ch, Cl, o1, x1, y1);
            }
        }
    }
}

// ---------------- hgemm wrapper kernels ----------------
// cov partials: z = g*8 + chunk ; K=512 slice of the 4096-long rows
__global__ void __launch_bounds__(256, 2) covp16_kernel(
    const __half* __restrict__ Fh, const __half* __restrict__ Fl, float* __restrict__ Covp)
{
    extern __shared__ __half smh[];
    int z = blockIdx.z;
    int g = z >> 3, chunk = z & 7;
    long long o = (long long)g * CHW + (long long)chunk * 512;
    hgemm_tile(Fh + o, Fl + o, Fh + o, Fl + o,
               Covp + (long long)z * CC, nullptr, nullptr,
               512, 512, 4096, 1.f, 0.f, nullptr, smh);
}

__global__ void covred_kernel(const float* __restrict__ Covp, float* __restrict__ Cov)
{
    long long i = (long long)blockIdx.x * 256 + threadIdx.x;
    if (i >= 4 * CC) return;
    int g = (int)(i / CC);
    long long r = i % CC;
    const float* base = Covp + (long long)g * 8 * CC + r;
    float s = 0.f;
#pragma unroll
    for (int c = 0; c < 8; c++) s += base[(long long)c * CC];
    Cov[i] = s * (1.f / 4095.f);
}

__global__ void __launch_bounds__(256, 2) nsT16_kernel(
    const __half* __restrict__ Zh, const __half* __restrict__ Zl,
    const __half* __restrict__ Yh, const __half* __restrict__ Yl,
    __half* __restrict__ Th, __half* __restrict__ Tl)
{
    extern __shared__ __half smh[];
    long long o = (long long)blockIdx.z * CC;
    hgemm_tile(Zh + o, Zl + o, Yh + o, Yl + o,
               nullptr, Th + o, Tl + o, 512, 512, 512, -0.5f, 1.5f, nullptr, smh);
}

__global__ void __launch_bounds__(256, 2) nsYZ16_kernel(
    const __half* __restrict__ Yh, const __half* __restrict__ Yl,
    const __half* __restrict__ Zh, const __half* __restrict__ Zl,
    const __half* __restrict__ Th, const __half* __restrict__ Tl,
    float* __restrict__ Ynf, __half* __restrict__ Ynh, __half* __restrict__ Ynl,
    float* __restrict__ Znf, __half* __restrict__ Znh, __half* __restrict__ Znl)
{
    extern __shared__ __half smh[];
    int z = blockIdx.z;
    if (z < 4) {
        long long o = (long long)z * CC;
        hgemm_tile(Yh + o, Yl + o, Th + o, Tl + o,
                   Ynf + o, Ynh + o, Ynl + o, 512, 512, 512, 1.f, 0.f, nullptr, smh);
    } else {
        long long o = (long long)(z - 4) * CC;
        hgemm_tile(Th + o, Tl + o, Zh + o, Zl + o,
                   Znf + o, Znh + o, Znl + o, 512, 512, 512, 1.f, 0.f, nullptr, smh);
    }
}

__global__ void __launch_bounds__(256, 2) whiten16_kernel(
    const __half* __restrict__ FcTh, const __half* __restrict__ FcTl,
    const __half* __restrict__ Wh, const __half* __restrict__ Wl,
    float* __restrict__ NSt,
    __half* __restrict__ NCth, __half* __restrict__ NCtl,
    __half* __restrict__ NSth, __half* __restrict__ NStl)
{
    extern __shared__ __half smh[];
    int z = blockIdx.z;
    long long oa = (long long)z * CHW;
    long long ow = (long long)z * CC;
    float* cf; __half *ch, *cl;
    if (z < 2) { cf = nullptr; ch = NCth + oa; cl = NCtl + oa; }
    else       { long long os = (long long)(z - 2) * CHW;
                 cf = NSt + os; ch = NSth + os; cl = NStl + os; }
    hgemm_tile(FcTh + oa, FcTl + oa, Wh + ow, Wl + ow,
               cf, ch, cl, 512, 512, 512, 1.f, 0.f, nullptr, smh);
}

__global__ void __launch_bounds__(256, 2) m016_kernel(
    const __half* __restrict__ Ah, const __half* __restrict__ Al,
    const __half* __restrict__ Bh, const __half* __restrict__ Bl,
    float* __restrict__ M0out)
{
    extern __shared__ __half smh[];
    long long o = (long long)blockIdx.z * CHW;
    hgemm_tile(Ah + o, Al + o, Bh + o, Bl + o,
               M0out + (long long)blockIdx.z * PQ, nullptr, nullptr,
               4096, 512, 512, 1.f, 0.f, nullptr, smh);
}

__global__ void __launch_bounds__(256, 2) color16_kernel(
    const __half* __restrict__ Cmh, const __half* __restrict__ Cml,
    const __half* __restrict__ rTh, const __half* __restrict__ rTl,
    float* __restrict__ out, const float* __restrict__ means)
{
    extern __shared__ __half smh[];
    int b = blockIdx.z;
    hgemm_tile(Cmh + (long long)b * CC, Cml + (long long)b * CC,
               rTh + (long long)b * CHW, rTl + (long long)b * CHW,
               out + (long long)b * CHW, nullptr, nullptr,
               4096, 512, 512, 1.f, 0.f, means + (long long)(2 + b) * CH, smh);
}

// ---------------- per-channel mean + center (+ fp16 split) ----------------
__global__ void center_kernel(const float* __restrict__ content, const float* __restrict__ style,
                              float* __restrict__ Fcent, __half* __restrict__ Fch,
                              __half* __restrict__ Fcl, float* __restrict__ means)
{
    int c = blockIdx.x, g = blockIdx.y;
    const float* src = (g < 2 ? content + (long long)g * CHW : style + (long long)(g - 2) * CHW)
                       + (long long)c * HW;
    __shared__ float red[256];
    float s = 0.f;
    for (int i = threadIdx.x; i < HW; i += 256) s += src[i];
    red[threadIdx.x] = s; __syncthreads();
    for (int st = 128; st > 0; st >>= 1) {
        if (threadIdx.x < st) red[threadIdx.x] += red[threadIdx.x + st];
        __syncthreads();
    }
    float mean = red[0] * (1.f / HW);
    if (threadIdx.x == 0) means[g * CH + c] = mean;
    long long base = (long long)g * CHW + (long long)c * HW;
    for (int i = threadIdx.x; i < HW; i += 256) {
        float v = src[i] - mean;
        Fcent[base + i] = v;
        __half h = __float2half_rn(v);
        Fch[base + i] = h;
        Fcl[base + i] = __float2half_rn(v - __half2float(h));
    }
}

// ---------------- transpose + fp16 split of Fcent ----------------
__global__ void transposeFcT_kernel(const float* __restrict__ Fcent,
                                    __half* __restrict__ FcTh, __half* __restrict__ FcTl)
{
    __shared__ float tile[32][33];
    int g = blockIdx.z;
    int p0 = blockIdx.x * 32, c0 = blockIdx.y * 32;
    tile[threadIdx.y][threadIdx.x] =
        Fcent[(long long)g * CHW + (long long)(c0 + threadIdx.y) * HW + p0 + threadIdx.x];
    __syncthreads();
    float x = tile[threadIdx.x][threadIdx.y];
    long long o = (long long)g * CHW + (long long)(p0 + threadIdx.y) * CH + c0 + threadIdx.x;
    __half h = __float2half_rn(x);
    FcTh[o] = h;
    FcTl[o] = __float2half_rn(x - __half2float(h));
}

// ---------------- power iteration as unnormalized matvec chain ----------------
__global__ void pinit_kernel(float* __restrict__ v)
{
    int i = blockIdx.x * 256 + threadIdx.x;
    if (i < 4 * CH) v[i] = 1.f + 1e-4f * (i & (CH - 1));
}

__global__ void matvec_kernel(const float* __restrict__ Cov,
                              const float* __restrict__ vin, float* __restrict__ vout)
{
    int gmat = blockIdx.y;
    const float* A = Cov + (long long)gmat * CC;
    const float* v = vin + gmat * CH;
    int col = blockIdx.x * 64 + (threadIdx.x & 63);
    int kc  = threadIdx.x >> 6;
    __shared__ float part[4][64];
    float a0 = 0.f, a1 = 0.f, a2 = 0.f, a3 = 0.f;
    int k0 = kc * 128;
#pragma unroll 8
    for (int k = 0; k < 128; k += 4) {
        a0 = fmaf(A[(long long)(k0 + k + 0) * CH + col], v[k0 + k + 0], a0);
        a1 = fmaf(A[(long long)(k0 + k + 1) * CH + col], v[k0 + k + 1], a1);
        a2 = fmaf(A[(long long)(k0 + k + 2) * CH + col], v[k0 + k + 2], a2);
        a3 = fmaf(A[(long long)(k0 + k + 3) * CH + col], v[k0 + k + 3], a3);
    }
    part[kc][threadIdx.x & 63] = (a0 + a1) + (a2 + a3);
    __syncthreads();
    if (kc == 0) {
        int c = threadIdx.x & 63;
        vout[gmat * CH + col] = part[0][c] + part[1][c] + part[2][c] + part[3][c];
    }
}

__global__ void lam_kernel(const float* __restrict__ vprev, const float* __restrict__ vlast,
                           float* __restrict__ sigma)
{
    int g = blockIdx.x;
    int t = threadIdx.x;
    __shared__ float rp[512], rl[512];
    float vp = vprev[g * CH + t], vl = vlast[g * CH + t];
    rp[t] = vp * vp; rl[t] = vl * vl;
    __syncthreads();
    for (int st = 256; st > 0; st >>= 1) {
        if (t < st) { rp[t] += rp[t + st]; rl[t] += rl[t + st]; }
        __syncthreads();
    }
    if (t == 0) sigma[g] = 1.02f * sqrtf(rl[0] / fmaxf(rp[0], 1e-30f)) + 1e-20f;
}

// ---------------- Newton-Schulz init (fp16 split) ----------------
__global__ void ns_init_kernel(const float* __restrict__ Cov, const float* __restrict__ sigma,
                               __half* __restrict__ Yh, __half* __restrict__ Yl,
                               __half* __restrict__ Zh, __half* __restrict__ Zl)
{
    long long i = (long long)blockIdx.x * blockDim.x + threadIdx.x;
    if (i >= 4 * CC) return;
    int g = (int)(i / CC);
    long long r = i % CC;
    int row = (int)(r / CH), col = (int)(r % CH);
    float y = Cov[i] / sigma[g];
    __half h = __float2half_rn(y);
    Yh[i] = h;
    Yl[i] = __float2half_rn(y - __half2float(h));
    Zh[i] = __float2half_rn((row == col) ? 1.f : 0.f);
    Zl[i] = __float2half_rn(0.f);
}

// ---------------- rescale -> W, Cm fp16 splits ----------------
__global__ void scale16_kernel(const float* __restrict__ Yf, const float* __restrict__ Zf,
                               const float* __restrict__ sigma,
                               __half* __restrict__ Wh, __half* __restrict__ Wl,
                               __half* __restrict__ Cmh, __half* __restrict__ Cml)
{
    long long i = (long long)blockIdx.x * blockDim.x + threadIdx.x;
    if (i >= 4 * CC) return;
    int g = (int)(i / CC);
    float sq = sqrtf(sigma[g]);
    float w = Zf[i] / sq;
    __half h = __float2half_rn(w);
    Wh[i] = h;
    Wl[i] = __float2half_rn(w - __half2float(h));
    if (g >= 2) {
        float cm = Yf[i] * sq;
        __half hc = __float2half_rn(cm);
        Cmh[i - 2 * CC] = hc;
        Cml[i - 2 * CC] = __float2half_rn(cm - __half2float(hc));
    }
}

// ---------------- per-pixel squared norms ----------------
__global__ void snorm_kernel(const float* __restrict__ NSt, float* __restrict__ snorm)
{
    int gw = (blockIdx.x * blockDim.x + threadIdx.x) >> 5;
    int lane = threadIdx.x & 31;
    if (gw >= 2 * HW) return;
    int b = gw / HW, p = gw % HW;
    const float* row = NSt + (long long)b * CHW + (long long)p * CH;
    float s = 0.f;
    for (int c = lane; c < CH; c += 32) { float v = row[c]; s = fmaf(v, v, s); }
    for (int o = 16; o > 0; o >>= 1) s += __shfl_down_sync(0xffffffff, s, o);
    if (lane == 0) snorm[b * HW + p] = s;
}

__global__ void rknorm_kernel(const float* __restrict__ snorm, float* __restrict__ rk)
{
    int i = blockIdx.x * blockDim.x + threadIdx.x;
    if (i >= 2 * HW) return;
    int b = i / HW, p = i % HW;
    int py = p >> 6, px = p & 63;
    float sum = 0.f;
    for (int u = -1; u <= 1; u++)
        for (int v = -1; v <= 1; v++) {
            int yy = py + u, xx = px + v;
            if ((unsigned)yy < 64u && (unsigned)xx < 64u) sum += snorm[b * HW + yy * 64 + xx];
        }
    rk[i] = 1.f / (sqrtf(sum) + 1e-5f);
}

// ---------------- horizontal diagonal 3-box ----------------
__global__ void boxh_kernel(const float* __restrict__ M0, float* __restrict__ Tb)
{
    long long i = (long long)blockIdx.x * 256 + threadIdx.x;
    int b = blockIdx.y;
    const float* M = M0 + (long long)b * PQ;
    int p = (int)(i >> 12);
    int q = (int)(i & 4095);
    int px = p & 63, qx = q & 63;
    float s = 0.f;
#pragma unroll
    for (int v = -1; v <= 1; v++) {
        if ((unsigned)(px + v) < 64u && (unsigned)(qx + v) < 64u) s += M[i + (long long)v * 4097];
    }
    Tb[(long long)b * PQ + i] = s;
}

// ---------------- vertical diagonal 3-box + partial argmax ----------------
__global__ void argmax_part_kernel(const float* __restrict__ Tb, const float* __restrict__ rk,
                                   float* __restrict__ pbs, int* __restrict__ pbi)
{
    int b = blockIdx.z;
    int q = blockIdx.x * 256 + threadIdx.x;
    int pc = blockIdx.y;
    __shared__ float srk[256];
    srk[threadIdx.x] = rk[b * HW + pc * 256 + threadIdx.x];
    __syncthreads();
    const float* T = Tb + (long long)b * PQ;
    float best = -FLT_MAX; int bi = 0;
    for (int pp = 0; pp < 256; pp++) {
        int p = pc * 256 + pp;
        float s = 0.f;
#pragma unroll
        for (int u = -1; u <= 1; u++) {
            int row = p + 64 * u, col = q + 64 * u;
            if ((unsigned)row < (unsigned)HW && (unsigned)col < (unsigned)HW)
                s += T[(long long)row * HW + col];
        }
        float sc = s * srk[pp];
        if (sc > best) { best = sc; bi = p; }
    }
    pbs[(b * 16 + pc) * HW + q] = best;
    pbi[(b * 16 + pc) * HW + q] = bi;
}

__global__ void argmax_comb_kernel(const float* __restrict__ pbs, const int* __restrict__ pbi,
                                   int* __restrict__ idx)
{
    int i = blockIdx.x * 256 + threadIdx.x;
    if (i >= 2 * HW) return;
    int b = i / HW, q = i % HW;
    float best = -FLT_MAX; int bi = 0;
    for (int k = 0; k < 16; k++) {
        float s = pbs[(b * 16 + k) * HW + q];
        int p = pbi[(b * 16 + k) * HW + q];
        if (s > best || (s == best && p < bi)) { best = s; bi = p; }
    }
    idx[b * HW + q] = bi;
}

// ---------------- gather + overlap-add (emit fp16 split) ----------------
__global__ void gather_kernel(const float* __restrict__ NSt, const int* __restrict__ idx,
                              __half* __restrict__ rTh, __half* __restrict__ rTl)
{
    int b = blockIdx.y, pix = blockIdx.x;
    int Y = pix >> 6, X = pix & 63;
    __shared__ int sp[9];
    if (threadIdx.x < 9) {
        int dx = threadIdx.x / 3, dy = threadIdx.x % 3;
        int y = Y + 1 - dx, x = X + 1 - dy;
        int pos = -1;
        if ((unsigned)y < 64u && (unsigned)x < 64u) {
            int p = idx[b * HW + y * 64 + x];
            int sy = (p >> 6) + dx - 1, sx = (p & 63) + dy - 1;
            if ((unsigned)sy < 64u && (unsigned)sx < 64u) pos = sy * 64 + sx;
        }
        sp[threadIdx.x] = pos;
    }
    __syncthreads();
    int cy = (Y == 0 || Y == 63) ? 2 : 3;
    int cx = (X == 0 || X == 63) ? 2 : 3;
    float inv = 1.f / (float)(cy * cx);
    const float* base = NSt + (long long)b * CHW;
    long long obase = (long long)b * CHW + (long long)pix * CH;
    for (int c = threadIdx.x; c < CH; c += 128) {
        float a = 0.f;
#pragma unroll
        for (int k = 0; k < 9; k++) {
            int pos = sp[k];
            if (pos >= 0) a += base[(long long)pos * CH + c];
        }
        float v = a * inv;
        __half h = __float2half_rn(v);
        rTh[obase + c] = h;
        rTl[obase + c] = __float2half_rn(v - __half2float(h));
    }
}

// ---------------- host orchestration ----------------
extern "C" void kernel_launch(void* const* d_in, const int* in_sizes, int n_in,
                              void* d_out, int out_size)
{
    (void)in_sizes; (void)n_in; (void)out_size;
    const float* content = (const float*)d_in[0];
    const float* style   = (const float*)d_in[1];
    float* out = (float*)d_out;

    float *Fcent, *means, *Cov, *Covp, *sigma, *pv, *Yf, *Zf, *NSt, *snorm, *rk, *M0, *Tb, *pbs;
    __half *Fch, *Fcl, *FcTh, *FcTl, *Yh, *Yl, *Zh, *Zl, *Th, *Tl, *Wh, *Wl, *Cmh, *Cml;
    __half *NCth, *NCtl, *NSth, *NStl, *rTh, *rTl;
    int *idx, *pbi;
    cudaGetSymbolAddress((void**)&Fcent, g_Fcent);
    cudaGetSymbolAddress((void**)&Fch,   g_Fch);
    cudaGetSymbolAddress((void**)&Fcl,   g_Fcl);
    cudaGetSymbolAddress((void**)&FcTh,  g_FcTh);
    cudaGetSymbolAddress((void**)&FcTl,  g_FcTl);
    cudaGetSymbolAddress((void**)&means, g_means);
    cudaGetSymbolAddress((void**)&Cov,   g_Cov);
    cudaGetSymbolAddress((void**)&Covp,  g_Covp);
    cudaGetSymbolAddress((void**)&sigma, g_sigma);
    cudaGetSymbolAddress((void**)&pv,    g_pv);
    cudaGetSymbolAddress((void**)&Yf,    g_Yf);
    cudaGetSymbolAddress((void**)&Zf,    g_Zf);
    cudaGetSymbolAddress((void**)&Yh,    g_Yh);
    cudaGetSymbolAddress((void**)&Yl,    g_Yl);
    cudaGetSymbolAddress((void**)&Zh,    g_Zh);
    cudaGetSymbolAddress((void**)&Zl,    g_Zl);
    cudaGetSymbolAddress((void**)&Th,    g_Th);
    cudaGetSymbolAddress((void**)&Tl,    g_Tl);
    cudaGetSymbolAddress((void**)&Wh,    g_Wh);
    cudaGetSymbolAddress((void**)&Wl,    g_Wl);
    cudaGetSymbolAddress((void**)&Cmh,   g_Cmh);
    cudaGetSymbolAddress((void**)&Cml,   g_Cml);
    cudaGetSymbolAddress((void**)&NSt,   g_NSt);
    cudaGetSymbolAddress((void**)&NCth,  g_NCth);
    cudaGetSymbolAddress((void**)&NCtl,  g_NCtl);
    cudaGetSymbolAddress((void**)&NSth,  g_NSth);
    cudaGetSymbolAddress((void**)&NStl,  g_NStl);
    cudaGetSymbolAddress((void**)&snorm, g_snorm);
    cudaGetSymbolAddress((void**)&rk,    g_rk);
    cudaGetSymbolAddress((void**)&M0,    g_M0);
    cudaGetSymbolAddress((void**)&Tb,    g_Tb);
    cudaGetSymbolAddress((void**)&idx,   g_idx);
    cudaGetSymbolAddress((void**)&pbs,   g_pbs);
    cudaGetSymbolAddress((void**)&pbi,   g_pbi);
    cudaGetSymbolAddress((void**)&rTh,   g_rTh);
    cudaGetSymbolAddress((void**)&rTl,   g_rTl);

    cudaFuncSetAttribute(covp16_kernel,   cudaFuncAttributeMaxDynamicSharedMemorySize, HG_SMEM);
    cudaFuncSetAttribute(nsT16_kernel,    cudaFuncAttributeMaxDynamicSharedMemorySize, HG_SMEM);
    cudaFuncSetAttribute(nsYZ16_kernel,   cudaFuncAttributeMaxDynamicSharedMemorySize, HG_SMEM);
    cudaFuncSetAttribute(whiten16_kernel, cudaFuncAttributeMaxDynamicSharedMemorySize, HG_SMEM);
    cudaFuncSetAttribute(m016_kernel,     cudaFuncAttributeMaxDynamicSharedMemorySize, HG_SMEM);
    cudaFuncSetAttribute(color16_kernel,  cudaFuncAttributeMaxDynamicSharedMemorySize, HG_SMEM);

    // 1) center (+ channel-major fp16 split)
    center_kernel<<<dim3(CH, 4), 256>>>(content, style, Fcent, Fch, Fcl, means);

    // 2) pixel-major transposed fp16 split
    transposeFcT_kernel<<<dim3(128, 16, 4), dim3(32, 32)>>>(Fcent, FcTh, FcTl);

    // 3) covariances: K split into 8 chunks (512 blocks, full chip) + reduce
    covp16_kernel<<<dim3(4, 4, 32), 256, HG_SMEM>>>(Fch, Fcl, Covp);
    covred_kernel<<<4096, 256>>>(Covp, Cov);

    // 4) lambda_max: 6 unnormalized matvecs + norm ratio
    pinit_kernel<<<8, 256>>>(pv);
    float* vc = pv;
    float* vn = pv + 4 * CH;
    for (int it = 0; it < 6; it++) {
        matvec_kernel<<<dim3(8, 4), 256>>>(Cov, vc, vn);
        float* t = vc; vc = vn; vn = t;
    }
    lam_kernel<<<4, 512>>>(vn, vc, sigma);

    // 5) Newton-Schulz (5 iterations)
    ns_init_kernel<<<4096, 256>>>(Cov, sigma, Yh, Yl, Zh, Zl);
    int cur = 0;
    for (int it = 0; it < 5; it++) {
        int nxt = cur ^ 1;
        long long hc = (long long)cur * 4 * CC, hn = (long long)nxt * 4 * CC;
        nsT16_kernel<<<dim3(4, 4, 4), 256, HG_SMEM>>>(
            Zh + hc, Zl + hc, Yh + hc, Yl + hc, Th, Tl);
        nsYZ16_kernel<<<dim3(4, 4, 8), 256, HG_SMEM>>>(
            Yh + hc, Yl + hc, Zh + hc, Zl + hc, Th, Tl,
            Yf + hn, Yh + hn, Yl + hn, Zf + hn, Zh + hn, Zl + hn);
        cur = nxt;
    }
    long long hf = (long long)cur * 4 * CC;

    // 6) rescale -> W, Cm splits
    scale16_kernel<<<4096, 256>>>(Yf + hf, Zf + hf, sigma, Wh, Wl, Cmh, Cml);

    // 7) whitening on tensor cores
    whiten16_kernel<<<dim3(4, 32, 4), 256, HG_SMEM>>>(
        FcTh, FcTl, Wh, Wl, NSt, NCth, NCtl, NSth, NStl);

    // 8) patch norms
    snorm_kernel<<<1024, 256>>>(NSt, snorm);
    rknorm_kernel<<<32, 256>>>(snorm, rk);

    // 9) M0 on tensor cores
    m016_kernel<<<dim3(32, 32, 2), 256, HG_SMEM>>>(NSth, NStl, NCth, NCtl, M0);

    // 10) box filter + argmax
    boxh_kernel<<<dim3(65536, 2), 256>>>(M0, Tb);
    argmax_part_kernel<<<dim3(16, 16, 2), 256>>>(Tb, rk, pbs, pbi);
    argmax_comb_kernel<<<32, 256>>>(pbs, pbi, idx);

    // 11) gather + overlap-add
    gather_kernel<<<dim3(4096, 2), 128>>>(NSt, idx, rTh, rTl);

    // 12) color on tensor cores
    color16_kernel<<<dim3(32, 4, 2), 256, HG_SMEM>>>(Cmh, Cml, rTh, rTl, out, means);
}

// round 17
// speedup vs baseline: 2.2362x; 1.0108x over previous
#include <cuda_runtime.h>
#include <cuda_fp16.h>
#include <math.h>
#include <float.h>
#include <stdint.h>

// ---------------- problem constants ----------------
#define CH   512
#define HW   4096
constexpr long long CHW = (long long)CH * HW;
constexpr long long CC  = (long long)CH * CH;
constexpr long long PQ  = (long long)HW * HW;

// ---------------- device scratch ----------------
__device__ float  g_Fcent[4 * 2097152];
__device__ __half g_Fch[4 * 2097152];
__device__ __half g_Fcl[4 * 2097152];
__device__ __half g_FcTh[4 * 2097152];
__device__ __half g_FcTl[4 * 2097152];
__device__ float  g_means[4 * 512];
__device__ float  g_Cov[4 * 262144];
__device__ float  g_Covp[32 * 262144];   // shared partial buffer (cov / nsT / nsYZ)
__device__ float  g_sigma[4];
__device__ float  g_pv[2 * 4 * 512];
__device__ float  g_Yf[2 * 4 * 262144];
__device__ float  g_Zf[2 * 4 * 262144];
__device__ __half g_Yh[2 * 4 * 262144];
__device__ __half g_Yl[2 * 4 * 262144];
__device__ __half g_Zh[2 * 4 * 262144];
__device__ __half g_Zl[2 * 4 * 262144];
__device__ __half g_Th[4 * 262144];
__device__ __half g_Tl[4 * 262144];
__device__ __half g_Wh[4 * 262144];
__device__ __half g_Wl[4 * 262144];
__device__ __half g_Cmh[2 * 262144];
__device__ __half g_Cml[2 * 262144];
__device__ float  g_NSt[2 * 2097152];
__device__ __half g_NCth[2 * 2097152];
__device__ __half g_NCtl[2 * 2097152];
__device__ __half g_NSth[2 * 2097152];
__device__ __half g_NStl[2 * 2097152];
__device__ float  g_snorm[2 * 4096];
__device__ float  g_rk[2 * 4096];
__device__ float  g_M0[33554432];
__device__ float  g_Tb[33554432];
__device__ int    g_idx[2 * 4096];
__device__ float  g_pbs[2 * 16 * 4096];
__device__ int    g_pbi[2 * 16 * 4096];
__device__ __half g_rTh[2 * 2097152];
__device__ __half g_rTl[2 * 2097152];

// ---------------- helpers ----------------
__device__ __forceinline__ uint32_t smem_to_u32(const void* p) {
    uint32_t a;
    asm("{ .reg .u64 t; cvta.to.shared.u64 t, %1; cvt.u32.u64 %0, t; }" : "=r"(a) : "l"(p));
    return a;
}
__device__ __forceinline__ void cp_async16(uint32_t saddr, const void* g) {
    asm volatile("cp.async.cg.shared.global [%0], [%1], 16;" :: "r"(saddr), "l"(g));
}
#define CP_COMMIT() asm volatile("cp.async.commit_group;" ::: "memory")
#define CP_WAIT1()  asm volatile("cp.async.wait_group 1;" ::: "memory")
#define CP_WAIT0()  asm volatile("cp.async.wait_group 0;" ::: "memory")

__device__ __forceinline__ void mma_f16(float* c, const uint32_t* a, const uint32_t* b) {
    asm volatile(
        "mma.sync.aligned.m16n8k16.row.col.f32.f16.f16.f32 "
        "{%0,%1,%2,%3}, {%4,%5,%6,%7}, {%8,%9}, {%0,%1,%2,%3};"
        : "+f"(c[0]), "+f"(c[1]), "+f"(c[2]), "+f"(c[3])
        : "r"(a[0]), "r"(a[1]), "r"(a[2]), "r"(a[3]), "r"(b[0]), "r"(b[1]));
}

__device__ __forceinline__ void split_store(__half* Ch, __half* Cl, long long off,
                                            float x, float y) {
    __half hx = __float2half_rn(x), hy = __float2half_rn(y);
    __half lx = __float2half_rn(x - __half2float(hx));
    __half ly = __float2half_rn(y - __half2float(hy));
    *(__half2*)&Ch[off] = __halves2half2(hx, hy);
    *(__half2*)&Cl[off] = __halves2half2(lx, ly);
}

// ---------------- generic fp16-split 3-product MMA GEMM tile ----------------
#define SKPH 40
constexpr int HG_ARRH = 128 * SKPH;
constexpr int HG_BUFH = 4 * HG_ARRH;
constexpr int HG_SMEM = 2 * HG_BUFH * 2;     // 81920 bytes

__device__ __forceinline__ void hgemm_tile(
    const __half* __restrict__ Ah, const __half* __restrict__ Al,
    const __half* __restrict__ Bh, const __half* __restrict__ Bl,
    float* __restrict__ Cf, __half* __restrict__ Ch, __half* __restrict__ Cl,
    int ldC, int K, int lda, float alpha, float diagAdd, const float* __restrict__ bias,
    __half* smh)
{
    const uint32_t sbase = smem_to_u32(smh);
    const int tid  = threadIdx.x;
    const int wid  = tid >> 5, lane = tid & 31;
    const int g    = lane >> 2, t = lane & 3;
    const int wm   = wid & 3, wn = wid >> 2;
    const int m0   = blockIdx.y * 128, n0 = blockIdx.x * 128;

    auto stage = [&](int kt, int buf) {
#pragma unroll
        for (int tt = 0; tt < 8; tt++) {
            int idx = tid + tt * 256;
            int a   = idx >> 9;
            int rem = idx & 511;
            int r   = rem >> 2;
            int c8  = (rem & 3) * 8;
            const __half* src = (a == 0) ? Ah : (a == 1) ? Al : (a == 2) ? Bh : Bl;
            int rowbase = (a < 2) ? m0 : n0;
            const __half* gp = src + (long long)(rowbase + r) * lda + kt * 32 + c8;
            uint32_t sa = sbase + (uint32_t)(buf * HG_BUFH + a * HG_ARRH + r * SKPH + c8) * 2u;
            cp_async16(sa, gp);
        }
    };

    float acc[2][8][4];
#pragma unroll
    for (int i = 0; i < 2; i++)
#pragma unroll
        for (int j = 0; j < 8; j++)
#pragma unroll
            for (int k = 0; k < 4; k++) acc[i][j][k] = 0.f;

    const int nk = K >> 5;
    stage(0, 0); CP_COMMIT();

    for (int kt = 0; kt < nk; kt++) {
        const int buf = kt & 1;
        if (kt + 1 < nk) { stage(kt + 1, buf ^ 1); CP_COMMIT(); CP_WAIT1(); }
        else             { CP_WAIT0(); }
        __syncthreads();

        const __half* sAh = smh + buf * HG_BUFH;
        const __half* sAl = sAh + HG_ARRH;
        const __half* sBh = sAl + HG_ARRH;
        const __half* sBl = sBh + HG_ARRH;
#pragma unroll
        for (int ks = 0; ks < 32; ks += 16) {
            uint32_t afh[2][4], afl[2][4];
#pragma unroll
            for (int mt = 0; mt < 2; mt++) {
                int r  = wm * 32 + mt * 16;
                int i0 = (r + g) * SKPH + ks + 2 * t;
                int i8 = (r + g + 8) * SKPH + ks + 2 * t;
                afh[mt][0] = *(const uint32_t*)&sAh[i0];
                afh[mt][1] = *(const uint32_t*)&sAh[i8];
                afh[mt][2] = *(const uint32_t*)&sAh[i0 + 8];
                afh[mt][3] = *(const uint32_t*)&sAh[i8 + 8];
                afl[mt][0] = *(const uint32_t*)&sAl[i0];
                afl[mt][1] = *(const uint32_t*)&sAl[i8];
                afl[mt][2] = *(const uint32_t*)&sAl[i0 + 8];
                afl[mt][3] = *(const uint32_t*)&sAl[i8 + 8];
            }
#pragma unroll
            for (int nt = 0; nt < 8; nt++) {
                int bb = (wn * 64 + nt * 8 + g) * SKPH + ks + 2 * t;
                uint32_t bfh[2] = { *(const uint32_t*)&sBh[bb], *(const uint32_t*)&sBh[bb + 8] };
                uint32_t bfl[2] = { *(const uint32_t*)&sBl[bb], *(const uint32_t*)&sBl[bb + 8] };
#pragma unroll
                for (int mt = 0; mt < 2; mt++) {
                    mma_f16(acc[mt][nt], afh[mt], bfh);
                    mma_f16(acc[mt][nt], afh[mt], bfl);
                    mma_f16(acc[mt][nt], afl[mt], bfh);
                }
            }
        }
        __syncthreads();
    }

#pragma unroll
    for (int mt = 0; mt < 2; mt++) {
        int row0 = m0 + wm * 32 + mt * 16 + g;
        int row1 = row0 + 8;
        float bv0 = bias ? bias[row0] : 0.f;
        float bv1 = bias ? bias[row1] : 0.f;
#pragma unroll
        for (int nt = 0; nt < 8; nt++) {
            int col = n0 + wn * 64 + nt * 8 + 2 * t;
            float x0 = alpha * acc[mt][nt][0] + bv0; if (row0 == col)     x0 += diagAdd;
            float y0 = alpha * acc[mt][nt][1] + bv0; if (row0 == col + 1) y0 += diagAdd;
            float x1 = alpha * acc[mt][nt][2] + bv1; if (row1 == col)     x1 += diagAdd;
            float y1 = alpha * acc[mt][nt][3] + bv1; if (row1 == col + 1) y1 += diagAdd;
            long long o0 = (long long)row0 * ldC + col;
            long long o1 = (long long)row1 * ldC + col;
            if (Cf) {
                float2 v0; v0.x = x0; v0.y = y0; *(float2*)&Cf[o0] = v0;
                float2 v1; v1.x = x1; v1.y = y1; *(float2*)&Cf[o1] = v1;
            }
            if (Ch) {
                split_store(Ch, Cl, o0, x0, y0);
                split_store(Ch, Cl, o1, x1, y1);
            }
        }
    }
}

// ---------------- hgemm wrapper kernels ----------------
__global__ void __launch_bounds__(256, 2) covp16_kernel(
    const __half* __restrict__ Fh, const __half* __restrict__ Fl, float* __restrict__ Covp)
{
    extern __shared__ __half smh[];
    int z = blockIdx.z;
    int g = z >> 3, chunk = z & 7;
    long long o = (long long)g * CHW + (long long)chunk * 512;
    hgemm_tile(Fh + o, Fl + o, Fh + o, Fl + o,
               Covp + (long long)z * CC, nullptr, nullptr,
               512, 512, 4096, 1.f, 0.f, nullptr, smh);
}

__global__ void covred_kernel(const float* __restrict__ Covp, float* __restrict__ Cov)
{
    long long i = (long long)blockIdx.x * 256 + threadIdx.x;
    if (i >= 4 * CC) return;
    int g = (int)(i / CC);
    long long r = i % CC;
    const float* base = Covp + (long long)g * 8 * CC + r;
    float s = 0.f;
#pragma unroll
    for (int c = 0; c < 8; c++) s += base[(long long)c * CC];
    Cov[i] = s * (1.f / 4095.f);
}

// NS T partials: z = mat*4 + chunk ; K=128 slice ; P[z] = (Z@Y)_chunk
__global__ void __launch_bounds__(256, 2) nsTp16_kernel(
    const __half* __restrict__ Zh, const __half* __restrict__ Zl,
    const __half* __restrict__ Yh, const __half* __restrict__ Yl,
    float* __restrict__ P)
{
    extern __shared__ __half smh[];
    int z = blockIdx.z;
    int m = z >> 2, ch = z & 3;
    long long o = (long long)m * CC + (long long)ch * 128;
    hgemm_tile(Zh + o, Zl + o, Yh + o, Yl + o,
               P + (long long)z * CC, nullptr, nullptr,
               512, 128, 512, 1.f, 0.f, nullptr, smh);
}

// reduce 4 chunks -> T = 1.5 I - 0.5 * sum, fp16 split
__global__ void redT_kernel(const float* __restrict__ P,
                            __half* __restrict__ Th, __half* __restrict__ Tl)
{
    long long i = (long long)blockIdx.x * 256 + threadIdx.x;
    if (i >= 4 * CC) return;
    int m = (int)(i / CC);
    long long r = i % CC;
    const float* b = P + (long long)(m * 4) * CC + r;
    float s = -0.5f * (b[0] + b[CC] + b[2 * CC] + b[3 * CC]);
    int row = (int)(r / CH), col = (int)(r % CH);
    if (row == col) s += 1.5f;
    __half h = __float2half_rn(s);
    Th[i] = h;
    Tl[i] = __float2half_rn(s - __half2float(h));
}

// NS YZ partials: z = zi*4 + chunk ; zi<4 -> (Y@T)_chunk ; zi>=4 -> (T@Z)_chunk
__global__ void __launch_bounds__(256, 2) nsYZp16_kernel(
    const __half* __restrict__ Yh, const __half* __restrict__ Yl,
    const __half* __restrict__ Zh, const __half* __restrict__ Zl,
    const __half* __restrict__ Th, const __half* __restrict__ Tl,
    float* __restrict__ P)
{
    extern __shared__ __half smh[];
    int z = blockIdx.z;
    int zi = z >> 2, ch = z & 3;
    if (zi < 4) {
        long long o = (long long)zi * CC + (long long)ch * 128;
        hgemm_tile(Yh + o, Yl + o, Th + o, Tl + o,
                   P + (long long)z * CC, nullptr, nullptr,
                   512, 128, 512, 1.f, 0.f, nullptr, smh);
    } else {
        long long o = (long long)(zi - 4) * CC + (long long)ch * 128;
        hgemm_tile(Th + o, Tl + o, Zh + o, Zl + o,
                   P + (long long)z * CC, nullptr, nullptr,
                   512, 128, 512, 1.f, 0.f, nullptr, smh);
    }
}

__global__ void redYZ_kernel(const float* __restrict__ P,
                             float* __restrict__ Ynf, __half* __restrict__ Ynh, __half* __restrict__ Ynl,
                             float* __restrict__ Znf, __half* __restrict__ Znh, __half* __restrict__ Znl)
{
    long long i = (long long)blockIdx.x * 256 + threadIdx.x;
    if (i >= 8 * CC) return;
    int zi = (int)(i / CC);
    long long r = i % CC;
    const float* b = P + (long long)(zi * 4) * CC + r;
    float s = b[0] + b[CC] + b[2 * CC] + b[3 * CC];
    __half h = __float2half_rn(s);
    __half l = __float2half_rn(s - __half2float(h));
    if (zi < 4) { long long o = (long long)zi * CC + r;       Ynf[o] = s; Ynh[o] = h; Ynl[o] = l; }
    else        { long long o = (long long)(zi - 4) * CC + r; Znf[o] = s; Znh[o] = h; Znl[o] = l; }
}

__global__ void __launch_bounds__(256, 2) whiten16_kernel(
    const __half* __restrict__ FcTh, const __half* __restrict__ FcTl,
    const __half* __restrict__ Wh, const __half* __restrict__ Wl,
    float* __restrict__ NSt,
    __half* __restrict__ NCth, __half* __restrict__ NCtl,
    __half* __restrict__ NSth, __half* __restrict__ NStl)
{
    extern __shared__ __half smh[];
    int z = blockIdx.z;
    long long oa = (long long)z * CHW;
    long long ow = (long long)z * CC;
    float* cf; __half *ch, *cl;
    if (z < 2) { cf = nullptr; ch = NCth + oa; cl = NCtl + oa; }
    else       { long long os = (long long)(z - 2) * CHW;
                 cf = NSt + os; ch = NSth + os; cl = NStl + os; }
    hgemm_tile(FcTh + oa, FcTl + oa, Wh + ow, Wl + ow,
               cf, ch, cl, 512, 512, 512, 1.f, 0.f, nullptr, smh);
}

__global__ void __launch_bounds__(256, 2) m016_kernel(
    const __half* __restrict__ Ah, const __half* __restrict__ Al,
    const __half* __restrict__ Bh, const __half* __restrict__ Bl,
    float* __restrict__ M0out)
{
    extern __shared__ __half smh[];
    long long o = (long long)blockIdx.z * CHW;
    hgemm_tile(Ah + o, Al + o, Bh + o, Bl + o,
               M0out + (long long)blockIdx.z * PQ, nullptr, nullptr,
               4096, 512, 512, 1.f, 0.f, nullptr, smh);
}

__global__ void __launch_bounds__(256, 2) color16_kernel(
    const __half* __restrict__ Cmh, const __half* __restrict__ Cml,
    const __half* __restrict__ rTh, const __half* __restrict__ rTl,
    float* __restrict__ out, const float* __restrict__ means)
{
    extern __shared__ __half smh[];
    int b = blockIdx.z;
    hgemm_tile(Cmh + (long long)b * CC, Cml + (long long)b * CC,
               rTh + (long long)b * CHW, rTl + (long long)b * CHW,
               out + (long long)b * CHW, nullptr, nullptr,
               4096, 512, 512, 1.f, 0.f, means + (long long)(2 + b) * CH, smh);
}

// ---------------- per-channel mean + center (+ fp16 split) ----------------
__global__ void center_kernel(const float* __restrict__ content, const float* __restrict__ style,
                              float* __restrict__ Fcent, __half* __restrict__ Fch,
                              __half* __restrict__ Fcl, float* __restrict__ means)
{
    int c = blockIdx.x, g = blockIdx.y;
    const float* src = (g < 2 ? content + (long long)g * CHW : style + (long long)(g - 2) * CHW)
                       + (long long)c * HW;
    __shared__ float red[256];
    float s = 0.f;
    for (int i = threadIdx.x; i < HW; i += 256) s += src[i];
    red[threadIdx.x] = s; __syncthreads();
    for (int st = 128; st > 0; st >>= 1) {
        if (threadIdx.x < st) red[threadIdx.x] += red[threadIdx.x + st];
        __syncthreads();
    }
    float mean = red[0] * (1.f / HW);
    if (threadIdx.x == 0) means[g * CH + c] = mean;
    long long base = (long long)g * CHW + (long long)c * HW;
    for (int i = threadIdx.x; i < HW; i += 256) {
        float v = src[i] - mean;
        Fcent[base + i] = v;
        __half h = __float2half_rn(v);
        Fch[base + i] = h;
        Fcl[base + i] = __float2half_rn(v - __half2float(h));
    }
}

// ---------------- transpose + fp16 split of Fcent ----------------
__global__ void transposeFcT_kernel(const float* __restrict__ Fcent,
                                    __half* __restrict__ FcTh, __half* __restrict__ FcTl)
{
    __shared__ float tile[32][33];
    int g = blockIdx.z;
    int p0 = blockIdx.x * 32, c0 = blockIdx.y * 32;
    tile[threadIdx.y][threadIdx.x] =
        Fcent[(long long)g * CHW + (long long)(c0 + threadIdx.y) * HW + p0 + threadIdx.x];
    __syncthreads();
    float x = tile[threadIdx.x][threadIdx.y];
    long long o = (long long)g * CHW + (long long)(p0 + threadIdx.y) * CH + c0 + threadIdx.x;
    __half h = __float2half_rn(x);
    FcTh[o] = h;
    FcTl[o] = __float2half_rn(x - __half2float(h));
}

// ---------------- power iteration as unnormalized matvec chain ----------------
__global__ void pinit_kernel(float* __restrict__ v)
{
    int i = blockIdx.x * 256 + threadIdx.x;
    if (i < 4 * CH) v[i] = 1.f + 1e-4f * (i & (CH - 1));
}

__global__ void matvec_kernel(const float* __restrict__ Cov,
                              const float* __restrict__ vin, float* __restrict__ vout)
{
    int gmat = blockIdx.y;
    const float* A = Cov + (long long)gmat * CC;
    const float* v = vin + gmat * CH;
    int col = blockIdx.x * 64 + (threadIdx.x & 63);
    int kc  = threadIdx.x >> 6;
    __shared__ float part[4][64];
    float a0 = 0.f, a1 = 0.f, a2 = 0.f, a3 = 0.f;
    int k0 = kc * 128;
#pragma unroll 8
    for (int k = 0; k < 128; k += 4) {
        a0 = fmaf(A[(long long)(k0 + k + 0) * CH + col], v[k0 + k + 0], a0);
        a1 = fmaf(A[(long long)(k0 + k + 1) * CH + col], v[k0 + k + 1], a1);
        a2 = fmaf(A[(long long)(k0 + k + 2) * CH + col], v[k0 + k + 2], a2);
        a3 = fmaf(A[(long long)(k0 + k + 3) * CH + col], v[k0 + k + 3], a3);
    }
    part[kc][threadIdx.x & 63] = (a0 + a1) + (a2 + a3);
    __syncthreads();
    if (kc == 0) {
        int c = threadIdx.x & 63;
        vout[gmat * CH + col] = part[0][c] + part[1][c] + part[2][c] + part[3][c];
    }
}

__global__ void lam_kernel(const float* __restrict__ vprev, const float* __restrict__ vlast,
                           float* __restrict__ sigma)
{
    int g = blockIdx.x;
    int t = threadIdx.x;
    __shared__ float rp[512], rl[512];
    float vp = vprev[g * CH + t], vl = vlast[g * CH + t];
    rp[t] = vp * vp; rl[t] = vl * vl;
    __syncthreads();
    for (int st = 256; st > 0; st >>= 1) {
        if (t < st) { rp[t] += rp[t + st]; rl[t] += rl[t + st]; }
        __syncthreads();
    }
    if (t == 0) sigma[g] = 1.02f * sqrtf(rl[0] / fmaxf(rp[0], 1e-30f)) + 1e-20f;
}

// ---------------- Newton-Schulz init (fp16 split) ----------------
__global__ void ns_init_kernel(const float* __restrict__ Cov, const float* __restrict__ sigma,
                               __half* __restrict__ Yh, __half* __restrict__ Yl,
                               __half* __restrict__ Zh, __half* __restrict__ Zl)
{
    long long i = (long long)blockIdx.x * blockDim.x + threadIdx.x;
    if (i >= 4 * CC) return;
    int g = (int)(i / CC);
    long long r = i % CC;
    int row = (int)(r / CH), col = (int)(r % CH);
    float y = Cov[i] / sigma[g];
    __half h = __float2half_rn(y);
    Yh[i] = h;
    Yl[i] = __float2half_rn(y - __half2float(h));
    Zh[i] = __float2half_rn((row == col) ? 1.f : 0.f);
    Zl[i] = __float2half_rn(0.f);
}

// ---------------- rescale -> W, Cm fp16 splits ----------------
__global__ void scale16_kernel(const float* __restrict__ Yf, const float* __restrict__ Zf,
                               const float* __restrict__ sigma,
                               __half* __restrict__ Wh, __half* __restrict__ Wl,
                               __half* __restrict__ Cmh, __half* __restrict__ Cml)
{
    long long i = (long long)blockIdx.x * blockDim.x + threadIdx.x;
    if (i >= 4 * CC) return;
    int g = (int)(i / CC);
    float sq = sqrtf(sigma[g]);
    float w = Zf[i] / sq;
    __half h = __float2half_rn(w);
    Wh[i] = h;
    Wl[i] = __float2half_rn(w - __half2float(h));
    if (g >= 2) {
        float cm = Yf[i] * sq;
        __half hc = __float2half_rn(cm);
        Cmh[i - 2 * CC] = hc;
        Cml[i - 2 * CC] = __float2half_rn(cm - __half2float(hc));
    }
}

// ---------------- per-pixel squared norms ----------------
__global__ void snorm_kernel(const float* __restrict__ NSt, float* __restrict__ snorm)
{
    int gw = (blockIdx.x * blockDim.x + threadIdx.x) >> 5;
    int lane = threadIdx.x & 31;
    if (gw >= 2 * HW) return;
    int b = gw / HW, p = gw % HW;
    const float* row = NSt + (long long)b * CHW + (long long)p * CH;
    float s = 0.f;
    for (int c = lane; c < CH; c += 32) { float v = row[c]; s = fmaf(v, v, s); }
    for (int o = 16; o > 0; o >>= 1) s += __shfl_down_sync(0xffffffff, s, o);
    if (lane == 0) snorm[b * HW + p] = s;
}

__global__ void rknorm_kernel(const float* __restrict__ snorm, float* __restrict__ rk)
{
    int i = blockIdx.x * blockDim.x + threadIdx.x;
    if (i >= 2 * HW) return;
    int b = i / HW, p = i % HW;
    int py = p >> 6, px = p & 63;
    float sum = 0.f;
    for (int u = -1; u <= 1; u++)
        for (int v = -1; v <= 1; v++) {
            int yy = py + u, xx = px + v;
            if ((unsigned)yy < 64u && (unsigned)xx < 64u) sum += snorm[b * HW + yy * 64 + xx];
        }
    rk[i] = 1.f / (sqrtf(sum) + 1e-5f);
}

// ---------------- horizontal diagonal 3-box ----------------
__global__ void boxh_kernel(const float* __restrict__ M0, float* __restrict__ Tb)
{
    long long i = (long long)blockIdx.x * 256 + threadIdx.x;
    int b = blockIdx.y;
    const float* M = M0 + (long long)b * PQ;
    int p = (int)(i >> 12);
    int q = (int)(i & 4095);
    int px = p & 63, qx = q & 63;
    float s = 0.f;
#pragma unroll
    for (int v = -1; v <= 1; v++) {
        if ((unsigned)(px + v) < 64u && (unsigned)(qx + v) < 64u) s += M[i + (long long)v * 4097];
    }
    Tb[(long long)b * PQ + i] = s;
}

// ---------------- vertical diagonal 3-box + partial argmax ----------------
__global__ void argmax_part_kernel(const float* __restrict__ Tb, const float* __restrict__ rk,
                                   float* __restrict__ pbs, int* __restrict__ pbi)
{
    int b = blockIdx.z;
    int q = blockIdx.x * 256 + threadIdx.x;
    int pc = blockIdx.y;
    __shared__ float srk[256];
    srk[threadIdx.x] = rk[b * HW + pc * 256 + threadIdx.x];
    __syncthreads();
    const float* T = Tb + (long long)b * PQ;
    float best = -FLT_MAX; int bi = 0;
    for (int pp = 0; pp < 256; pp++) {
        int p = pc * 256 + pp;
        float s = 0.f;
#pragma unroll
        for (int u = -1; u <= 1; u++) {
            int row = p + 64 * u, col = q + 64 * u;
            if ((unsigned)row < (unsigned)HW && (unsigned)col < (unsigned)HW)
                s += T[(long long)row * HW + col];
        }
        float sc = s * srk[pp];
        if (sc > best) { best = sc; bi = p; }
    }
    pbs[(b * 16 + pc) * HW + q] = best;
    pbi[(b * 16 + pc) * HW + q] = bi;
}

__global__ void argmax_comb_kernel(const float* __restrict__ pbs, const int* __restrict__ pbi,
                                   int* __restrict__ idx)
{
    int i = blockIdx.x * 256 + threadIdx.x;
    if (i >= 2 * HW) return;
    int b = i / HW, q = i % HW;
    float best = -FLT_MAX; int bi = 0;
    for (int k = 0; k < 16; k++) {
        float s = pbs[(b * 16 + k) * HW + q];
        int p = pbi[(b * 16 + k) * HW + q];
        if (s > best || (s == best && p < bi)) { best = s; bi = p; }
    }
    idx[b * HW + q] = bi;
}

// ---------------- gather + overlap-add (emit fp16 split) ----------------
__global__ void gather_kernel(const float* __restrict__ NSt, const int* __restrict__ idx,
                              __half* __restrict__ rTh, __half* __restrict__ rTl)
{
    int b = blockIdx.y, pix = blockIdx.x;
    int Y = pix >> 6, X = pix & 63;
    __shared__ int sp[9];
    if (threadIdx.x < 9) {
        int dx = threadIdx.x / 3, dy = threadIdx.x % 3;
        int y = Y + 1 - dx, x = X + 1 - dy;
        int pos = -1;
        if ((unsigned)y < 64u && (unsigned)x < 64u) {
            int p = idx[b * HW + y * 64 + x];
            int sy = (p >> 6) + dx - 1, sx = (p & 63) + dy - 1;
            if ((unsigned)sy < 64u && (unsigned)sx < 64u) pos = sy * 64 + sx;
        }
        sp[threadIdx.x] = pos;
    }
    __syncthreads();
    int cy = (Y == 0 || Y == 63) ? 2 : 3;
    int cx = (X == 0 || X == 63) ? 2 : 3;
    float inv = 1.f / (float)(cy * cx);
    const float* base = NSt + (long long)b * CHW;
    long long obase = (long long)b * CHW + (long long)pix * CH;
    for (int c = threadIdx.x; c < CH; c += 128) {
        float a = 0.f;
#pragma unroll
        for (int k = 0; k < 9; k++) {
            int pos = sp[k];
            if (pos >= 0) a += base[(long long)pos * CH + c];
        }
        float v = a * inv;
        __half h = __float2half_rn(v);
        rTh[obase + c] = h;
        rTl[obase + c] = __float2half_rn(v - __half2float(h));
    }
}

// ---------------- host orchestration ----------------
extern "C" void kernel_launch(void* const* d_in, const int* in_sizes, int n_in,
                              void* d_out, int out_size)
{
    (void)in_sizes; (void)n_in; (void)out_size;
    const float* content = (const float*)d_in[0];
    const float* style   = (const float*)d_in[1];
    float* out = (float*)d_out;

    float *Fcent, *means, *Cov, *Covp, *sigma, *pv, *Yf, *Zf, *NSt, *snorm, *rk, *M0, *Tb, *pbs;
    __half *Fch, *Fcl, *FcTh, *FcTl, *Yh, *Yl, *Zh, *Zl, *Th, *Tl, *Wh, *Wl, *Cmh, *Cml;
    __half *NCth, *NCtl, *NSth, *NStl, *rTh, *rTl;
    int *idx, *pbi;
    cudaGetSymbolAddress((void**)&Fcent, g_Fcent);
    cudaGetSymbolAddress((void**)&Fch,   g_Fch);
    cudaGetSymbolAddress((void**)&Fcl,   g_Fcl);
    cudaGetSymbolAddress((void**)&FcTh,  g_FcTh);
    cudaGetSymbolAddress((void**)&FcTl,  g_FcTl);
    cudaGetSymbolAddress((void**)&means, g_means);
    cudaGetSymbolAddress((void**)&Cov,   g_Cov);
    cudaGetSymbolAddress((void**)&Covp,  g_Covp);
    cudaGetSymbolAddress((void**)&sigma, g_sigma);
    cudaGetSymbolAddress((void**)&pv,    g_pv);
    cudaGetSymbolAddress((void**)&Yf,    g_Yf);
    cudaGetSymbolAddress((void**)&Zf,    g_Zf);
    cudaGetSymbolAddress((void**)&Yh,    g_Yh);
    cudaGetSymbolAddress((void**)&Yl,    g_Yl);
    cudaGetSymbolAddress((void**)&Zh,    g_Zh);
    cudaGetSymbolAddress((void**)&Zl,    g_Zl);
    cudaGetSymbolAddress((void**)&Th,    g_Th);
    cudaGetSymbolAddress((void**)&Tl,    g_Tl);
    cudaGetSymbolAddress((void**)&Wh,    g_Wh);
    cudaGetSymbolAddress((void**)&Wl,    g_Wl);
    cudaGetSymbolAddress((void**)&Cmh,   g_Cmh);
    cudaGetSymbolAddress((void**)&Cml,   g_Cml);
    cudaGetSymbolAddress((void**)&NSt,   g_NSt);
    cudaGetSymbolAddress((void**)&NCth,  g_NCth);
    cudaGetSymbolAddress((void**)&NCtl,  g_NCtl);
    cudaGetSymbolAddress((void**)&NSth,  g_NSth);
    cudaGetSymbolAddress((void**)&NStl,  g_NStl);
    cudaGetSymbolAddress((void**)&snorm, g_snorm);
    cudaGetSymbolAddress((void**)&rk,    g_rk);
    cudaGetSymbolAddress((void**)&M0,    g_M0);
    cudaGetSymbolAddress((void**)&Tb,    g_Tb);
    cudaGetSymbolAddress((void**)&idx,   g_idx);
    cudaGetSymbolAddress((void**)&pbs,   g_pbs);
    cudaGetSymbolAddress((void**)&pbi,   g_pbi);
    cudaGetSymbolAddress((void**)&rTh,   g_rTh);
    cudaGetSymbolAddress((void**)&rTl,   g_rTl);

    cudaFuncSetAttribute(covp16_kernel,   cudaFuncAttributeMaxDynamicSharedMemorySize, HG_SMEM);
    cudaFuncSetAttribute(nsTp16_kernel,   cudaFuncAttributeMaxDynamicSharedMemorySize, HG_SMEM);
    cudaFuncSetAttribute(nsYZp16_kernel,  cudaFuncAttributeMaxDynamicSharedMemorySize, HG_SMEM);
    cudaFuncSetAttribute(whiten16_kernel, cudaFuncAttributeMaxDynamicSharedMemorySize, HG_SMEM);
    cudaFuncSetAttribute(m016_kernel,     cudaFuncAttributeMaxDynamicSharedMemorySize, HG_SMEM);
    cudaFuncSetAttribute(color16_kernel,  cudaFuncAttributeMaxDynamicSharedMemorySize, HG_SMEM);

    // 1) center (+ channel-major fp16 split)
    center_kernel<<<dim3(CH, 4), 256>>>(content, style, Fcent, Fch, Fcl, means);

    // 2) pixel-major transposed fp16 split
    transposeFcT_kernel<<<dim3(128, 16, 4), dim3(32, 32)>>>(Fcent, FcTh, FcTl);

    // 3) covariances: K split into 8 chunks + reduce
    covp16_kernel<<<dim3(4, 4, 32), 256, HG_SMEM>>>(Fch, Fcl, Covp);
    covred_kernel<<<4096, 256>>>(Covp, Cov);

    // 4) lambda_max: 6 unnormalized matvecs + norm ratio
    pinit_kernel<<<8, 256>>>(pv);
    float* vc = pv;
    float* vn = pv + 4 * CH;
    for (int it = 0; it < 6; it++) {
        matvec_kernel<<<dim3(8, 4), 256>>>(Cov, vc, vn);
        float* t = vc; vc = vn; vn = t;
    }
    lam_kernel<<<4, 512>>>(vn, vc, sigma);

    // 5) Newton-Schulz (5 iterations, K-split x4 for full-chip occupancy)
    ns_init_kernel<<<4096, 256>>>(Cov, sigma, Yh, Yl, Zh, Zl);
    int cur = 0;
    for (int it = 0; it < 5; it++) {
        int nxt = cur ^ 1;
        long long hc = (long long)cur * 4 * CC, hn = (long long)nxt * 4 * CC;
        nsTp16_kernel<<<dim3(4, 4, 16), 256, HG_SMEM>>>(
            Zh + hc, Zl + hc, Yh + hc, Yl + hc, Covp);
        redT_kernel<<<4096, 256>>>(Covp, Th, Tl);
        nsYZp16_kernel<<<dim3(4, 4, 32), 256, HG_SMEM>>>(
            Yh + hc, Yl + hc, Zh + hc, Zl + hc, Th, Tl, Covp);
        redYZ_kernel<<<8192, 256>>>(Covp,
            Yf + hn, Yh + hn, Yl + hn, Zf + hn, Zh + hn, Zl + hn);
        cur = nxt;
    }
    long long hf = (long long)cur * 4 * CC;

    // 6) rescale -> W, Cm splits
    scale16_kernel<<<4096, 256>>>(Yf + hf, Zf + hf, sigma, Wh, Wl, Cmh, Cml);

    // 7) whitening on tensor cores
    whiten16_kernel<<<dim3(4, 32, 4), 256, HG_SMEM>>>(
        FcTh, FcTl, Wh, Wl, NSt, NCth, NCtl, NSth, NStl);

    // 8) patch norms
    snorm_kernel<<<1024, 256>>>(NSt, snorm);
    rknorm_kernel<<<32, 256>>>(snorm, rk);

    // 9) M0 on tensor cores
    m016_kernel<<<dim3(32, 32, 2), 256, HG_SMEM>>>(NSth, NStl, NCth, NCtl, M0);

    // 10) box filter + argmax
    boxh_kernel<<<dim3(65536, 2), 256>>>(M0, Tb);
    argmax_part_kernel<<<dim3(16, 16, 2), 256>>>(Tb, rk, pbs, pbi);
    argmax_comb_kernel<<<32, 256>>>(pbs, pbi, idx);

    // 11) gather + overlap-add
    gather_kernel<<<dim3(4096, 2), 128>>>(NSt, idx, rTh, rTl);

    // 12) color on tensor cores
    color16_kernel<<<dim3(32, 4, 2), 256, HG_SMEM>>>(Cmh, Cml, rTh, rTl, out, means);
}